// round 2
// baseline (speedup 1.0000x reference)
#include <cuda_runtime.h>
#include <cuda_bf16.h>
#include <math.h>

// Problem constants
#define B_  2
#define L_  2048
#define H_  16
#define DK_ 64
#define D_  (H_ * DK_)        // 1024
#define ML_ (B_ * L_)         // 4096 rows for projections

// Scratch (device globals: no allocation allowed)
__device__ float g_q[(size_t)B_ * L_ * D_];
__device__ float g_k[(size_t)B_ * L_ * D_];
__device__ float g_v[(size_t)B_ * L_ * D_];
__device__ float g_attn[(size_t)B_ * L_ * D_];
__device__ int   g_mask_kind;   // 0 = uint8, 1 = int32, 2 = float32

#define TS 64
#define KT 16

// ---------------------------------------------------------------------------
// Sniff the storage dtype of the (0/1-valued) attention mask.
// int32 0/1  -> every u32 word is 0 or 1
// float32    -> every u32 word is 0x00000000 or 0x3F800000
// uint8      -> neither (random 0/1 bytes packed 4-per-word)
// ---------------------------------------------------------------------------
__global__ void detect_mask_kernel(const unsigned int* __restrict__ m)
{
    if (threadIdx.x == 0 && blockIdx.x == 0) {
        int all01 = 1, allf = 1;
        for (int i = 0; i < 1024; i++) {
            unsigned int w = m[i];
            if (w > 1u) all01 = 0;
            if (w != 0u && w != 0x3F800000u) allf = 0;
        }
        g_mask_kind = all01 ? 1 : (allf ? 2 : 0);
    }
}

// ---------------------------------------------------------------------------
// C[m,n] = alpha * sum_k A[m,k]*B[n,k] + bias[n]   (A: M x K lda, B: N x K ldb)
// All dims multiples of 64 (K multiple of 16). 256 threads, 4x4 per thread.
// ---------------------------------------------------------------------------
__global__ void gemm_abt(const float* __restrict__ A, int lda,
                         const float* __restrict__ B, int ldb,
                         float* __restrict__ C, int ldc,
                         int K, const float* __restrict__ bias, float alpha)
{
    __shared__ float As[KT][TS + 1];
    __shared__ float Bs[KT][TS + 1];
    const int tid = threadIdx.x;
    const int tx = tid & 15, ty = tid >> 4;
    const int m0 = blockIdx.y * TS, n0 = blockIdx.x * TS;

    float acc[4][4] = {};
    for (int k0 = 0; k0 < K; k0 += KT) {
        #pragma unroll
        for (int i = 0; i < 4; i++) {
            int e = tid + i * 256;          // 0..1023
            int r = e >> 4, c = e & 15;
            As[c][r] = A[(size_t)(m0 + r) * lda + k0 + c];
            Bs[c][r] = B[(size_t)(n0 + r) * ldb + k0 + c];
        }
        __syncthreads();
        #pragma unroll
        for (int kk = 0; kk < KT; kk++) {
            float a[4], b[4];
            #pragma unroll
            for (int i = 0; i < 4; i++) a[i] = As[kk][ty * 4 + i];
            #pragma unroll
            for (int j = 0; j < 4; j++) b[j] = Bs[kk][tx * 4 + j];
            #pragma unroll
            for (int i = 0; i < 4; i++)
                #pragma unroll
                for (int j = 0; j < 4; j++) acc[i][j] += a[i] * b[j];
        }
        __syncthreads();
    }
    #pragma unroll
    for (int i = 0; i < 4; i++)
        #pragma unroll
        for (int j = 0; j < 4; j++) {
            int m = m0 + ty * 4 + i, n = n0 + tx * 4 + j;
            float v = acc[i][j] * alpha + (bias ? bias[n] : 0.0f);
            C[(size_t)m * ldc + n] = v;
        }
}

// ---------------------------------------------------------------------------
// RoPE in-place on (B, L, H, DK) fp32 buffer. One thread per (b,l,h,j<32).
// ---------------------------------------------------------------------------
__global__ void rope_kernel(float* __restrict__ x)
{
    int idx = blockIdx.x * blockDim.x + threadIdx.x;   // 2^21 threads
    int j = idx & 31;
    int h = (idx >> 5) & 15;
    int l = (idx >> 9) & 2047;
    int b = idx >> 20;
    size_t base = (((size_t)(b * L_ + l)) * H_ + h) * DK_;
    float inv = 1.0f / powf(10000.0f, (2.0f * j) / 64.0f);
    float freq = (float)l * inv;
    float c = cosf(freq), s = sinf(freq);
    float a  = x[base + j];
    float bb = x[base + j + 32];
    x[base + j]      = a * c - bb * s;
    x[base + j + 32] = bb * c + a * s;
}

// ---------------------------------------------------------------------------
// Logits: per (b,h) tile GEMM Q·K^T/8, epilogue mask + bias. Writes into the
// weights section of d_out (pre-softmax). Mask dtype selected via g_mask_kind.
// ---------------------------------------------------------------------------
__global__ void logits_kernel(const float* __restrict__ gq,
                              const float* __restrict__ gk,
                              const void* __restrict__ mask,
                              const float* __restrict__ awb,
                              float* __restrict__ Wt)
{
    const int z = blockIdx.z;          // b*H + h
    const int b = z >> 4, h = z & 15;
    const float* A = gq + ((size_t)b * L_ * H_ + h) * DK_;   // lda = D_
    const float* Bm = gk + ((size_t)b * L_ * H_ + h) * DK_;  // ldb = D_
    const float* arow = awb + (size_t)h * L_ * L_;
    float* C = Wt + (size_t)z * L_ * L_;
    const size_t mbase = (size_t)b * L_ * L_;

    const int mk = g_mask_kind;
    const unsigned char* m8  = (const unsigned char*)mask;
    const int*           m32 = (const int*)mask;
    const float*         mf  = (const float*)mask;

    __shared__ float As[KT][TS + 1];
    __shared__ float Bs[KT][TS + 1];
    const int tid = threadIdx.x;
    const int tx = tid & 15, ty = tid >> 4;
    const int m0 = blockIdx.y * TS, n0 = blockIdx.x * TS;

    float acc[4][4] = {};
    for (int k0 = 0; k0 < DK_; k0 += KT) {
        #pragma unroll
        for (int i = 0; i < 4; i++) {
            int e = tid + i * 256;
            int r = e >> 4, c = e & 15;
            As[c][r] = A[(size_t)(m0 + r) * D_ + k0 + c];
            Bs[c][r] = Bm[(size_t)(n0 + r) * D_ + k0 + c];
        }
        __syncthreads();
        #pragma unroll
        for (int kk = 0; kk < KT; kk++) {
            float a[4], bb[4];
            #pragma unroll
            for (int i = 0; i < 4; i++) a[i] = As[kk][ty * 4 + i];
            #pragma unroll
            for (int j = 0; j < 4; j++) bb[j] = Bs[kk][tx * 4 + j];
            #pragma unroll
            for (int i = 0; i < 4; i++)
                #pragma unroll
                for (int j = 0; j < 4; j++) acc[i][j] += a[i] * bb[j];
        }
        __syncthreads();
    }
    #pragma unroll
    for (int i = 0; i < 4; i++)
        #pragma unroll
        for (int j = 0; j < 4; j++) {
            int m = m0 + ty * 4 + i, n = n0 + tx * 4 + j;
            size_t o = (size_t)m * L_ + n;
            bool keep;
            if (mk == 1)      keep = (m32[mbase + o] != 0);
            else if (mk == 2) keep = (mf[mbase + o] != 0.0f);
            else              keep = (m8[mbase + o] != 0);
            float v = acc[i][j] * 0.125f;      // 1/sqrt(64)
            v = keep ? v : -1e30f;
            C[o] = v + arow[o];
        }
}

// ---------------------------------------------------------------------------
// Row softmax in-place over L_=2048 columns. One block (256 thr) per row.
// ---------------------------------------------------------------------------
__global__ void softmax_kernel(float* __restrict__ W)
{
    float* p = W + (size_t)blockIdx.x * L_;
    const int tid = threadIdx.x;
    float v[8];
    float mx = -INFINITY;
    #pragma unroll
    for (int i = 0; i < 8; i++) { v[i] = p[tid + i * 256]; mx = fmaxf(mx, v[i]); }

    __shared__ float sm[256];
    sm[tid] = mx; __syncthreads();
    for (int s = 128; s > 0; s >>= 1) {
        if (tid < s) sm[tid] = fmaxf(sm[tid], sm[tid + s]);
        __syncthreads();
    }
    mx = sm[0]; __syncthreads();

    float sum = 0.0f;
    #pragma unroll
    for (int i = 0; i < 8; i++) { v[i] = expf(v[i] - mx); sum += v[i]; }
    sm[tid] = sum; __syncthreads();
    for (int s = 128; s > 0; s >>= 1) {
        if (tid < s) sm[tid] += sm[tid + s];
        __syncthreads();
    }
    float inv = 1.0f / sm[0];
    #pragma unroll
    for (int i = 0; i < 8; i++) p[tid + i * 256] = v[i] * inv;
}

// ---------------------------------------------------------------------------
// attn = weights @ V  per (b,h): (2048 x 2048) @ (2048 x 64)
// ---------------------------------------------------------------------------
__global__ void attnv_kernel(const float* __restrict__ Wt,
                             const float* __restrict__ gv,
                             float* __restrict__ gattn)
{
    const int z = blockIdx.z;
    const int b = z >> 4, h = z & 15;
    const float* A = Wt + (size_t)z * L_ * L_;                  // lda = L_
    const float* Bm = gv + ((size_t)b * L_ * H_ + h) * DK_;     // ldb = D_
    float* C = gattn + (size_t)b * L_ * D_ + h * DK_;           // ldc = D_

    __shared__ float As[KT][TS + 1];
    __shared__ float Bs[KT][TS + 1];
    const int tid = threadIdx.x;
    const int tx = tid & 15, ty = tid >> 4;
    const int m0 = blockIdx.y * TS;     // n0 = 0 (N=64 single tile)

    float acc[4][4] = {};
    for (int k0 = 0; k0 < L_; k0 += KT) {
        #pragma unroll
        for (int i = 0; i < 4; i++) {
            int e = tid + i * 256;
            { int r = e >> 4, c = e & 15;
              As[c][r] = A[(size_t)(m0 + r) * L_ + k0 + c]; }
            { int r = e >> 6, c = e & 63;          // 16 x 64 of V rows
              Bs[r][c] = Bm[(size_t)(k0 + r) * D_ + c]; }
        }
        __syncthreads();
        #pragma unroll
        for (int kk = 0; kk < KT; kk++) {
            float a[4], bb[4];
            #pragma unroll
            for (int i = 0; i < 4; i++) a[i] = As[kk][ty * 4 + i];
            #pragma unroll
            for (int j = 0; j < 4; j++) bb[j] = Bs[kk][tx * 4 + j];
            #pragma unroll
            for (int i = 0; i < 4; i++)
                #pragma unroll
                for (int j = 0; j < 4; j++) acc[i][j] += a[i] * bb[j];
        }
        __syncthreads();
    }
    #pragma unroll
    for (int i = 0; i < 4; i++)
        #pragma unroll
        for (int j = 0; j < 4; j++) {
            int m = m0 + ty * 4 + i, n = tx * 4 + j;
            C[(size_t)m * D_ + n] = acc[i][j];
        }
}

// ---------------------------------------------------------------------------
extern "C" void kernel_launch(void* const* d_in, const int* in_sizes, int n_in,
                              void* d_out, int out_size)
{
    const float* query = (const float*)d_in[0];
    const float* key   = (const float*)d_in[1];
    const float* value = (const float*)d_in[2];
    const void*  mask  = d_in[3];
    const float* awb = (const float*)d_in[4];
    const float* Wq = (const float*)d_in[5];
    const float* bq = (const float*)d_in[6];
    const float* Wk = (const float*)d_in[7];
    const float* bk = (const float*)d_in[8];
    const float* Wv = (const float*)d_in[9];
    const float* bv = (const float*)d_in[10];
    const float* Wo = (const float*)d_in[11];
    const float* bo = (const float*)d_in[12];

    float* out = (float*)d_out;                              // (B, L, D)
    float* weights = out + (size_t)B_ * L_ * D_;             // (B, H, L, L)

    float *gq, *gk, *gv, *gattn;
    cudaGetSymbolAddress((void**)&gq, g_q);
    cudaGetSymbolAddress((void**)&gk, g_k);
    cudaGetSymbolAddress((void**)&gv, g_v);
    cudaGetSymbolAddress((void**)&gattn, g_attn);

    dim3 blk(256);

    // 0) Sniff mask dtype (bool may arrive as u8 / i32 / f32)
    detect_mask_kernel<<<1, 32>>>((const unsigned int*)mask);

    // 1) QKV projections: (4096 x 1024) @ W^T + b
    dim3 gproj(D_ / TS, ML_ / TS);                           // 16 x 64
    gemm_abt<<<gproj, blk>>>(query, D_, Wq, D_, gq, D_, D_, bq, 1.0f);
    gemm_abt<<<gproj, blk>>>(key,   D_, Wk, D_, gk, D_, D_, bk, 1.0f);
    gemm_abt<<<gproj, blk>>>(value, D_, Wv, D_, gv, D_, D_, bv, 1.0f);

    // 2) RoPE on q and k
    int nrope = B_ * L_ * H_ * 32;                           // 2^21
    rope_kernel<<<nrope / 256, 256>>>(gq);
    rope_kernel<<<nrope / 256, 256>>>(gk);

    // 3) Logits + mask + bias -> weights section of d_out (pre-softmax)
    dim3 glog(L_ / TS, L_ / TS, B_ * H_);                    // 32 x 32 x 32
    logits_kernel<<<glog, blk>>>(gq, gk, mask, awb, weights);

    // 4) Softmax (in place on d_out weights)
    softmax_kernel<<<B_ * H_ * L_, 256>>>(weights);

    // 5) attn = weights @ V  -> g_attn (B, L, H*DK)
    dim3 gat(1, L_ / TS, B_ * H_);                           // 1 x 32 x 32
    attnv_kernel<<<gat, blk>>>(weights, gv, gattn);

    // 6) Output projection: (4096 x 1024) @ Wo^T + bo -> out
    gemm_abt<<<gproj, blk>>>(gattn, D_, Wo, D_, out, D_, D_, bo, 1.0f);
}

// round 4
// speedup vs baseline: 1.5769x; 1.5769x over previous
#include <cuda_runtime.h>
#include <cuda_bf16.h>
#include <math.h>

// Problem constants
#define B_  2
#define L_  2048
#define H_  16
#define DK_ 64
#define D_  (H_ * DK_)        // 1024
#define ML_ (B_ * L_)         // 4096 rows for projections

// Scratch (device globals: no allocation allowed)
__device__ float g_q[(size_t)B_ * L_ * D_];
__device__ float g_k[(size_t)B_ * L_ * D_];
__device__ float g_v[(size_t)B_ * L_ * D_];
__device__ float g_attn[(size_t)B_ * L_ * D_];
__device__ int   g_mask_kind;   // 0 = uint8, 1 = int32, 2 = float32

// ---------------------------------------------------------------------------
// Sniff the storage dtype of the (0/1-valued) attention mask.
// ---------------------------------------------------------------------------
__global__ void detect_mask_kernel(const unsigned int* __restrict__ m)
{
    if (threadIdx.x == 0 && blockIdx.x == 0) {
        int all01 = 1, allf = 1;
        for (int i = 0; i < 1024; i++) {
            unsigned int w = m[i];
            if (w > 1u) all01 = 0;
            if (w != 0u && w != 0x3F800000u) allf = 0;
        }
        g_mask_kind = all01 ? 1 : (allf ? 2 : 0);
    }
}

// ---------------------------------------------------------------------------
// 128x128x8 register-blocked SGEMM:  C = alpha * A @ B^T + bias
// A: M x K (lda), B: N x K (ldb). M,N multiples of 128, K multiple of 8.
// 256 threads, 8x8 per thread (split-half fragments for conflict-free LDS.128)
// ---------------------------------------------------------------------------
__global__ __launch_bounds__(256, 2)
void gemm128(const float* __restrict__ A, int lda,
             const float* __restrict__ B, int ldb,
             float* __restrict__ C, int ldc,
             int K, const float* __restrict__ bias, float alpha)
{
    __shared__ float As[8][132];
    __shared__ float Bs[8][132];
    const int tid = threadIdx.x;
    const int tx = tid & 15, ty = tid >> 4;
    const int m0 = blockIdx.y * 128, n0 = blockIdx.x * 128;
    const int lr = tid >> 1, lc = (tid & 1) * 4;

    const float* Ap = A + (size_t)(m0 + lr) * lda + lc;
    const float* Bp = B + (size_t)(n0 + lr) * ldb + lc;

    float acc[8][8] = {};
    for (int k0 = 0; k0 < K; k0 += 8) {
        float4 av = *(const float4*)(Ap + k0);
        float4 bv = *(const float4*)(Bp + k0);
        As[lc + 0][lr] = av.x; As[lc + 1][lr] = av.y;
        As[lc + 2][lr] = av.z; As[lc + 3][lr] = av.w;
        Bs[lc + 0][lr] = bv.x; Bs[lc + 1][lr] = bv.y;
        Bs[lc + 2][lr] = bv.z; Bs[lc + 3][lr] = bv.w;
        __syncthreads();
        #pragma unroll
        for (int kk = 0; kk < 8; kk++) {
            float a[8], b[8];
            *(float4*)(a)     = *(const float4*)&As[kk][ty * 4];
            *(float4*)(a + 4) = *(const float4*)&As[kk][64 + ty * 4];
            *(float4*)(b)     = *(const float4*)&Bs[kk][tx * 4];
            *(float4*)(b + 4) = *(const float4*)&Bs[kk][64 + tx * 4];
            #pragma unroll
            for (int i = 0; i < 8; i++)
                #pragma unroll
                for (int j = 0; j < 8; j++) acc[i][j] += a[i] * b[j];
        }
        __syncthreads();
    }
    #pragma unroll
    for (int i = 0; i < 8; i++) {
        int m = m0 + ((i < 4) ? (ty * 4 + i) : (64 + ty * 4 + i - 4));
        #pragma unroll
        for (int jh = 0; jh < 2; jh++) {
            int n = n0 + jh * 64 + tx * 4;
            float4 bb = bias ? *(const float4*)&bias[n] : make_float4(0.f, 0.f, 0.f, 0.f);
            float4 o;
            o.x = acc[i][jh * 4 + 0] * alpha + bb.x;
            o.y = acc[i][jh * 4 + 1] * alpha + bb.y;
            o.z = acc[i][jh * 4 + 2] * alpha + bb.z;
            o.w = acc[i][jh * 4 + 3] * alpha + bb.w;
            *(float4*)&C[(size_t)m * ldc + n] = o;
        }
    }
}

// ---------------------------------------------------------------------------
// RoPE in-place on (B, L, H, DK) fp32 buffer. One thread per (b,l,h,j<32).
// ---------------------------------------------------------------------------
__global__ void rope_kernel(float* __restrict__ x)
{
    int idx = blockIdx.x * blockDim.x + threadIdx.x;   // 2^21 threads
    int j = idx & 31;
    int h = (idx >> 5) & 15;
    int l = (idx >> 9) & 2047;
    int b = idx >> 20;
    size_t base = (((size_t)(b * L_ + l)) * H_ + h) * DK_;
    float inv = 1.0f / powf(10000.0f, (2.0f * j) / 64.0f);
    float freq = (float)l * inv;
    float c = cosf(freq), s = sinf(freq);
    float a  = x[base + j];
    float bb = x[base + j + 32];
    x[base + j]      = a * c - bb * s;
    x[base + j + 32] = bb * c + a * s;
}

// ---------------------------------------------------------------------------
// Logits: per (b,h) 64x64 tile GEMM Q.K^T/8 + mask + bias -> weights (pre-sm)
// ---------------------------------------------------------------------------
#define TS 64
#define KT 16

__global__ void logits_kernel(const float* __restrict__ gq,
                              const float* __restrict__ gk,
                              const void* __restrict__ mask,
                              const float* __restrict__ awb,
                              float* __restrict__ Wt)
{
    const int z = blockIdx.z;          // b*H + h
    const int b = z >> 4, h = z & 15;
    const float* A  = gq + ((size_t)b * L_ * H_ + h) * DK_;   // lda = D_
    const float* Bm = gk + ((size_t)b * L_ * H_ + h) * DK_;   // ldb = D_
    const float* arow = awb + (size_t)h * L_ * L_;
    float* C = Wt + (size_t)z * L_ * L_;
    const size_t mbase = (size_t)b * L_ * L_;

    const int mk = g_mask_kind;
    const unsigned char* m8  = (const unsigned char*)mask;
    const int*           m32 = (const int*)mask;
    const float*         mf  = (const float*)mask;

    __shared__ float As[KT][TS + 4];
    __shared__ float Bs[KT][TS + 4];
    const int tid = threadIdx.x;
    const int tx = tid & 15, ty = tid >> 4;
    const int m0 = blockIdx.y * TS, n0 = blockIdx.x * TS;
    const int lr = tid >> 2, lc = (tid & 3) * 4;   // 64 rows x 16 k

    float acc[4][4] = {};
    for (int k0 = 0; k0 < DK_; k0 += KT) {
        float4 av = *(const float4*)&A[(size_t)(m0 + lr) * D_ + k0 + lc];
        float4 bv = *(const float4*)&Bm[(size_t)(n0 + lr) * D_ + k0 + lc];
        As[lc + 0][lr] = av.x; As[lc + 1][lr] = av.y;
        As[lc + 2][lr] = av.z; As[lc + 3][lr] = av.w;
        Bs[lc + 0][lr] = bv.x; Bs[lc + 1][lr] = bv.y;
        Bs[lc + 2][lr] = bv.z; Bs[lc + 3][lr] = bv.w;
        __syncthreads();
        #pragma unroll
        for (int kk = 0; kk < KT; kk++) {
            float a[4], bb[4];
            *(float4*)a  = *(const float4*)&As[kk][ty * 4];
            *(float4*)bb = *(const float4*)&Bs[kk][tx * 4];
            #pragma unroll
            for (int i = 0; i < 4; i++)
                #pragma unroll
                for (int j = 0; j < 4; j++) acc[i][j] += a[i] * bb[j];
        }
        __syncthreads();
    }
    #pragma unroll
    for (int i = 0; i < 4; i++) {
        int m = m0 + ty * 4 + i, n = n0 + tx * 4;
        size_t o = (size_t)m * L_ + n;
        float4 ar = *(const float4*)&arow[o];
        float4 res;
        float v0 = acc[i][0] * 0.125f, v1 = acc[i][1] * 0.125f;
        float v2 = acc[i][2] * 0.125f, v3 = acc[i][3] * 0.125f;
        if (mk == 1) {
            int4 mm = *(const int4*)&m32[mbase + o];
            res.x = (mm.x ? v0 : -1e30f) + ar.x;
            res.y = (mm.y ? v1 : -1e30f) + ar.y;
            res.z = (mm.z ? v2 : -1e30f) + ar.z;
            res.w = (mm.w ? v3 : -1e30f) + ar.w;
        } else if (mk == 2) {
            float4 mm = *(const float4*)&mf[mbase + o];
            res.x = (mm.x != 0.0f ? v0 : -1e30f) + ar.x;
            res.y = (mm.y != 0.0f ? v1 : -1e30f) + ar.y;
            res.z = (mm.z != 0.0f ? v2 : -1e30f) + ar.z;
            res.w = (mm.w != 0.0f ? v3 : -1e30f) + ar.w;
        } else {
            res.x = (m8[mbase + o + 0] ? v0 : -1e30f) + ar.x;
            res.y = (m8[mbase + o + 1] ? v1 : -1e30f) + ar.y;
            res.z = (m8[mbase + o + 2] ? v2 : -1e30f) + ar.z;
            res.w = (m8[mbase + o + 3] ? v3 : -1e30f) + ar.w;
        }
        *(float4*)&C[o] = res;
    }
}

// ---------------------------------------------------------------------------
// Row softmax in-place over 2048 columns. One block (256 thr) per row.
// float4 I/O + warp-shuffle reductions.
// ---------------------------------------------------------------------------
__global__ void softmax_kernel(float* __restrict__ W)
{
    float4* p = (float4*)(W + (size_t)blockIdx.x * L_);
    const int tid = threadIdx.x;
    const int lane = tid & 31, warp = tid >> 5;
    __shared__ float sm[8];

    float4 v0 = p[tid];
    float4 v1 = p[tid + 256];
    float mx = fmaxf(fmaxf(fmaxf(v0.x, v0.y), fmaxf(v0.z, v0.w)),
                     fmaxf(fmaxf(v1.x, v1.y), fmaxf(v1.z, v1.w)));
    #pragma unroll
    for (int o = 16; o > 0; o >>= 1) mx = fmaxf(mx, __shfl_xor_sync(0xffffffffu, mx, o));
    if (lane == 0) sm[warp] = mx;
    __syncthreads();
    mx = sm[0];
    #pragma unroll
    for (int w = 1; w < 8; w++) mx = fmaxf(mx, sm[w]);
    __syncthreads();

    v0.x = expf(v0.x - mx); v0.y = expf(v0.y - mx);
    v0.z = expf(v0.z - mx); v0.w = expf(v0.w - mx);
    v1.x = expf(v1.x - mx); v1.y = expf(v1.y - mx);
    v1.z = expf(v1.z - mx); v1.w = expf(v1.w - mx);
    float sum = v0.x + v0.y + v0.z + v0.w + v1.x + v1.y + v1.z + v1.w;
    #pragma unroll
    for (int o = 16; o > 0; o >>= 1) sum += __shfl_xor_sync(0xffffffffu, sum, o);
    if (lane == 0) sm[warp] = sum;
    __syncthreads();
    sum = sm[0] + sm[1] + sm[2] + sm[3] + sm[4] + sm[5] + sm[6] + sm[7];

    float inv = 1.0f / sum;
    v0.x *= inv; v0.y *= inv; v0.z *= inv; v0.w *= inv;
    v1.x *= inv; v1.y *= inv; v1.z *= inv; v1.w *= inv;
    p[tid] = v0;
    p[tid + 256] = v1;
}

// ---------------------------------------------------------------------------
// attn = weights @ V  per (b,h): (2048 x 2048) @ (2048 x 64), vectorized
// ---------------------------------------------------------------------------
__global__ void attnv_kernel(const float* __restrict__ Wt,
                             const float* __restrict__ gv,
                             float* __restrict__ gattn)
{
    const int z = blockIdx.z;
    const int b = z >> 4, h = z & 15;
    const float* A  = Wt + (size_t)z * L_ * L_;                 // lda = L_
    const float* Bm = gv + ((size_t)b * L_ * H_ + h) * DK_;     // ldb = D_
    float* C = gattn + (size_t)b * L_ * D_ + h * DK_;           // ldc = D_

    __shared__ float As[KT][TS + 4];
    __shared__ float Bs[KT][TS];
    const int tid = threadIdx.x;
    const int tx = tid & 15, ty = tid >> 4;
    const int m0 = blockIdx.y * TS;     // single n tile (N=64)
    const int lra = tid >> 2, lca = (tid & 3) * 4;   // A: 64 rows x 16 k
    const int lrb = tid >> 4, lcb = (tid & 15) * 4;  // B: 16 rows x 64 n

    float acc[4][4] = {};
    for (int k0 = 0; k0 < L_; k0 += KT) {
        float4 av = *(const float4*)&A[(size_t)(m0 + lra) * L_ + k0 + lca];
        As[lca + 0][lra] = av.x; As[lca + 1][lra] = av.y;
        As[lca + 2][lra] = av.z; As[lca + 3][lra] = av.w;
        float4 bv = *(const float4*)&Bm[(size_t)(k0 + lrb) * D_ + lcb];
        *(float4*)&Bs[lrb][lcb] = bv;
        __syncthreads();
        #pragma unroll
        for (int kk = 0; kk < KT; kk++) {
            float a[4], bb[4];
            *(float4*)a  = *(const float4*)&As[kk][ty * 4];
            *(float4*)bb = *(const float4*)&Bs[kk][tx * 4];
            #pragma unroll
            for (int i = 0; i < 4; i++)
                #pragma unroll
                for (int j = 0; j < 4; j++) acc[i][j] += a[i] * bb[j];
        }
        __syncthreads();
    }
    #pragma unroll
    for (int i = 0; i < 4; i++) {
        int m = m0 + ty * 4 + i, n = tx * 4;
        float4 o;
        o.x = acc[i][0]; o.y = acc[i][1]; o.z = acc[i][2]; o.w = acc[i][3];
        *(float4*)&C[(size_t)m * D_ + n] = o;
    }
}

// ---------------------------------------------------------------------------
extern "C" void kernel_launch(void* const* d_in, const int* in_sizes, int n_in,
                              void* d_out, int out_size)
{
    const float* query = (const float*)d_in[0];
    const float* key   = (const float*)d_in[1];
    const float* value = (const float*)d_in[2];
    const void*  mask  = d_in[3];
    const float* awb = (const float*)d_in[4];
    const float* Wq = (const float*)d_in[5];
    const float* bq = (const float*)d_in[6];
    const float* Wk = (const float*)d_in[7];
    const float* bk = (const float*)d_in[8];
    const float* Wv = (const float*)d_in[9];
    const float* bv = (const float*)d_in[10];
    const float* Wo = (const float*)d_in[11];
    const float* bo = (const float*)d_in[12];

    float* out = (float*)d_out;                              // (B, L, D)
    float* weights = out + (size_t)B_ * L_ * D_;             // (B, H, L, L)

    float *gq, *gk, *gv, *gattn;
    cudaGetSymbolAddress((void**)&gq, g_q);
    cudaGetSymbolAddress((void**)&gk, g_k);
    cudaGetSymbolAddress((void**)&gv, g_v);
    cudaGetSymbolAddress((void**)&gattn, g_attn);

    dim3 blk(256);

    // 0) Sniff mask dtype (bool may arrive as u8 / i32 / f32)
    detect_mask_kernel<<<1, 32>>>((const unsigned int*)mask);

    // 1) QKV projections: (4096 x 1024) @ W^T + b
    dim3 gproj(D_ / 128, ML_ / 128);                         // 8 x 32
    gemm128<<<gproj, blk>>>(query, D_, Wq, D_, gq, D_, D_, bq, 1.0f);
    gemm128<<<gproj, blk>>>(key,   D_, Wk, D_, gk, D_, D_, bk, 1.0f);
    gemm128<<<gproj, blk>>>(value, D_, Wv, D_, gv, D_, D_, bv, 1.0f);

    // 2) RoPE on q and k
    int nrope = B_ * L_ * H_ * 32;                           // 2^21
    rope_kernel<<<nrope / 256, 256>>>(gq);
    rope_kernel<<<nrope / 256, 256>>>(gk);

    // 3) Logits + mask + bias -> weights section of d_out (pre-softmax)
    dim3 glog(L_ / TS, L_ / TS, B_ * H_);                    // 32 x 32 x 32
    logits_kernel<<<glog, blk>>>(gq, gk, mask, awb, weights);

    // 4) Softmax (in place on d_out weights)
    softmax_kernel<<<B_ * H_ * L_, 256>>>(weights);

    // 5) attn = weights @ V  -> g_attn (B, L, H*DK)
    dim3 gat(1, L_ / TS, B_ * H_);                           // 1 x 32 x 32
    attnv_kernel<<<gat, blk>>>(weights, gv, gattn);

    // 6) Output projection: (4096 x 1024) @ Wo^T + bo -> out
    gemm128<<<gproj, blk>>>(gattn, D_, Wo, D_, out, D_, D_, bo, 1.0f);
}

// round 5
// speedup vs baseline: 1.7369x; 1.1015x over previous
#include <cuda_runtime.h>
#include <cuda_bf16.h>
#include <math.h>

// Problem constants
#define B_  2
#define L_  2048
#define H_  16
#define DK_ 64
#define D_  (H_ * DK_)        // 1024
#define ML_ (B_ * L_)         // 4096

// Scratch (device globals: no allocation allowed)
__device__ float g_q[(size_t)ML_ * D_];
__device__ float g_k[(size_t)ML_ * D_];
__device__ float g_v[(size_t)ML_ * D_];
__device__ float g_attn[(size_t)ML_ * D_];
__device__ float g_rsum[(size_t)B_ * H_ * L_];
__device__ int   g_mask_kind;   // 0 = uint8, 1 = int32, 2 = float32

// ---------------------------------------------------------------------------
// Sniff the storage dtype of the (0/1-valued) attention mask.
// ---------------------------------------------------------------------------
__global__ void detect_mask_kernel(const unsigned int* __restrict__ m)
{
    if (threadIdx.x == 0 && blockIdx.x == 0) {
        int all01 = 1, allf = 1;
        for (int i = 0; i < 1024; i++) {
            unsigned int w = m[i];
            if (w > 1u) all01 = 0;
            if (w != 0u && w != 0x3F800000u) allf = 0;
        }
        g_mask_kind = all01 ? 1 : (allf ? 2 : 0);
    }
}

// ---------------------------------------------------------------------------
// Double-buffered 128x128x8 SGEMM: C = A @ B^T + bias.  All dims = 1024/4096.
// Batched over blockIdx.z (selects A/B/C/bias set) so QKV is one launch.
// ---------------------------------------------------------------------------
__global__ __launch_bounds__(256, 2)
void gemm128db(const float* __restrict__ A0, const float* __restrict__ A1,
               const float* __restrict__ A2,
               const float* __restrict__ W0, const float* __restrict__ W1,
               const float* __restrict__ W2,
               float* __restrict__ C0, float* __restrict__ C1, float* __restrict__ C2,
               const float* __restrict__ bi0, const float* __restrict__ bi1,
               const float* __restrict__ bi2)
{
    const int z = blockIdx.z;
    const float* A  = (z == 0) ? A0 : (z == 1) ? A1 : A2;
    const float* Bw = (z == 0) ? W0 : (z == 1) ? W1 : W2;
    float* C        = (z == 0) ? C0 : (z == 1) ? C1 : C2;
    const float* bias = (z == 0) ? bi0 : (z == 1) ? bi1 : bi2;

    __shared__ float As[2][8][132];
    __shared__ float Bs[2][8][132];
    const int tid = threadIdx.x;
    const int tx = tid & 15, ty = tid >> 4;
    const int m0 = blockIdx.y * 128, n0 = blockIdx.x * 128;
    const int lr = tid >> 1, lc = (tid & 1) * 4;

    const float* Ap = A  + (size_t)(m0 + lr) * D_ + lc;
    const float* Bp = Bw + (size_t)(n0 + lr) * D_ + lc;

    float4 av = *(const float4*)Ap;
    float4 bv = *(const float4*)Bp;
    As[0][lc + 0][lr] = av.x; As[0][lc + 1][lr] = av.y;
    As[0][lc + 2][lr] = av.z; As[0][lc + 3][lr] = av.w;
    Bs[0][lc + 0][lr] = bv.x; Bs[0][lc + 1][lr] = bv.y;
    Bs[0][lc + 2][lr] = bv.z; Bs[0][lc + 3][lr] = bv.w;
    __syncthreads();

    float acc[8][8] = {};
    int buf = 0;
    for (int k0 = 8; k0 < D_; k0 += 8) {
        float4 a2 = *(const float4*)(Ap + k0);
        float4 b2 = *(const float4*)(Bp + k0);
        #pragma unroll
        for (int kk = 0; kk < 8; kk++) {
            float a[8], b[8];
            *(float4*)(a)     = *(const float4*)&As[buf][kk][ty * 4];
            *(float4*)(a + 4) = *(const float4*)&As[buf][kk][64 + ty * 4];
            *(float4*)(b)     = *(const float4*)&Bs[buf][kk][tx * 4];
            *(float4*)(b + 4) = *(const float4*)&Bs[buf][kk][64 + tx * 4];
            #pragma unroll
            for (int i = 0; i < 8; i++)
                #pragma unroll
                for (int j = 0; j < 8; j++) acc[i][j] += a[i] * b[j];
        }
        int nb = buf ^ 1;
        As[nb][lc + 0][lr] = a2.x; As[nb][lc + 1][lr] = a2.y;
        As[nb][lc + 2][lr] = a2.z; As[nb][lc + 3][lr] = a2.w;
        Bs[nb][lc + 0][lr] = b2.x; Bs[nb][lc + 1][lr] = b2.y;
        Bs[nb][lc + 2][lr] = b2.z; Bs[nb][lc + 3][lr] = b2.w;
        __syncthreads();
        buf = nb;
    }
    #pragma unroll
    for (int kk = 0; kk < 8; kk++) {
        float a[8], b[8];
        *(float4*)(a)     = *(const float4*)&As[buf][kk][ty * 4];
        *(float4*)(a + 4) = *(const float4*)&As[buf][kk][64 + ty * 4];
        *(float4*)(b)     = *(const float4*)&Bs[buf][kk][tx * 4];
        *(float4*)(b + 4) = *(const float4*)&Bs[buf][kk][64 + tx * 4];
        #pragma unroll
        for (int i = 0; i < 8; i++)
            #pragma unroll
            for (int j = 0; j < 8; j++) acc[i][j] += a[i] * b[j];
    }

    #pragma unroll
    for (int i = 0; i < 8; i++) {
        int m = m0 + ((i < 4) ? (ty * 4 + i) : (64 + ty * 4 + i - 4));
        #pragma unroll
        for (int jh = 0; jh < 2; jh++) {
            int n = n0 + jh * 64 + tx * 4;
            float4 bb = *(const float4*)&bias[n];
            float4 o;
            o.x = acc[i][jh * 4 + 0] + bb.x;
            o.y = acc[i][jh * 4 + 1] + bb.y;
            o.z = acc[i][jh * 4 + 2] + bb.z;
            o.w = acc[i][jh * 4 + 3] + bb.w;
            *(float4*)&C[(size_t)m * D_ + n] = o;
        }
    }
}

// ---------------------------------------------------------------------------
// RoPE in-place on q and k, one launch. Thread per (buf,b,l,h,j<32).
// ---------------------------------------------------------------------------
__global__ void rope_kernel(float* __restrict__ q, float* __restrict__ k)
{
    int idx = blockIdx.x * blockDim.x + threadIdx.x;   // 2 * 2^21 threads
    float* x = (idx >> 21) ? k : q;
    idx &= (1 << 21) - 1;
    int j = idx & 31;
    int h = (idx >> 5) & 15;
    int l = (idx >> 9) & 2047;
    int b = idx >> 20;
    size_t base = (((size_t)(b * L_ + l)) * H_ + h) * DK_;
    float inv = 1.0f / powf(10000.0f, (2.0f * j) / 64.0f);
    float freq = (float)l * inv;
    float c = cosf(freq), s = sinf(freq);
    float a  = x[base + j];
    float bb = x[base + j + 32];
    x[base + j]      = a * c - bb * s;
    x[base + j + 32] = bb * c + a * s;
}

// ---------------------------------------------------------------------------
// Logits: 64x64 tile GEMM Q.K^T/8, mask, +bias, then store exp(logit) and
// atomically accumulate per-row sums. z is h-major for awb L2 reuse.
// ---------------------------------------------------------------------------
#define TS 64
#define KT 16

__global__ void logits_kernel(const float* __restrict__ gq,
                              const float* __restrict__ gk,
                              const void* __restrict__ mask,
                              const float* __restrict__ awb,
                              float* __restrict__ Wt)
{
    const int z = blockIdx.z;
    const int h = z >> 1, b = z & 1;
    const int zp = b * H_ + h;                                // output plane
    const float* A  = gq + ((size_t)b * L_ * H_ + h) * DK_;   // lda = D_
    const float* Bm = gk + ((size_t)b * L_ * H_ + h) * DK_;   // ldb = D_
    const float* arow = awb + (size_t)h * L_ * L_;
    float* C = Wt + (size_t)zp * L_ * L_;
    const size_t mbase = (size_t)b * L_ * L_;

    const int mk = g_mask_kind;
    const unsigned char* m8  = (const unsigned char*)mask;
    const int*           m32 = (const int*)mask;
    const float*         mf  = (const float*)mask;

    __shared__ float As[KT][TS + 4];
    __shared__ float Bs[KT][TS + 4];
    const int tid = threadIdx.x;
    const int tx = tid & 15, ty = tid >> 4;
    const int m0 = blockIdx.y * TS, n0 = blockIdx.x * TS;
    const int lr = tid >> 2, lc = (tid & 3) * 4;

    float acc[4][4] = {};
    for (int k0 = 0; k0 < DK_; k0 += KT) {
        float4 av = *(const float4*)&A[(size_t)(m0 + lr) * D_ + k0 + lc];
        float4 bv = *(const float4*)&Bm[(size_t)(n0 + lr) * D_ + k0 + lc];
        As[lc + 0][lr] = av.x; As[lc + 1][lr] = av.y;
        As[lc + 2][lr] = av.z; As[lc + 3][lr] = av.w;
        Bs[lc + 0][lr] = bv.x; Bs[lc + 1][lr] = bv.y;
        Bs[lc + 2][lr] = bv.z; Bs[lc + 3][lr] = bv.w;
        __syncthreads();
        #pragma unroll
        for (int kk = 0; kk < KT; kk++) {
            float a[4], bb[4];
            *(float4*)a  = *(const float4*)&As[kk][ty * 4];
            *(float4*)bb = *(const float4*)&Bs[kk][tx * 4];
            #pragma unroll
            for (int i = 0; i < 4; i++)
                #pragma unroll
                for (int j = 0; j < 4; j++) acc[i][j] += a[i] * bb[j];
        }
        __syncthreads();
    }

    float rs[4];
    #pragma unroll
    for (int i = 0; i < 4; i++) {
        int m = m0 + ty * 4 + i, n = n0 + tx * 4;
        size_t o = (size_t)m * L_ + n;
        float4 ar = *(const float4*)&arow[o];
        float v0 = acc[i][0] * 0.125f, v1 = acc[i][1] * 0.125f;
        float v2 = acc[i][2] * 0.125f, v3 = acc[i][3] * 0.125f;
        if (mk == 1) {
            int4 mm = *(const int4*)&m32[mbase + o];
            v0 = mm.x ? v0 : -1e30f;  v1 = mm.y ? v1 : -1e30f;
            v2 = mm.z ? v2 : -1e30f;  v3 = mm.w ? v3 : -1e30f;
        } else if (mk == 2) {
            float4 mm = *(const float4*)&mf[mbase + o];
            v0 = (mm.x != 0.0f) ? v0 : -1e30f;  v1 = (mm.y != 0.0f) ? v1 : -1e30f;
            v2 = (mm.z != 0.0f) ? v2 : -1e30f;  v3 = (mm.w != 0.0f) ? v3 : -1e30f;
        } else {
            v0 = m8[mbase + o + 0] ? v0 : -1e30f;
            v1 = m8[mbase + o + 1] ? v1 : -1e30f;
            v2 = m8[mbase + o + 2] ? v2 : -1e30f;
            v3 = m8[mbase + o + 3] ? v3 : -1e30f;
        }
        float4 e;
        e.x = expf(fminf(v0 + ar.x, 80.0f));
        e.y = expf(fminf(v1 + ar.y, 80.0f));
        e.z = expf(fminf(v2 + ar.z, 80.0f));
        e.w = expf(fminf(v3 + ar.w, 80.0f));
        *(float4*)&C[o] = e;
        rs[i] = e.x + e.y + e.z + e.w;
    }
    // Reduce each row-partial across the 16 tx lanes, then one atomic per row.
    #pragma unroll
    for (int i = 0; i < 4; i++) {
        float s = rs[i];
        #pragma unroll
        for (int o2 = 8; o2 >= 1; o2 >>= 1)
            s += __shfl_xor_sync(0xffffffffu, s, o2);
        if (tx == 0)
            atomicAdd(&g_rsum[(size_t)zp * L_ + m0 + ty * 4 + i], s);
    }
}

// ---------------------------------------------------------------------------
// attnv_norm: read raw exp-logits, normalize by row sum, write normalized
// weights back in place, and accumulate attn = W @ V in the same pass.
// ---------------------------------------------------------------------------
__global__ void attnv_kernel(float* __restrict__ Wt,
                             const float* __restrict__ gv,
                             float* __restrict__ gattn)
{
    const int z = blockIdx.z;
    const int b = z >> 4, h = z & 15;
    float* A  = Wt + (size_t)z * L_ * L_;                       // lda = L_
    const float* Bm = gv + ((size_t)b * L_ * H_ + h) * DK_;     // ldb = D_
    float* C = gattn + (size_t)b * L_ * D_ + h * DK_;           // ldc = D_

    __shared__ float As[KT][TS + 4];
    __shared__ float Bs[KT][TS];
    __shared__ float inv_s[64];
    const int tid = threadIdx.x;
    const int tx = tid & 15, ty = tid >> 4;
    const int m0 = blockIdx.y * TS;
    const int lra = tid >> 2, lca = (tid & 3) * 4;   // A: 64 rows x 16 k
    const int lrb = tid >> 4, lcb = (tid & 15) * 4;  // V: 16 rows x 64 n

    if (tid < 64) inv_s[tid] = 1.0f / g_rsum[(size_t)z * L_ + m0 + tid];
    __syncthreads();
    const float iv = inv_s[lra];

    float acc[4][4] = {};
    for (int k0 = 0; k0 < L_; k0 += KT) {
        size_t ao = (size_t)(m0 + lra) * L_ + k0 + lca;
        float4 av = *(const float4*)&A[ao];
        av.x *= iv; av.y *= iv; av.z *= iv; av.w *= iv;
        *(float4*)&A[ao] = av;                       // normalized weights out
        As[lca + 0][lra] = av.x; As[lca + 1][lra] = av.y;
        As[lca + 2][lra] = av.z; As[lca + 3][lra] = av.w;
        float4 bv = *(const float4*)&Bm[(size_t)(k0 + lrb) * D_ + lcb];
        *(float4*)&Bs[lrb][lcb] = bv;
        __syncthreads();
        #pragma unroll
        for (int kk = 0; kk < KT; kk++) {
            float a[4], bb[4];
            *(float4*)a  = *(const float4*)&As[kk][ty * 4];
            *(float4*)bb = *(const float4*)&Bs[kk][tx * 4];
            #pragma unroll
            for (int i = 0; i < 4; i++)
                #pragma unroll
                for (int j = 0; j < 4; j++) acc[i][j] += a[i] * bb[j];
        }
        __syncthreads();
    }
    #pragma unroll
    for (int i = 0; i < 4; i++) {
        int m = m0 + ty * 4 + i, n = tx * 4;
        float4 o;
        o.x = acc[i][0]; o.y = acc[i][1]; o.z = acc[i][2]; o.w = acc[i][3];
        *(float4*)&C[(size_t)m * D_ + n] = o;
    }
}

// ---------------------------------------------------------------------------
extern "C" void kernel_launch(void* const* d_in, const int* in_sizes, int n_in,
                              void* d_out, int out_size)
{
    const float* query = (const float*)d_in[0];
    const float* key   = (const float*)d_in[1];
    const float* value = (const float*)d_in[2];
    const void*  mask  = d_in[3];
    const float* awb = (const float*)d_in[4];
    const float* Wq = (const float*)d_in[5];
    const float* bq = (const float*)d_in[6];
    const float* Wk = (const float*)d_in[7];
    const float* bk = (const float*)d_in[8];
    const float* Wv = (const float*)d_in[9];
    const float* bv = (const float*)d_in[10];
    const float* Wo = (const float*)d_in[11];
    const float* bo = (const float*)d_in[12];

    float* out = (float*)d_out;                              // (B, L, D)
    float* weights = out + (size_t)B_ * L_ * D_;             // (B, H, L, L)

    float *gq, *gk, *gv, *gattn, *grsum;
    cudaGetSymbolAddress((void**)&gq, g_q);
    cudaGetSymbolAddress((void**)&gk, g_k);
    cudaGetSymbolAddress((void**)&gv, g_v);
    cudaGetSymbolAddress((void**)&gattn, g_attn);
    cudaGetSymbolAddress((void**)&grsum, g_rsum);

    dim3 blk(256);

    // 0) mask dtype sniff + zero row sums (both capturable, deterministic)
    detect_mask_kernel<<<1, 32>>>((const unsigned int*)mask);
    cudaMemsetAsync(grsum, 0, (size_t)B_ * H_ * L_ * sizeof(float));

    // 1) QKV projections in one batched launch
    dim3 gproj(D_ / 128, ML_ / 128, 3);                      // 8 x 32 x 3
    gemm128db<<<gproj, blk>>>(query, key, value, Wq, Wk, Wv,
                              gq, gk, gv, bq, bk, bv);

    // 2) RoPE on q and k (single launch)
    rope_kernel<<<2 * (B_ * L_ * H_ * 32) / 256, 256>>>(gq, gk);

    // 3) Logits -> exp(logit) into weights buffer + row-sum atomics
    dim3 glog(L_ / TS, L_ / TS, B_ * H_);                    // z = h*2+b
    logits_kernel<<<glog, blk>>>(gq, gk, mask, awb, weights);

    // 4) Normalize weights in place + attn = W @ V
    dim3 gat(1, L_ / TS, B_ * H_);
    attnv_kernel<<<gat, blk>>>(weights, gv, gattn);

    // 5) Output projection
    dim3 gout(D_ / 128, ML_ / 128, 1);
    gemm128db<<<gout, blk>>>(gattn, gattn, gattn, Wo, Wo, Wo,
                             out, out, out, bo, bo, bo);
}

// round 7
// speedup vs baseline: 2.2360x; 1.2874x over previous
#include <cuda_runtime.h>
#include <cuda_bf16.h>
#include <math.h>
#include <stdint.h>

// Problem constants
#define B_  2
#define L_  2048
#define H_  16
#define DK_ 64
#define D_  (H_ * DK_)        // 1024
#define ML_ (B_ * L_)         // 4096

// Scratch (device globals: no allocation allowed)
__device__ float g_q[(size_t)ML_ * D_];
__device__ float g_k[(size_t)ML_ * D_];
__device__ float g_v[(size_t)ML_ * D_];
__device__ float g_attn[(size_t)ML_ * D_];
__device__ float g_rsum[(size_t)B_ * H_ * L_];
__device__ int   g_mask_kind;   // 0 = uint8, 1 = int32, 2 = float32

// ===========================================================================
// Helpers
// ===========================================================================
__device__ __forceinline__ uint32_t smem_u32(const void* p) {
    uint32_t a;
    asm("{ .reg .u64 t; cvta.to.shared.u64 t, %1; cvt.u32.u64 %0, t; }"
        : "=r"(a) : "l"(p));
    return a;
}

__device__ __forceinline__ void ldsm4(uint32_t* r, uint32_t addr) {
    asm volatile("ldmatrix.sync.aligned.m8n8.x4.shared.b16 {%0,%1,%2,%3}, [%4];"
                 : "=r"(r[0]), "=r"(r[1]), "=r"(r[2]), "=r"(r[3]) : "r"(addr));
}

__device__ __forceinline__ void mma16816(float* c, const uint32_t* a, const uint32_t* b) {
    asm volatile(
        "mma.sync.aligned.m16n8k16.row.col.f32.bf16.bf16.f32 "
        "{%0,%1,%2,%3}, {%4,%5,%6,%7}, {%8,%9}, {%0,%1,%2,%3};"
        : "+f"(c[0]), "+f"(c[1]), "+f"(c[2]), "+f"(c[3])
        : "r"(a[0]), "r"(a[1]), "r"(a[2]), "r"(a[3]), "r"(b[0]), "r"(b[1]));
}

// Split fp32 float4 -> packed hi / lo bf16x2 pairs (uint2 each)
__device__ __forceinline__ void split4(float4 v, uint2& hi, uint2& lo) {
    __nv_bfloat16 h0 = __float2bfloat16(v.x), h1 = __float2bfloat16(v.y),
                  h2 = __float2bfloat16(v.z), h3 = __float2bfloat16(v.w);
    __nv_bfloat16 l0 = __float2bfloat16(v.x - __bfloat162float(h0)),
                  l1 = __float2bfloat16(v.y - __bfloat162float(h1)),
                  l2 = __float2bfloat16(v.z - __bfloat162float(h2)),
                  l3 = __float2bfloat16(v.w - __bfloat162float(h3));
    __nv_bfloat162 hp0 = __halves2bfloat162(h0, h1);
    __nv_bfloat162 hp1 = __halves2bfloat162(h2, h3);
    __nv_bfloat162 lp0 = __halves2bfloat162(l0, l1);
    __nv_bfloat162 lp1 = __halves2bfloat162(l2, l3);
    hi = make_uint2(*(uint32_t*)&hp0, *(uint32_t*)&hp1);
    lo = make_uint2(*(uint32_t*)&lp0, *(uint32_t*)&lp1);
}

// ===========================================================================
// Mask dtype sniffer
// ===========================================================================
__global__ void detect_mask_kernel(const unsigned int* __restrict__ m)
{
    if (threadIdx.x == 0 && blockIdx.x == 0) {
        int all01 = 1, allf = 1;
        for (int i = 0; i < 1024; i++) {
            unsigned int w = m[i];
            if (w > 1u) all01 = 0;
            if (w != 0u && w != 0x3F800000u) allf = 0;
        }
        g_mask_kind = all01 ? 1 : (allf ? 2 : 0);
    }
}

// ===========================================================================
// HMMA split-bf16 projection GEMM: C = A @ W^T + bias
// A: ML x D fp32 (row-major), W: D x D fp32 (row-major = B^T col-major).
// Block 128x128, 8 warps of 64x32, k-chunk 32, 3-pass split-bf16.
// Smem rows padded to 40 bf16 (80B stride): ldmatrix conflict-free.
// ===========================================================================
#define PADK 40

__global__ __launch_bounds__(256)
void proj_mma(const float* __restrict__ A0, const float* __restrict__ A1,
              const float* __restrict__ A2,
              const float* __restrict__ W0, const float* __restrict__ W1,
              const float* __restrict__ W2,
              float* __restrict__ C0, float* __restrict__ C1, float* __restrict__ C2,
              const float* __restrict__ bi0, const float* __restrict__ bi1,
              const float* __restrict__ bi2)
{
    const int z = blockIdx.z;
    const float* A    = (z == 0) ? A0 : (z == 1) ? A1 : A2;
    const float* W    = (z == 0) ? W0 : (z == 1) ? W1 : W2;
    float* C          = (z == 0) ? C0 : (z == 1) ? C1 : C2;
    const float* bias = (z == 0) ? bi0 : (z == 1) ? bi1 : bi2;

    __shared__ __nv_bfloat16 sAh[128][PADK], sAl[128][PADK];
    __shared__ __nv_bfloat16 sBh[128][PADK], sBl[128][PADK];

    const int tid  = threadIdx.x;
    const int wid  = tid >> 5, lane = tid & 31;
    const int wm   = wid & 1, wn = wid >> 1;          // 2 x 4 warp grid
    const int m0   = blockIdx.y * 128, n0 = blockIdx.x * 128;

    const uint32_t bAh = smem_u32(sAh), bAl = smem_u32(sAl);
    const uint32_t bBh = smem_u32(sBh), bBl = smem_u32(sBl);

    // ldmatrix lane address components (byte offsets, within-tile)
    const uint32_t aoff = (uint32_t)((wm * 64 + (lane & 15)) * PADK + ((lane >> 4) << 3)) * 2;
    const uint32_t boff = (uint32_t)((wn * 32 + (lane & 7) + ((lane >> 4) << 3)) * PADK
                                     + (((lane >> 3) & 1) << 3)) * 2;

    // Loader indices: 4 iterations, each covers 32 rows x 32 k (float4 per thread)
    const int lrow = tid >> 3;            // 0..31
    const int lk   = (tid & 7) * 4;       // 0,4,..,28

    const float* Ag = A + (size_t)m0 * D_;
    const float* Wg = W + (size_t)n0 * D_;

    float acc[4][4][4] = {};

    for (int kc = 0; kc < D_; kc += 32) {
        __syncthreads();
        #pragma unroll
        for (int it = 0; it < 4; it++) {
            int r = it * 32 + lrow;
            uint2 hi, lo;
            split4(*(const float4*)&Ag[(size_t)r * D_ + kc + lk], hi, lo);
            *(uint2*)&sAh[r][lk] = hi;
            *(uint2*)&sAl[r][lk] = lo;
            split4(*(const float4*)&Wg[(size_t)r * D_ + kc + lk], hi, lo);
            *(uint2*)&sBh[r][lk] = hi;
            *(uint2*)&sBl[r][lk] = lo;
        }
        __syncthreads();

        #pragma unroll
        for (int kb = 0; kb < 32; kb += 16) {
            const uint32_t kbo = (uint32_t)kb * 2;
            uint32_t ah[4][4], al[4][4];
            #pragma unroll
            for (int i = 0; i < 4; i++) {
                uint32_t step = (uint32_t)(i * 16 * PADK) * 2;
                ldsm4(ah[i], bAh + aoff + kbo + step);
                ldsm4(al[i], bAl + aoff + kbo + step);
            }
            uint32_t bh[8], bl[8];
            ldsm4(bh,     bBh + boff + kbo);
            ldsm4(bh + 4, bBh + boff + kbo + (uint32_t)(16 * PADK) * 2);
            ldsm4(bl,     bBl + boff + kbo);
            ldsm4(bl + 4, bBl + boff + kbo + (uint32_t)(16 * PADK) * 2);
            #pragma unroll
            for (int i = 0; i < 4; i++)
                #pragma unroll
                for (int j = 0; j < 4; j++) {
                    mma16816(acc[i][j], ah[i], &bh[j * 2]);
                    mma16816(acc[i][j], ah[i], &bl[j * 2]);
                    mma16816(acc[i][j], al[i], &bh[j * 2]);
                }
        }
    }

    // Epilogue: fragment (g, 2tig) mapping, add bias, float2 stores
    const int g = lane >> 2, tig = lane & 3;
    #pragma unroll
    for (int i = 0; i < 4; i++) {
        int row = m0 + wm * 64 + i * 16 + g;
        #pragma unroll
        for (int j = 0; j < 4; j++) {
            int col = n0 + wn * 32 + j * 8 + tig * 2;
            float2 b2 = *(const float2*)&bias[col];
            float2 o0, o1;
            o0.x = acc[i][j][0] + b2.x;  o0.y = acc[i][j][1] + b2.y;
            o1.x = acc[i][j][2] + b2.x;  o1.y = acc[i][j][3] + b2.y;
            *(float2*)&C[(size_t)row * D_ + col]       = o0;
            *(float2*)&C[(size_t)(row + 8) * D_ + col] = o1;
        }
    }
}

// ---------------------------------------------------------------------------
// RoPE in-place on q and k, one launch.
// ---------------------------------------------------------------------------
__global__ void rope_kernel(float* __restrict__ q, float* __restrict__ k)
{
    int idx = blockIdx.x * blockDim.x + threadIdx.x;   // 2 * 2^21 threads
    float* x = (idx >> 21) ? k : q;
    idx &= (1 << 21) - 1;
    int j = idx & 31;
    int h = (idx >> 5) & 15;
    int l = (idx >> 9) & 2047;
    int b = idx >> 20;
    size_t base = (((size_t)(b * L_ + l)) * H_ + h) * DK_;
    float inv = 1.0f / powf(10000.0f, (2.0f * j) / 64.0f);
    float freq = (float)l * inv;
    float c = cosf(freq), s = sinf(freq);
    float a  = x[base + j];
    float bb = x[base + j + 32];
    x[base + j]      = a * c - bb * s;
    x[base + j + 32] = bb * c + a * s;
}

// ---------------------------------------------------------------------------
// Logits: 64x64 tile GEMM Q.K^T/8, mask, +bias, store exp(logit) + row sums.
// ---------------------------------------------------------------------------
#define TS 64
#define KT 16

__global__ void logits_kernel(const float* __restrict__ gq,
                              const float* __restrict__ gk,
                              const void* __restrict__ mask,
                              const float* __restrict__ awb,
                              float* __restrict__ Wt)
{
    const int z = blockIdx.z;
    const int h = z >> 1, b = z & 1;
    const int zp = b * H_ + h;
    const float* A  = gq + ((size_t)b * L_ * H_ + h) * DK_;
    const float* Bm = gk + ((size_t)b * L_ * H_ + h) * DK_;
    const float* arow = awb + (size_t)h * L_ * L_;
    float* C = Wt + (size_t)zp * L_ * L_;
    const size_t mbase = (size_t)b * L_ * L_;

    const int mk = g_mask_kind;
    const unsigned char* m8  = (const unsigned char*)mask;
    const int*           m32 = (const int*)mask;
    const float*         mf  = (const float*)mask;

    __shared__ float As[KT][TS + 4];
    __shared__ float Bs[KT][TS + 4];
    const int tid = threadIdx.x;
    const int tx = tid & 15, ty = tid >> 4;
    const int m0 = blockIdx.y * TS, n0 = blockIdx.x * TS;
    const int lr = tid >> 2, lc = (tid & 3) * 4;

    float acc[4][4] = {};
    for (int k0 = 0; k0 < DK_; k0 += KT) {
        float4 av = *(const float4*)&A[(size_t)(m0 + lr) * D_ + k0 + lc];
        float4 bv = *(const float4*)&Bm[(size_t)(n0 + lr) * D_ + k0 + lc];
        As[lc + 0][lr] = av.x; As[lc + 1][lr] = av.y;
        As[lc + 2][lr] = av.z; As[lc + 3][lr] = av.w;
        Bs[lc + 0][lr] = bv.x; Bs[lc + 1][lr] = bv.y;
        Bs[lc + 2][lr] = bv.z; Bs[lc + 3][lr] = bv.w;
        __syncthreads();
        #pragma unroll
        for (int kk = 0; kk < KT; kk++) {
            float a[4], bb[4];
            *(float4*)a  = *(const float4*)&As[kk][ty * 4];
            *(float4*)bb = *(const float4*)&Bs[kk][tx * 4];
            #pragma unroll
            for (int i = 0; i < 4; i++)
                #pragma unroll
                for (int j = 0; j < 4; j++) acc[i][j] += a[i] * bb[j];
        }
        __syncthreads();
    }

    float rs[4];
    #pragma unroll
    for (int i = 0; i < 4; i++) {
        int m = m0 + ty * 4 + i, n = n0 + tx * 4;
        size_t o = (size_t)m * L_ + n;
        float4 ar = *(const float4*)&arow[o];
        float v0 = acc[i][0] * 0.125f, v1 = acc[i][1] * 0.125f;
        float v2 = acc[i][2] * 0.125f, v3 = acc[i][3] * 0.125f;
        if (mk == 1) {
            int4 mm = *(const int4*)&m32[mbase + o];
            v0 = mm.x ? v0 : -1e30f;  v1 = mm.y ? v1 : -1e30f;
            v2 = mm.z ? v2 : -1e30f;  v3 = mm.w ? v3 : -1e30f;
        } else if (mk == 2) {
            float4 mm = *(const float4*)&mf[mbase + o];
            v0 = (mm.x != 0.0f) ? v0 : -1e30f;  v1 = (mm.y != 0.0f) ? v1 : -1e30f;
            v2 = (mm.z != 0.0f) ? v2 : -1e30f;  v3 = (mm.w != 0.0f) ? v3 : -1e30f;
        } else {
            v0 = m8[mbase + o + 0] ? v0 : -1e30f;
            v1 = m8[mbase + o + 1] ? v1 : -1e30f;
            v2 = m8[mbase + o + 2] ? v2 : -1e30f;
            v3 = m8[mbase + o + 3] ? v3 : -1e30f;
        }
        float4 e;
        e.x = expf(fminf(v0 + ar.x, 80.0f));
        e.y = expf(fminf(v1 + ar.y, 80.0f));
        e.z = expf(fminf(v2 + ar.z, 80.0f));
        e.w = expf(fminf(v3 + ar.w, 80.0f));
        *(float4*)&C[o] = e;
        rs[i] = e.x + e.y + e.z + e.w;
    }
    #pragma unroll
    for (int i = 0; i < 4; i++) {
        float s = rs[i];
        #pragma unroll
        for (int o2 = 8; o2 >= 1; o2 >>= 1)
            s += __shfl_xor_sync(0xffffffffu, s, o2);
        if (tx == 0)
            atomicAdd(&g_rsum[(size_t)zp * L_ + m0 + ty * 4 + i], s);
    }
}

// ---------------------------------------------------------------------------
// attnv: normalize exp-logits by row sum (write back) + attn = W @ V.
// ---------------------------------------------------------------------------
__global__ void attnv_kernel(float* __restrict__ Wt,
                             const float* __restrict__ gv,
                             float* __restrict__ gattn)
{
    const int z = blockIdx.z;
    const int b = z >> 4, h = z & 15;
    float* A  = Wt + (size_t)z * L_ * L_;
    const float* Bm = gv + ((size_t)b * L_ * H_ + h) * DK_;
    float* C = gattn + (size_t)b * L_ * D_ + h * DK_;

    __shared__ float As[KT][TS + 4];
    __shared__ float Bs[KT][TS];
    __shared__ float inv_s[64];
    const int tid = threadIdx.x;
    const int tx = tid & 15, ty = tid >> 4;
    const int m0 = blockIdx.y * TS;
    const int lra = tid >> 2, lca = (tid & 3) * 4;
    const int lrb = tid >> 4, lcb = (tid & 15) * 4;

    if (tid < 64) inv_s[tid] = 1.0f / g_rsum[(size_t)z * L_ + m0 + tid];
    __syncthreads();
    const float iv = inv_s[lra];

    float acc[4][4] = {};
    for (int k0 = 0; k0 < L_; k0 += KT) {
        size_t ao = (size_t)(m0 + lra) * L_ + k0 + lca;
        float4 av = *(const float4*)&A[ao];
        av.x *= iv; av.y *= iv; av.z *= iv; av.w *= iv;
        *(float4*)&A[ao] = av;
        As[lca + 0][lra] = av.x; As[lca + 1][lra] = av.y;
        As[lca + 2][lra] = av.z; As[lca + 3][lra] = av.w;
        float4 bv = *(const float4*)&Bm[(size_t)(k0 + lrb) * D_ + lcb];
        *(float4*)&Bs[lrb][lcb] = bv;
        __syncthreads();
        #pragma unroll
        for (int kk = 0; kk < KT; kk++) {
            float a[4], bb[4];
            *(float4*)a  = *(const float4*)&As[kk][ty * 4];
            *(float4*)bb = *(const float4*)&Bs[kk][tx * 4];
            #pragma unroll
            for (int i = 0; i < 4; i++)
                #pragma unroll
                for (int j = 0; j < 4; j++) acc[i][j] += a[i] * bb[j];
        }
        __syncthreads();
    }
    #pragma unroll
    for (int i = 0; i < 4; i++) {
        int m = m0 + ty * 4 + i, n = tx * 4;
        float4 o;
        o.x = acc[i][0]; o.y = acc[i][1]; o.z = acc[i][2]; o.w = acc[i][3];
        *(float4*)&C[(size_t)m * D_ + n] = o;
    }
}

// ---------------------------------------------------------------------------
extern "C" void kernel_launch(void* const* d_in, const int* in_sizes, int n_in,
                              void* d_out, int out_size)
{
    const float* query = (const float*)d_in[0];
    const float* key   = (const float*)d_in[1];
    const float* value = (const float*)d_in[2];
    const void*  mask  = d_in[3];
    const float* awb = (const float*)d_in[4];
    const float* Wq = (const float*)d_in[5];
    const float* bq = (const float*)d_in[6];
    const float* Wk = (const float*)d_in[7];
    const float* bk = (const float*)d_in[8];
    const float* Wv = (const float*)d_in[9];
    const float* bv = (const float*)d_in[10];
    const float* Wo = (const float*)d_in[11];
    const float* bo = (const float*)d_in[12];

    float* out = (float*)d_out;                              // (B, L, D)
    float* weights = out + (size_t)B_ * L_ * D_;             // (B, H, L, L)

    float *gq, *gk, *gv, *gattn, *grsum;
    cudaGetSymbolAddress((void**)&gq, g_q);
    cudaGetSymbolAddress((void**)&gk, g_k);
    cudaGetSymbolAddress((void**)&gv, g_v);
    cudaGetSymbolAddress((void**)&gattn, g_attn);
    cudaGetSymbolAddress((void**)&grsum, g_rsum);

    dim3 blk(256);

    // 0) mask dtype sniff + zero row sums
    detect_mask_kernel<<<1, 32>>>((const unsigned int*)mask);
    cudaMemsetAsync(grsum, 0, (size_t)B_ * H_ * L_ * sizeof(float));

    // 1) QKV projections via HMMA split-bf16 (one batched launch)
    dim3 gproj(D_ / 128, ML_ / 128, 3);                      // 8 x 32 x 3
    proj_mma<<<gproj, blk>>>(query, key, value, Wq, Wk, Wv,
                             gq, gk, gv, bq, bk, bv);

    // 2) RoPE on q and k
    rope_kernel<<<2 * (B_ * L_ * H_ * 32) / 256, 256>>>(gq, gk);

    // 3) Logits -> exp(logit) + row-sum atomics
    dim3 glog(L_ / TS, L_ / TS, B_ * H_);                    // z = h*2+b
    logits_kernel<<<glog, blk>>>(gq, gk, mask, awb, weights);

    // 4) Normalize weights in place + attn = W @ V
    dim3 gat(1, L_ / TS, B_ * H_);
    attnv_kernel<<<gat, blk>>>(weights, gv, gattn);

    // 5) Output projection via HMMA
    dim3 gout(D_ / 128, ML_ / 128, 1);
    proj_mma<<<gout, blk>>>(gattn, gattn, gattn, Wo, Wo, Wo,
                            out, out, out, bo, bo, bo);
}

// round 8
// speedup vs baseline: 2.3274x; 1.0409x over previous
#include <cuda_runtime.h>
#include <cuda_bf16.h>
#include <math.h>
#include <stdint.h>

// Problem constants
#define B_  2
#define L_  2048
#define H_  16
#define DK_ 64
#define D_  (H_ * DK_)        // 1024
#define ML_ (B_ * L_)         // 4096

// Scratch (device globals: no allocation allowed)
__device__ float g_q[(size_t)ML_ * D_];
__device__ float g_k[(size_t)ML_ * D_];
__device__ float g_v[(size_t)ML_ * D_];
__device__ float g_attn[(size_t)ML_ * D_];
__device__ float g_rsum[(size_t)B_ * H_ * L_];
__device__ int   g_mask_kind;   // 0 = uint8, 1 = int32, 2 = float32

// ===========================================================================
// Helpers
// ===========================================================================
__device__ __forceinline__ uint32_t smem_u32(const void* p) {
    uint32_t a;
    asm("{ .reg .u64 t; cvta.to.shared.u64 t, %1; cvt.u32.u64 %0, t; }"
        : "=r"(a) : "l"(p));
    return a;
}

__device__ __forceinline__ void ldsm4(uint32_t* r, uint32_t addr) {
    asm volatile("ldmatrix.sync.aligned.m8n8.x4.shared.b16 {%0,%1,%2,%3}, [%4];"
                 : "=r"(r[0]), "=r"(r[1]), "=r"(r[2]), "=r"(r[3]) : "r"(addr));
}

__device__ __forceinline__ void mma16816(float* c, const uint32_t* a, const uint32_t* b) {
    asm volatile(
        "mma.sync.aligned.m16n8k16.row.col.f32.bf16.bf16.f32 "
        "{%0,%1,%2,%3}, {%4,%5,%6,%7}, {%8,%9}, {%0,%1,%2,%3};"
        : "+f"(c[0]), "+f"(c[1]), "+f"(c[2]), "+f"(c[3])
        : "r"(a[0]), "r"(a[1]), "r"(a[2]), "r"(a[3]), "r"(b[0]), "r"(b[1]));
}

// Split fp32 float4 -> packed hi / lo bf16x2 pairs (uint2 each)
__device__ __forceinline__ void split4(float4 v, uint2& hi, uint2& lo) {
    __nv_bfloat16 h0 = __float2bfloat16(v.x), h1 = __float2bfloat16(v.y),
                  h2 = __float2bfloat16(v.z), h3 = __float2bfloat16(v.w);
    __nv_bfloat16 l0 = __float2bfloat16(v.x - __bfloat162float(h0)),
                  l1 = __float2bfloat16(v.y - __bfloat162float(h1)),
                  l2 = __float2bfloat16(v.z - __bfloat162float(h2)),
                  l3 = __float2bfloat16(v.w - __bfloat162float(h3));
    __nv_bfloat162 hp0 = __halves2bfloat162(h0, h1);
    __nv_bfloat162 hp1 = __halves2bfloat162(h2, h3);
    __nv_bfloat162 lp0 = __halves2bfloat162(l0, l1);
    __nv_bfloat162 lp1 = __halves2bfloat162(l2, l3);
    hi = make_uint2(*(uint32_t*)&hp0, *(uint32_t*)&hp1);
    lo = make_uint2(*(uint32_t*)&lp0, *(uint32_t*)&lp1);
}

// ===========================================================================
// Mask dtype sniffer
// ===========================================================================
__global__ void detect_mask_kernel(const unsigned int* __restrict__ m)
{
    if (threadIdx.x == 0 && blockIdx.x == 0) {
        int all01 = 1, allf = 1;
        for (int i = 0; i < 1024; i++) {
            unsigned int w = m[i];
            if (w > 1u) all01 = 0;
            if (w != 0u && w != 0x3F800000u) allf = 0;
        }
        g_mask_kind = all01 ? 1 : (allf ? 2 : 0);
    }
}

// ===========================================================================
// HMMA split-bf16 projection GEMM: C = A @ W^T + bias  (unchanged from R7)
// ===========================================================================
#define PADK 40

__global__ __launch_bounds__(256)
void proj_mma(const float* __restrict__ A0, const float* __restrict__ A1,
              const float* __restrict__ A2,
              const float* __restrict__ W0, const float* __restrict__ W1,
              const float* __restrict__ W2,
              float* __restrict__ C0, float* __restrict__ C1, float* __restrict__ C2,
              const float* __restrict__ bi0, const float* __restrict__ bi1,
              const float* __restrict__ bi2)
{
    const int z = blockIdx.z;
    const float* A    = (z == 0) ? A0 : (z == 1) ? A1 : A2;
    const float* W    = (z == 0) ? W0 : (z == 1) ? W1 : W2;
    float* C          = (z == 0) ? C0 : (z == 1) ? C1 : C2;
    const float* bias = (z == 0) ? bi0 : (z == 1) ? bi1 : bi2;

    __shared__ __nv_bfloat16 sAh[128][PADK], sAl[128][PADK];
    __shared__ __nv_bfloat16 sBh[128][PADK], sBl[128][PADK];

    const int tid  = threadIdx.x;
    const int wid  = tid >> 5, lane = tid & 31;
    const int wm   = wid & 1, wn = wid >> 1;          // 2 x 4 warp grid
    const int m0   = blockIdx.y * 128, n0 = blockIdx.x * 128;

    const uint32_t bAh = smem_u32(sAh), bAl = smem_u32(sAl);
    const uint32_t bBh = smem_u32(sBh), bBl = smem_u32(sBl);

    const uint32_t aoff = (uint32_t)((wm * 64 + (lane & 15)) * PADK + ((lane >> 4) << 3)) * 2;
    const uint32_t boff = (uint32_t)((wn * 32 + (lane & 7) + ((lane >> 4) << 3)) * PADK
                                     + (((lane >> 3) & 1) << 3)) * 2;

    const int lrow = tid >> 3;
    const int lk   = (tid & 7) * 4;

    const float* Ag = A + (size_t)m0 * D_;
    const float* Wg = W + (size_t)n0 * D_;

    float acc[4][4][4] = {};

    for (int kc = 0; kc < D_; kc += 32) {
        __syncthreads();
        #pragma unroll
        for (int it = 0; it < 4; it++) {
            int r = it * 32 + lrow;
            uint2 hi, lo;
            split4(*(const float4*)&Ag[(size_t)r * D_ + kc + lk], hi, lo);
            *(uint2*)&sAh[r][lk] = hi;
            *(uint2*)&sAl[r][lk] = lo;
            split4(*(const float4*)&Wg[(size_t)r * D_ + kc + lk], hi, lo);
            *(uint2*)&sBh[r][lk] = hi;
            *(uint2*)&sBl[r][lk] = lo;
        }
        __syncthreads();

        #pragma unroll
        for (int kb = 0; kb < 32; kb += 16) {
            const uint32_t kbo = (uint32_t)kb * 2;
            uint32_t ah[4][4], al[4][4];
            #pragma unroll
            for (int i = 0; i < 4; i++) {
                uint32_t step = (uint32_t)(i * 16 * PADK) * 2;
                ldsm4(ah[i], bAh + aoff + kbo + step);
                ldsm4(al[i], bAl + aoff + kbo + step);
            }
            uint32_t bh[8], bl[8];
            ldsm4(bh,     bBh + boff + kbo);
            ldsm4(bh + 4, bBh + boff + kbo + (uint32_t)(16 * PADK) * 2);
            ldsm4(bl,     bBl + boff + kbo);
            ldsm4(bl + 4, bBl + boff + kbo + (uint32_t)(16 * PADK) * 2);
            #pragma unroll
            for (int i = 0; i < 4; i++)
                #pragma unroll
                for (int j = 0; j < 4; j++) {
                    mma16816(acc[i][j], ah[i], &bh[j * 2]);
                    mma16816(acc[i][j], ah[i], &bl[j * 2]);
                    mma16816(acc[i][j], al[i], &bh[j * 2]);
                }
        }
    }

    const int g = lane >> 2, tig = lane & 3;
    #pragma unroll
    for (int i = 0; i < 4; i++) {
        int row = m0 + wm * 64 + i * 16 + g;
        #pragma unroll
        for (int j = 0; j < 4; j++) {
            int col = n0 + wn * 32 + j * 8 + tig * 2;
            float2 b2 = *(const float2*)&bias[col];
            float2 o0, o1;
            o0.x = acc[i][j][0] + b2.x;  o0.y = acc[i][j][1] + b2.y;
            o1.x = acc[i][j][2] + b2.x;  o1.y = acc[i][j][3] + b2.y;
            *(float2*)&C[(size_t)row * D_ + col]       = o0;
            *(float2*)&C[(size_t)(row + 8) * D_ + col] = o1;
        }
    }
}

// ---------------------------------------------------------------------------
// RoPE in-place on q and k, one launch.
// ---------------------------------------------------------------------------
__global__ void rope_kernel(float* __restrict__ q, float* __restrict__ k)
{
    int idx = blockIdx.x * blockDim.x + threadIdx.x;
    float* x = (idx >> 21) ? k : q;
    idx &= (1 << 21) - 1;
    int j = idx & 31;
    int h = (idx >> 5) & 15;
    int l = (idx >> 9) & 2047;
    int b = idx >> 20;
    size_t base = (((size_t)(b * L_ + l)) * H_ + h) * DK_;
    float inv = 1.0f / powf(10000.0f, (2.0f * j) / 64.0f);
    float freq = (float)l * inv;
    float c = cosf(freq), s = sinf(freq);
    float a  = x[base + j];
    float bb = x[base + j + 32];
    x[base + j]      = a * c - bb * s;
    x[base + j + 32] = bb * c + a * s;
}

// ===========================================================================
// HMMA logits: per (b,h) 128x128 tile of Q.K^T/8, mask, +awb, exp, rowsums.
// Same warp/fragment geometry as proj_mma; k = 64 in two 32-chunks.
// ===========================================================================
__global__ __launch_bounds__(256)
void logits_mma(const float* __restrict__ gq,
                const float* __restrict__ gk,
                const void* __restrict__ mask,
                const float* __restrict__ awb,
                float* __restrict__ Wt)
{
    const int z = blockIdx.z;
    const int h = z >> 1, b = z & 1;
    const int zp = b * H_ + h;
    const float* A  = gq + ((size_t)b * L_ * H_ + h) * DK_;   // lda = D_
    const float* Bm = gk + ((size_t)b * L_ * H_ + h) * DK_;   // ldb = D_
    const float* arow = awb + (size_t)h * L_ * L_;
    float* C = Wt + (size_t)zp * L_ * L_;
    const size_t mbase = (size_t)b * L_ * L_;

    const int mk = g_mask_kind;
    const unsigned char* m8  = (const unsigned char*)mask;
    const int*           m32 = (const int*)mask;
    const float*         mf  = (const float*)mask;

    __shared__ __nv_bfloat16 sAh[128][PADK], sAl[128][PADK];
    __shared__ __nv_bfloat16 sBh[128][PADK], sBl[128][PADK];

    const int tid  = threadIdx.x;
    const int wid  = tid >> 5, lane = tid & 31;
    const int wm   = wid & 1, wn = wid >> 1;
    const int m0   = blockIdx.y * 128, n0 = blockIdx.x * 128;

    const uint32_t bAh = smem_u32(sAh), bAl = smem_u32(sAl);
    const uint32_t bBh = smem_u32(sBh), bBl = smem_u32(sBl);

    const uint32_t aoff = (uint32_t)((wm * 64 + (lane & 15)) * PADK + ((lane >> 4) << 3)) * 2;
    const uint32_t boff = (uint32_t)((wn * 32 + (lane & 7) + ((lane >> 4) << 3)) * PADK
                                     + (((lane >> 3) & 1) << 3)) * 2;

    const int lrow = tid >> 3;
    const int lk   = (tid & 7) * 4;

    float acc[4][4][4] = {};

    for (int kc = 0; kc < DK_; kc += 32) {
        __syncthreads();
        #pragma unroll
        for (int it = 0; it < 4; it++) {
            int r = it * 32 + lrow;
            uint2 hi, lo;
            split4(*(const float4*)&A[(size_t)(m0 + r) * D_ + kc + lk], hi, lo);
            *(uint2*)&sAh[r][lk] = hi;
            *(uint2*)&sAl[r][lk] = lo;
            split4(*(const float4*)&Bm[(size_t)(n0 + r) * D_ + kc + lk], hi, lo);
            *(uint2*)&sBh[r][lk] = hi;
            *(uint2*)&sBl[r][lk] = lo;
        }
        __syncthreads();

        #pragma unroll
        for (int kb = 0; kb < 32; kb += 16) {
            const uint32_t kbo = (uint32_t)kb * 2;
            uint32_t ah[4][4], al[4][4];
            #pragma unroll
            for (int i = 0; i < 4; i++) {
                uint32_t step = (uint32_t)(i * 16 * PADK) * 2;
                ldsm4(ah[i], bAh + aoff + kbo + step);
                ldsm4(al[i], bAl + aoff + kbo + step);
            }
            uint32_t bh[8], bl[8];
            ldsm4(bh,     bBh + boff + kbo);
            ldsm4(bh + 4, bBh + boff + kbo + (uint32_t)(16 * PADK) * 2);
            ldsm4(bl,     bBl + boff + kbo);
            ldsm4(bl + 4, bBl + boff + kbo + (uint32_t)(16 * PADK) * 2);
            #pragma unroll
            for (int i = 0; i < 4; i++)
                #pragma unroll
                for (int j = 0; j < 4; j++) {
                    mma16816(acc[i][j], ah[i], &bh[j * 2]);
                    mma16816(acc[i][j], ah[i], &bl[j * 2]);
                    mma16816(acc[i][j], al[i], &bh[j * 2]);
                }
        }
    }

    // Epilogue: scale, mask, +awb, exp, store, rowsum partials -> atomics.
    const int g = lane >> 2, tig = lane & 3;
    #pragma unroll
    for (int i = 0; i < 4; i++) {
        float s0 = 0.0f, s1 = 0.0f;      // rows (..+g) and (..+g+8)
        int row = m0 + wm * 64 + i * 16 + g;
        #pragma unroll
        for (int j = 0; j < 4; j++) {
            int col = n0 + wn * 32 + j * 8 + tig * 2;
            size_t o0 = (size_t)row * L_ + col;
            size_t o1 = (size_t)(row + 8) * L_ + col;
            float2 a0 = *(const float2*)&arow[o0];
            float2 a1 = *(const float2*)&arow[o1];
            float v00 = acc[i][j][0] * 0.125f, v01 = acc[i][j][1] * 0.125f;
            float v10 = acc[i][j][2] * 0.125f, v11 = acc[i][j][3] * 0.125f;
            bool k00, k01, k10, k11;
            if (mk == 1) {
                int2 q0 = *(const int2*)&m32[mbase + o0];
                int2 q1 = *(const int2*)&m32[mbase + o1];
                k00 = q0.x != 0; k01 = q0.y != 0; k10 = q1.x != 0; k11 = q1.y != 0;
            } else if (mk == 2) {
                float2 q0 = *(const float2*)&mf[mbase + o0];
                float2 q1 = *(const float2*)&mf[mbase + o1];
                k00 = q0.x != 0.0f; k01 = q0.y != 0.0f;
                k10 = q1.x != 0.0f; k11 = q1.y != 0.0f;
            } else {
                k00 = m8[mbase + o0] != 0;     k01 = m8[mbase + o0 + 1] != 0;
                k10 = m8[mbase + o1] != 0;     k11 = m8[mbase + o1 + 1] != 0;
            }
            v00 = k00 ? v00 : -1e30f;  v01 = k01 ? v01 : -1e30f;
            v10 = k10 ? v10 : -1e30f;  v11 = k11 ? v11 : -1e30f;
            float2 e0, e1;
            e0.x = expf(fminf(v00 + a0.x, 80.0f));
            e0.y = expf(fminf(v01 + a0.y, 80.0f));
            e1.x = expf(fminf(v10 + a1.x, 80.0f));
            e1.y = expf(fminf(v11 + a1.y, 80.0f));
            *(float2*)&C[o0] = e0;
            *(float2*)&C[o1] = e1;
            s0 += e0.x + e0.y;
            s1 += e1.x + e1.y;
        }
        s0 += __shfl_xor_sync(0xffffffffu, s0, 1);
        s0 += __shfl_xor_sync(0xffffffffu, s0, 2);
        s1 += __shfl_xor_sync(0xffffffffu, s1, 1);
        s1 += __shfl_xor_sync(0xffffffffu, s1, 2);
        if (tig == 0) {
            atomicAdd(&g_rsum[(size_t)zp * L_ + row], s0);
            atomicAdd(&g_rsum[(size_t)zp * L_ + row + 8], s1);
        }
    }
}

// ===========================================================================
// HMMA attnv: normalize exp-weights by rowsum (write back fp32), split to
// bf16 hi/lo, attn = W @ V per (b,h). Block 128 rows x 64 cols, k = 2048.
// 8 warps: wm 0..3 (32 rows), wn 0..1 (32 cols). V transposed into n-major
// smem at load so B-side reuses the proven non-trans ldmatrix pattern.
// ===========================================================================
__global__ __launch_bounds__(256)
void attnv_mma(float* __restrict__ Wt,
               const float* __restrict__ gv,
               float* __restrict__ gattn)
{
    const int z = blockIdx.z;
    const int b = z >> 4, h = z & 15;
    float* A  = Wt + (size_t)z * L_ * L_;                       // lda = L_
    const float* V = gv + ((size_t)b * L_ * H_ + h) * DK_;      // ldb = D_
    float* C = gattn + (size_t)b * L_ * D_ + h * DK_;           // ldc = D_

    __shared__ __nv_bfloat16 sAh[128][PADK], sAl[128][PADK];
    __shared__ __nv_bfloat16 sVh[64][PADK],  sVl[64][PADK];
    __shared__ float inv_s[128];

    const int tid  = threadIdx.x;
    const int wid  = tid >> 5, lane = tid & 31;
    const int wm   = wid & 3, wn = wid >> 2;          // 4 x 2 warp grid
    const int m0   = blockIdx.y * 128;

    const uint32_t bAh = smem_u32(sAh), bAl = smem_u32(sAl);
    const uint32_t bVh = smem_u32(sVh), bVl = smem_u32(sVl);

    const uint32_t aoff = (uint32_t)((wm * 32 + (lane & 15)) * PADK + ((lane >> 4) << 3)) * 2;
    const uint32_t boff = (uint32_t)((wn * 32 + (lane & 7) + ((lane >> 4) << 3)) * PADK
                                     + (((lane >> 3) & 1) << 3)) * 2;

    const int lrow = tid >> 3;           // A loader: 32 rows per iter
    const int lk   = (tid & 7) * 4;
    const int vkr  = tid >> 4;           // V loader: k-row 0..15 per iter
    const int vnc  = (tid & 15) * 4;     // 4 n-cols

    if (tid < 128) inv_s[tid] = 1.0f / g_rsum[(size_t)z * L_ + m0 + tid];
    __syncthreads();

    float acc[2][4][4] = {};

    for (int kc = 0; kc < L_; kc += 32) {
        __syncthreads();
        // A: 128 x 32 exp-weights -> normalize, write back, split
        #pragma unroll
        for (int it = 0; it < 4; it++) {
            int r = it * 32 + lrow;
            size_t ao = (size_t)(m0 + r) * L_ + kc + lk;
            float4 v = *(const float4*)&A[ao];
            float iv = inv_s[r];
            v.x *= iv; v.y *= iv; v.z *= iv; v.w *= iv;
            *(float4*)&A[ao] = v;                    // normalized weights out
            uint2 hi, lo;
            split4(v, hi, lo);
            *(uint2*)&sAh[r][lk] = hi;
            *(uint2*)&sAl[r][lk] = lo;
        }
        // V: 32 k-rows x 64 n -> transpose into n-major smem
        #pragma unroll
        for (int it = 0; it < 2; it++) {
            int kr = it * 16 + vkr;
            float4 v = *(const float4*)&V[(size_t)(kc + kr) * D_ + vnc];
            uint2 hi, lo;
            split4(v, hi, lo);
            __nv_bfloat162 h0 = *(__nv_bfloat162*)&hi.x;
            __nv_bfloat162 h1 = *(__nv_bfloat162*)&hi.y;
            __nv_bfloat162 l0 = *(__nv_bfloat162*)&lo.x;
            __nv_bfloat162 l1 = *(__nv_bfloat162*)&lo.y;
            sVh[vnc + 0][kr] = __low2bfloat16(h0);
            sVh[vnc + 1][kr] = __high2bfloat16(h0);
            sVh[vnc + 2][kr] = __low2bfloat16(h1);
            sVh[vnc + 3][kr] = __high2bfloat16(h1);
            sVl[vnc + 0][kr] = __low2bfloat16(l0);
            sVl[vnc + 1][kr] = __high2bfloat16(l0);
            sVl[vnc + 2][kr] = __low2bfloat16(l1);
            sVl[vnc + 3][kr] = __high2bfloat16(l1);
        }
        __syncthreads();

        #pragma unroll
        for (int kb = 0; kb < 32; kb += 16) {
            const uint32_t kbo = (uint32_t)kb * 2;
            uint32_t ah[2][4], al[2][4];
            #pragma unroll
            for (int i = 0; i < 2; i++) {
                uint32_t step = (uint32_t)(i * 16 * PADK) * 2;
                ldsm4(ah[i], bAh + aoff + kbo + step);
                ldsm4(al[i], bAl + aoff + kbo + step);
            }
            uint32_t bh[8], bl[8];
            ldsm4(bh,     bVh + boff + kbo);
            ldsm4(bh + 4, bVh + boff + kbo + (uint32_t)(16 * PADK) * 2);
            ldsm4(bl,     bVl + boff + kbo);
            ldsm4(bl + 4, bVl + boff + kbo + (uint32_t)(16 * PADK) * 2);
            #pragma unroll
            for (int i = 0; i < 2; i++)
                #pragma unroll
                for (int j = 0; j < 4; j++) {
                    mma16816(acc[i][j], ah[i], &bh[j * 2]);
                    mma16816(acc[i][j], ah[i], &bl[j * 2]);
                    mma16816(acc[i][j], al[i], &bh[j * 2]);
                }
        }
    }

    const int g = lane >> 2, tig = lane & 3;
    #pragma unroll
    for (int i = 0; i < 2; i++) {
        int row = m0 + wm * 32 + i * 16 + g;
        #pragma unroll
        for (int j = 0; j < 4; j++) {
            int col = wn * 32 + j * 8 + tig * 2;
            float2 o0, o1;
            o0.x = acc[i][j][0];  o0.y = acc[i][j][1];
            o1.x = acc[i][j][2];  o1.y = acc[i][j][3];
            *(float2*)&C[(size_t)row * D_ + col]       = o0;
            *(float2*)&C[(size_t)(row + 8) * D_ + col] = o1;
        }
    }
}

// ---------------------------------------------------------------------------
extern "C" void kernel_launch(void* const* d_in, const int* in_sizes, int n_in,
                              void* d_out, int out_size)
{
    const float* query = (const float*)d_in[0];
    const float* key   = (const float*)d_in[1];
    const float* value = (const float*)d_in[2];
    const void*  mask  = d_in[3];
    const float* awb = (const float*)d_in[4];
    const float* Wq = (const float*)d_in[5];
    const float* bq = (const float*)d_in[6];
    const float* Wk = (const float*)d_in[7];
    const float* bk = (const float*)d_in[8];
    const float* Wv = (const float*)d_in[9];
    const float* bv = (const float*)d_in[10];
    const float* Wo = (const float*)d_in[11];
    const float* bo = (const float*)d_in[12];

    float* out = (float*)d_out;                              // (B, L, D)
    float* weights = out + (size_t)B_ * L_ * D_;             // (B, H, L, L)

    float *gq, *gk, *gv, *gattn, *grsum;
    cudaGetSymbolAddress((void**)&gq, g_q);
    cudaGetSymbolAddress((void**)&gk, g_k);
    cudaGetSymbolAddress((void**)&gv, g_v);
    cudaGetSymbolAddress((void**)&gattn, g_attn);
    cudaGetSymbolAddress((void**)&grsum, g_rsum);

    dim3 blk(256);

    // 0) mask dtype sniff + zero row sums
    detect_mask_kernel<<<1, 32>>>((const unsigned int*)mask);
    cudaMemsetAsync(grsum, 0, (size_t)B_ * H_ * L_ * sizeof(float));

    // 1) QKV projections via HMMA split-bf16
    dim3 gproj(D_ / 128, ML_ / 128, 3);
    proj_mma<<<gproj, blk>>>(query, key, value, Wq, Wk, Wv,
                             gq, gk, gv, bq, bk, bv);

    // 2) RoPE on q and k
    rope_kernel<<<2 * (B_ * L_ * H_ * 32) / 256, 256>>>(gq, gk);

    // 3) Logits via HMMA -> exp(logit) + row-sum atomics
    dim3 glog(L_ / 128, L_ / 128, B_ * H_);                  // z = h*2+b
    logits_mma<<<glog, blk>>>(gq, gk, mask, awb, weights);

    // 4) Normalize weights (write back) + attn = W @ V via HMMA
    dim3 gat(1, L_ / 128, B_ * H_);
    attnv_mma<<<gat, blk>>>(weights, gv, gattn);

    // 5) Output projection via HMMA
    dim3 gout(D_ / 128, ML_ / 128, 1);
    proj_mma<<<gout, blk>>>(gattn, gattn, gattn, Wo, Wo, Wo,
                            out, out, out, bo, bo, bo);
}

// round 10
// speedup vs baseline: 2.4080x; 1.0346x over previous
#include <cuda_runtime.h>
#include <cuda_bf16.h>
#include <math.h>
#include <stdint.h>

// Problem constants
#define B_  2
#define L_  2048
#define H_  16
#define DK_ 64
#define D_  (H_ * DK_)        // 1024
#define ML_ (B_ * L_)         // 4096

// Scratch (device globals: no allocation allowed)
__device__ float g_q[(size_t)ML_ * D_];
__device__ float g_k[(size_t)ML_ * D_];
__device__ float g_v[(size_t)ML_ * D_];
__device__ float g_attn[(size_t)ML_ * D_];
__device__ float g_rsum[(size_t)B_ * H_ * L_];
__device__ int   g_mask_kind;   // 0 = uint8, 1 = int32, 2 = float32

// ===========================================================================
// Helpers
// ===========================================================================
__device__ __forceinline__ uint32_t smem_u32(const void* p) {
    uint32_t a;
    asm("{ .reg .u64 t; cvta.to.shared.u64 t, %1; cvt.u32.u64 %0, t; }"
        : "=r"(a) : "l"(p));
    return a;
}

__device__ __forceinline__ void ldsm4(uint32_t* r, uint32_t addr) {
    asm volatile("ldmatrix.sync.aligned.m8n8.x4.shared.b16 {%0,%1,%2,%3}, [%4];"
                 : "=r"(r[0]), "=r"(r[1]), "=r"(r[2]), "=r"(r[3]) : "r"(addr));
}

__device__ __forceinline__ void mma16816(float* c, const uint32_t* a, const uint32_t* b) {
    asm volatile(
        "mma.sync.aligned.m16n8k16.row.col.f32.bf16.bf16.f32 "
        "{%0,%1,%2,%3}, {%4,%5,%6,%7}, {%8,%9}, {%0,%1,%2,%3};"
        : "+f"(c[0]), "+f"(c[1]), "+f"(c[2]), "+f"(c[3])
        : "r"(a[0]), "r"(a[1]), "r"(a[2]), "r"(a[3]), "r"(b[0]), "r"(b[1]));
}

// Split fp32 float4 -> packed hi / lo bf16x2 pairs (uint2 each)
__device__ __forceinline__ void split4(float4 v, uint2& hi, uint2& lo) {
    __nv_bfloat16 h0 = __float2bfloat16(v.x), h1 = __float2bfloat16(v.y),
                  h2 = __float2bfloat16(v.z), h3 = __float2bfloat16(v.w);
    __nv_bfloat16 l0 = __float2bfloat16(v.x - __bfloat162float(h0)),
                  l1 = __float2bfloat16(v.y - __bfloat162float(h1)),
                  l2 = __float2bfloat16(v.z - __bfloat162float(h2)),
                  l3 = __float2bfloat16(v.w - __bfloat162float(h3));
    __nv_bfloat162 hp0 = __halves2bfloat162(h0, h1);
    __nv_bfloat162 hp1 = __halves2bfloat162(h2, h3);
    __nv_bfloat162 lp0 = __halves2bfloat162(l0, l1);
    __nv_bfloat162 lp1 = __halves2bfloat162(l2, l3);
    hi = make_uint2(*(uint32_t*)&hp0, *(uint32_t*)&hp1);
    lo = make_uint2(*(uint32_t*)&lp0, *(uint32_t*)&lp1);
}

// ===========================================================================
// Mask dtype sniffer
// ===========================================================================
__global__ void detect_mask_kernel(const unsigned int* __restrict__ m)
{
    if (threadIdx.x == 0 && blockIdx.x == 0) {
        int all01 = 1, allf = 1;
        for (int i = 0; i < 1024; i++) {
            unsigned int w = m[i];
            if (w > 1u) all01 = 0;
            if (w != 0u && w != 0x3F800000u) allf = 0;
        }
        g_mask_kind = all01 ? 1 : (allf ? 2 : 0);
    }
}

// ===========================================================================
// HMMA split-bf16 projection GEMM: C = A @ W^T + bias  (unchanged, proven)
// ===========================================================================
#define PADK 40

__global__ __launch_bounds__(256)
void proj_mma(const float* __restrict__ A0, const float* __restrict__ A1,
              const float* __restrict__ A2,
              const float* __restrict__ W0, const float* __restrict__ W1,
              const float* __restrict__ W2,
              float* __restrict__ C0, float* __restrict__ C1, float* __restrict__ C2,
              const float* __restrict__ bi0, const float* __restrict__ bi1,
              const float* __restrict__ bi2)
{
    const int z = blockIdx.z;
    const float* A    = (z == 0) ? A0 : (z == 1) ? A1 : A2;
    const float* W    = (z == 0) ? W0 : (z == 1) ? W1 : W2;
    float* C          = (z == 0) ? C0 : (z == 1) ? C1 : C2;
    const float* bias = (z == 0) ? bi0 : (z == 1) ? bi1 : bi2;

    __shared__ __nv_bfloat16 sAh[128][PADK], sAl[128][PADK];
    __shared__ __nv_bfloat16 sBh[128][PADK], sBl[128][PADK];

    const int tid  = threadIdx.x;
    const int wid  = tid >> 5, lane = tid & 31;
    const int wm   = wid & 1, wn = wid >> 1;          // 2 x 4 warp grid
    const int m0   = blockIdx.y * 128, n0 = blockIdx.x * 128;

    const uint32_t bAh = smem_u32(sAh), bAl = smem_u32(sAl);
    const uint32_t bBh = smem_u32(sBh), bBl = smem_u32(sBl);

    const uint32_t aoff = (uint32_t)((wm * 64 + (lane & 15)) * PADK + ((lane >> 4) << 3)) * 2;
    const uint32_t boff = (uint32_t)((wn * 32 + (lane & 7) + ((lane >> 4) << 3)) * PADK
                                     + (((lane >> 3) & 1) << 3)) * 2;

    const int lrow = tid >> 3;
    const int lk   = (tid & 7) * 4;

    const float* Ag = A + (size_t)m0 * D_;
    const float* Wg = W + (size_t)n0 * D_;

    float acc[4][4][4] = {};

    for (int kc = 0; kc < D_; kc += 32) {
        __syncthreads();
        #pragma unroll
        for (int it = 0; it < 4; it++) {
            int r = it * 32 + lrow;
            uint2 hi, lo;
            split4(*(const float4*)&Ag[(size_t)r * D_ + kc + lk], hi, lo);
            *(uint2*)&sAh[r][lk] = hi;
            *(uint2*)&sAl[r][lk] = lo;
            split4(*(const float4*)&Wg[(size_t)r * D_ + kc + lk], hi, lo);
            *(uint2*)&sBh[r][lk] = hi;
            *(uint2*)&sBl[r][lk] = lo;
        }
        __syncthreads();

        #pragma unroll
        for (int kb = 0; kb < 32; kb += 16) {
            const uint32_t kbo = (uint32_t)kb * 2;
            uint32_t ah[4][4], al[4][4];
            #pragma unroll
            for (int i = 0; i < 4; i++) {
                uint32_t step = (uint32_t)(i * 16 * PADK) * 2;
                ldsm4(ah[i], bAh + aoff + kbo + step);
                ldsm4(al[i], bAl + aoff + kbo + step);
            }
            uint32_t bh[8], bl[8];
            ldsm4(bh,     bBh + boff + kbo);
            ldsm4(bh + 4, bBh + boff + kbo + (uint32_t)(16 * PADK) * 2);
            ldsm4(bl,     bBl + boff + kbo);
            ldsm4(bl + 4, bBl + boff + kbo + (uint32_t)(16 * PADK) * 2);
            #pragma unroll
            for (int i = 0; i < 4; i++)
                #pragma unroll
                for (int j = 0; j < 4; j++) {
                    mma16816(acc[i][j], ah[i], &bh[j * 2]);
                    mma16816(acc[i][j], ah[i], &bl[j * 2]);
                    mma16816(acc[i][j], al[i], &bh[j * 2]);
                }
        }
    }

    const int g = lane >> 2, tig = lane & 3;
    #pragma unroll
    for (int i = 0; i < 4; i++) {
        int row = m0 + wm * 64 + i * 16 + g;
        #pragma unroll
        for (int j = 0; j < 4; j++) {
            int col = n0 + wn * 32 + j * 8 + tig * 2;
            float2 b2 = *(const float2*)&bias[col];
            float2 o0, o1;
            o0.x = acc[i][j][0] + b2.x;  o0.y = acc[i][j][1] + b2.y;
            o1.x = acc[i][j][2] + b2.x;  o1.y = acc[i][j][3] + b2.y;
            *(float2*)&C[(size_t)row * D_ + col]       = o0;
            *(float2*)&C[(size_t)(row + 8) * D_ + col] = o1;
        }
    }
}

// ---------------------------------------------------------------------------
// RoPE in-place on q and k, one launch.
// ---------------------------------------------------------------------------
__global__ void rope_kernel(float* __restrict__ q, float* __restrict__ k)
{
    int idx = blockIdx.x * blockDim.x + threadIdx.x;
    float* x = (idx >> 21) ? k : q;
    idx &= (1 << 21) - 1;
    int j = idx & 31;
    int h = (idx >> 5) & 15;
    int l = (idx >> 9) & 2047;
    int b = idx >> 20;
    size_t base = (((size_t)(b * L_ + l)) * H_ + h) * DK_;
    float inv = 1.0f / powf(10000.0f, (2.0f * j) / 64.0f);
    float freq = (float)l * inv;
    float c = cosf(freq), s = sinf(freq);
    float a  = x[base + j];
    float bb = x[base + j + 32];
    x[base + j]      = a * c - bb * s;
    x[base + j + 32] = bb * c + a * s;
}

// ===========================================================================
// HMMA logits, 128x64 tile (occupancy-optimized): Q.K^T/8, mask, +awb, exp,
// rowsum atomics. Warp grid 2x4: per-warp 64 rows x 16 cols, acc 32 regs.
// ===========================================================================
__global__ __launch_bounds__(256, 3)
void logits_mma(const float* __restrict__ gq,
                const float* __restrict__ gk,
                const void* __restrict__ mask,
                const float* __restrict__ awb,
                float* __restrict__ Wt)
{
    const int z = blockIdx.z;
    const int h = z >> 1, b = z & 1;
    const int zp = b * H_ + h;
    const float* A  = gq + ((size_t)b * L_ * H_ + h) * DK_;   // lda = D_
    const float* Bm = gk + ((size_t)b * L_ * H_ + h) * DK_;   // ldb = D_
    const float* arow = awb + (size_t)h * L_ * L_;
    float* C = Wt + (size_t)zp * L_ * L_;
    const size_t mbase = (size_t)b * L_ * L_;

    const int mk = g_mask_kind;
    const unsigned char* m8  = (const unsigned char*)mask;
    const int*           m32 = (const int*)mask;
    const float*         mf  = (const float*)mask;

    __shared__ __nv_bfloat16 sAh[128][PADK], sAl[128][PADK];
    __shared__ __nv_bfloat16 sBh[64][PADK],  sBl[64][PADK];

    const int tid  = threadIdx.x;
    const int wid  = tid >> 5, lane = tid & 31;
    const int wm   = wid & 1, wn = wid >> 1;           // 2 x 4; 64 rows x 16 cols
    const int m0   = blockIdx.y * 128, n0 = blockIdx.x * 64;

    const uint32_t bAh = smem_u32(sAh), bAl = smem_u32(sAl);
    const uint32_t bBh = smem_u32(sBh), bBl = smem_u32(sBl);

    const uint32_t aoff = (uint32_t)((wm * 64 + (lane & 15)) * PADK + ((lane >> 4) << 3)) * 2;
    const uint32_t boff = (uint32_t)((wn * 16 + (lane & 7) + ((lane >> 4) << 3)) * PADK
                                     + (((lane >> 3) & 1) << 3)) * 2;

    const int lrow = tid >> 3;
    const int lk   = (tid & 7) * 4;

    float acc[4][2][4] = {};

    for (int kc = 0; kc < DK_; kc += 32) {
        __syncthreads();
        #pragma unroll
        for (int it = 0; it < 4; it++) {
            int r = it * 32 + lrow;
            uint2 hi, lo;
            split4(*(const float4*)&A[(size_t)(m0 + r) * D_ + kc + lk], hi, lo);
            *(uint2*)&sAh[r][lk] = hi;
            *(uint2*)&sAl[r][lk] = lo;
        }
        #pragma unroll
        for (int it = 0; it < 2; it++) {
            int r = it * 32 + lrow;
            uint2 hi, lo;
            split4(*(const float4*)&Bm[(size_t)(n0 + r) * D_ + kc + lk], hi, lo);
            *(uint2*)&sBh[r][lk] = hi;
            *(uint2*)&sBl[r][lk] = lo;
        }
        __syncthreads();

        #pragma unroll
        for (int kb = 0; kb < 32; kb += 16) {
            const uint32_t kbo = (uint32_t)kb * 2;
            uint32_t ah[4][4], al[4][4];
            #pragma unroll
            for (int i = 0; i < 4; i++) {
                uint32_t step = (uint32_t)(i * 16 * PADK) * 2;
                ldsm4(ah[i], bAh + aoff + kbo + step);
                ldsm4(al[i], bAl + aoff + kbo + step);
            }
            uint32_t bh[4], bl[4];
            ldsm4(bh, bBh + boff + kbo);
            ldsm4(bl, bBl + boff + kbo);
            #pragma unroll
            for (int i = 0; i < 4; i++)
                #pragma unroll
                for (int j = 0; j < 2; j++) {
                    mma16816(acc[i][j], ah[i], &bh[j * 2]);
                    mma16816(acc[i][j], ah[i], &bl[j * 2]);
                    mma16816(acc[i][j], al[i], &bh[j * 2]);
                }
        }
    }

    // Epilogue: scale, mask, +awb, exp, store, rowsum partials -> atomics.
    const int g = lane >> 2, tig = lane & 3;
    #pragma unroll
    for (int i = 0; i < 4; i++) {
        float s0 = 0.0f, s1 = 0.0f;
        int row = m0 + wm * 64 + i * 16 + g;
        #pragma unroll
        for (int j = 0; j < 2; j++) {
            int col = n0 + wn * 16 + j * 8 + tig * 2;
            size_t o0 = (size_t)row * L_ + col;
            size_t o1 = (size_t)(row + 8) * L_ + col;
            float2 a0 = *(const float2*)&arow[o0];
            float2 a1 = *(const float2*)&arow[o1];
            float v00 = acc[i][j][0] * 0.125f, v01 = acc[i][j][1] * 0.125f;
            float v10 = acc[i][j][2] * 0.125f, v11 = acc[i][j][3] * 0.125f;
            bool k00, k01, k10, k11;
            if (mk == 1) {
                int2 q0 = *(const int2*)&m32[mbase + o0];
                int2 q1 = *(const int2*)&m32[mbase + o1];
                k00 = q0.x != 0; k01 = q0.y != 0; k10 = q1.x != 0; k11 = q1.y != 0;
            } else if (mk == 2) {
                float2 q0 = *(const float2*)&mf[mbase + o0];
                float2 q1 = *(const float2*)&mf[mbase + o1];
                k00 = q0.x != 0.0f; k01 = q0.y != 0.0f;
                k10 = q1.x != 0.0f; k11 = q1.y != 0.0f;
            } else {
                k00 = m8[mbase + o0] != 0;     k01 = m8[mbase + o0 + 1] != 0;
                k10 = m8[mbase + o1] != 0;     k11 = m8[mbase + o1 + 1] != 0;
            }
            v00 = k00 ? v00 : -1e30f;  v01 = k01 ? v01 : -1e30f;
            v10 = k10 ? v10 : -1e30f;  v11 = k11 ? v11 : -1e30f;
            float2 e0, e1;
            e0.x = expf(fminf(v00 + a0.x, 80.0f));
            e0.y = expf(fminf(v01 + a0.y, 80.0f));
            e1.x = expf(fminf(v10 + a1.x, 80.0f));
            e1.y = expf(fminf(v11 + a1.y, 80.0f));
            *(float2*)&C[o0] = e0;
            *(float2*)&C[o1] = e1;
            s0 += e0.x + e0.y;
            s1 += e1.x + e1.y;
        }
        s0 += __shfl_xor_sync(0xffffffffu, s0, 1);
        s0 += __shfl_xor_sync(0xffffffffu, s0, 2);
        s1 += __shfl_xor_sync(0xffffffffu, s1, 1);
        s1 += __shfl_xor_sync(0xffffffffu, s1, 2);
        if (tig == 0) {
            atomicAdd(&g_rsum[(size_t)zp * L_ + row], s0);
            atomicAdd(&g_rsum[(size_t)zp * L_ + row + 8], s1);
        }
    }
}

// ===========================================================================
// HMMA attnv: normalize exp-weights by rowsum (write back fp32), split to
// bf16 hi/lo, attn = W @ V per (b,h). Forced occupancy 3.
// ===========================================================================
__global__ __launch_bounds__(256, 3)
void attnv_mma(float* __restrict__ Wt,
               const float* __restrict__ gv,
               float* __restrict__ gattn)
{
    const int z = blockIdx.z;
    const int b = z >> 4, h = z & 15;
    float* A  = Wt + (size_t)z * L_ * L_;                       // lda = L_
    const float* V = gv + ((size_t)b * L_ * H_ + h) * DK_;      // ldb = D_
    float* C = gattn + (size_t)b * L_ * D_ + h * DK_;           // ldc = D_

    __shared__ __nv_bfloat16 sAh[128][PADK], sAl[128][PADK];
    __shared__ __nv_bfloat16 sVh[64][PADK],  sVl[64][PADK];
    __shared__ float inv_s[128];

    const int tid  = threadIdx.x;
    const int wid  = tid >> 5, lane = tid & 31;
    const int wm   = wid & 3, wn = wid >> 2;          // 4 x 2 warp grid
    const int m0   = blockIdx.y * 128;

    const uint32_t bAh = smem_u32(sAh), bAl = smem_u32(sAl);
    const uint32_t bVh = smem_u32(sVh), bVl = smem_u32(sVl);

    const uint32_t aoff = (uint32_t)((wm * 32 + (lane & 15)) * PADK + ((lane >> 4) << 3)) * 2;
    const uint32_t boff = (uint32_t)((wn * 32 + (lane & 7) + ((lane >> 4) << 3)) * PADK
                                     + (((lane >> 3) & 1) << 3)) * 2;

    const int lrow = tid >> 3;
    const int lk   = (tid & 7) * 4;
    const int vkr  = tid >> 4;
    const int vnc  = (tid & 15) * 4;

    if (tid < 128) inv_s[tid] = 1.0f / g_rsum[(size_t)z * L_ + m0 + tid];
    __syncthreads();

    float acc[2][4][4] = {};

    for (int kc = 0; kc < L_; kc += 32) {
        __syncthreads();
        #pragma unroll
        for (int it = 0; it < 4; it++) {
            int r = it * 32 + lrow;
            size_t ao = (size_t)(m0 + r) * L_ + kc + lk;
            float4 v = *(const float4*)&A[ao];
            float iv = inv_s[r];
            v.x *= iv; v.y *= iv; v.z *= iv; v.w *= iv;
            *(float4*)&A[ao] = v;
            uint2 hi, lo;
            split4(v, hi, lo);
            *(uint2*)&sAh[r][lk] = hi;
            *(uint2*)&sAl[r][lk] = lo;
        }
        #pragma unroll
        for (int it = 0; it < 2; it++) {
            int kr = it * 16 + vkr;
            float4 v = *(const float4*)&V[(size_t)(kc + kr) * D_ + vnc];
            uint2 hi, lo;
            split4(v, hi, lo);
            __nv_bfloat162 h0 = *(__nv_bfloat162*)&hi.x;
            __nv_bfloat162 h1 = *(__nv_bfloat162*)&hi.y;
            __nv_bfloat162 l0 = *(__nv_bfloat162*)&lo.x;
            __nv_bfloat162 l1 = *(__nv_bfloat162*)&lo.y;
            sVh[vnc + 0][kr] = __low2bfloat16(h0);
            sVh[vnc + 1][kr] = __high2bfloat16(h0);
            sVh[vnc + 2][kr] = __low2bfloat16(h1);
            sVh[vnc + 3][kr] = __high2bfloat16(h1);
            sVl[vnc + 0][kr] = __low2bfloat16(l0);
            sVl[vnc + 1][kr] = __high2bfloat16(l0);
            sVl[vnc + 2][kr] = __low2bfloat16(l1);
            sVl[vnc + 3][kr] = __high2bfloat16(l1);
        }
        __syncthreads();

        #pragma unroll
        for (int kb = 0; kb < 32; kb += 16) {
            const uint32_t kbo = (uint32_t)kb * 2;
            uint32_t ah[2][4], al[2][4];
            #pragma unroll
            for (int i = 0; i < 2; i++) {
                uint32_t step = (uint32_t)(i * 16 * PADK) * 2;
                ldsm4(ah[i], bAh + aoff + kbo + step);
                ldsm4(al[i], bAl + aoff + kbo + step);
            }
            uint32_t bh[8], bl[8];
            ldsm4(bh,     bVh + boff + kbo);
            ldsm4(bh + 4, bVh + boff + kbo + (uint32_t)(16 * PADK) * 2);
            ldsm4(bl,     bVl + boff + kbo);
            ldsm4(bl + 4, bVl + boff + kbo + (uint32_t)(16 * PADK) * 2);
            #pragma unroll
            for (int i = 0; i < 2; i++)
                #pragma unroll
                for (int j = 0; j < 4; j++) {
                    mma16816(acc[i][j], ah[i], &bh[j * 2]);
                    mma16816(acc[i][j], ah[i], &bl[j * 2]);
                    mma16816(acc[i][j], al[i], &bh[j * 2]);
                }
        }
    }

    const int g = lane >> 2, tig = lane & 3;
    #pragma unroll
    for (int i = 0; i < 2; i++) {
        int row = m0 + wm * 32 + i * 16 + g;
        #pragma unroll
        for (int j = 0; j < 4; j++) {
            int col = wn * 32 + j * 8 + tig * 2;
            float2 o0, o1;
            o0.x = acc[i][j][0];  o0.y = acc[i][j][1];
            o1.x = acc[i][j][2];  o1.y = acc[i][j][3];
            *(float2*)&C[(size_t)row * D_ + col]       = o0;
            *(float2*)&C[(size_t)(row + 8) * D_ + col] = o1;
        }
    }
}

// ---------------------------------------------------------------------------
extern "C" void kernel_launch(void* const* d_in, const int* in_sizes, int n_in,
                              void* d_out, int out_size)
{
    const float* query = (const float*)d_in[0];
    const float* key   = (const float*)d_in[1];
    const float* value = (const float*)d_in[2];
    const void*  mask  = d_in[3];
    const float* awb = (const float*)d_in[4];
    const float* Wq = (const float*)d_in[5];
    const float* bq = (const float*)d_in[6];
    const float* Wk = (const float*)d_in[7];
    const float* bk = (const float*)d_in[8];
    const float* Wv = (const float*)d_in[9];
    const float* bv = (const float*)d_in[10];
    const float* Wo = (const float*)d_in[11];
    const float* bo = (const float*)d_in[12];

    float* out = (float*)d_out;                              // (B, L, D)
    float* weights = out + (size_t)B_ * L_ * D_;             // (B, H, L, L)

    float *gq, *gk, *gv, *gattn, *grsum;
    cudaGetSymbolAddress((void**)&gq, g_q);
    cudaGetSymbolAddress((void**)&gk, g_k);
    cudaGetSymbolAddress((void**)&gv, g_v);
    cudaGetSymbolAddress((void**)&gattn, g_attn);
    cudaGetSymbolAddress((void**)&grsum, g_rsum);

    dim3 blk(256);

    // 0) mask dtype sniff + zero row sums
    detect_mask_kernel<<<1, 32>>>((const unsigned int*)mask);
    cudaMemsetAsync(grsum, 0, (size_t)B_ * H_ * L_ * sizeof(float));

    // 1) QKV projections via HMMA split-bf16
    dim3 gproj(D_ / 128, ML_ / 128, 3);
    proj_mma<<<gproj, blk>>>(query, key, value, Wq, Wk, Wv,
                             gq, gk, gv, bq, bk, bv);

    // 2) RoPE on q and k
    rope_kernel<<<2 * (B_ * L_ * H_ * 32) / 256, 256>>>(gq, gk);

    // 3) Logits via HMMA (128x64 tiles) -> exp(logit) + row-sum atomics
    dim3 glog(L_ / 64, L_ / 128, B_ * H_);                   // 32 x 16 x 32
    logits_mma<<<glog, blk>>>(gq, gk, mask, awb, weights);

    // 4) Normalize weights (write back) + attn = W @ V via HMMA
    dim3 gat(1, L_ / 128, B_ * H_);
    attnv_mma<<<gat, blk>>>(weights, gv, gattn);

    // 5) Output projection via HMMA
    dim3 gout(D_ / 128, ML_ / 128, 1);
    proj_mma<<<gout, blk>>>(gattn, gattn, gattn, Wo, Wo, Wo,
                            out, out, out, bo, bo, bo);
}

// round 11
// speedup vs baseline: 2.7843x; 1.1563x over previous
#include <cuda_runtime.h>
#include <cuda_bf16.h>
#include <math.h>
#include <stdint.h>

// Problem constants
#define B_  2
#define L_  2048
#define H_  16
#define DK_ 64
#define D_  (H_ * DK_)        // 1024
#define ML_ (B_ * L_)         // 4096
#define KSPLIT 4
#define KCH (L_ / KSPLIT)     // 512

// Scratch (device globals: no allocation allowed)
__device__ float g_q[(size_t)ML_ * D_];
__device__ float g_k[(size_t)ML_ * D_];
__device__ float g_v[(size_t)ML_ * D_];
__device__ float g_attn[(size_t)ML_ * D_];
__device__ float g_part[KSPLIT][(size_t)ML_ * D_];
__device__ float g_rsum[(size_t)B_ * H_ * L_];
__device__ int   g_mask_kind;   // 0 = uint8, 1 = int32, 2 = float32

// ===========================================================================
// Helpers
// ===========================================================================
__device__ __forceinline__ uint32_t smem_u32(const void* p) {
    uint32_t a;
    asm("{ .reg .u64 t; cvta.to.shared.u64 t, %1; cvt.u32.u64 %0, t; }"
        : "=r"(a) : "l"(p));
    return a;
}

__device__ __forceinline__ void ldsm4(uint32_t* r, uint32_t addr) {
    asm volatile("ldmatrix.sync.aligned.m8n8.x4.shared.b16 {%0,%1,%2,%3}, [%4];"
                 : "=r"(r[0]), "=r"(r[1]), "=r"(r[2]), "=r"(r[3]) : "r"(addr));
}

__device__ __forceinline__ void mma16816(float* c, const uint32_t* a, const uint32_t* b) {
    asm volatile(
        "mma.sync.aligned.m16n8k16.row.col.f32.bf16.bf16.f32 "
        "{%0,%1,%2,%3}, {%4,%5,%6,%7}, {%8,%9}, {%0,%1,%2,%3};"
        : "+f"(c[0]), "+f"(c[1]), "+f"(c[2]), "+f"(c[3])
        : "r"(a[0]), "r"(a[1]), "r"(a[2]), "r"(a[3]), "r"(b[0]), "r"(b[1]));
}

// Split fp32 float4 -> packed hi / lo bf16x2 pairs (uint2 each)
__device__ __forceinline__ void split4(float4 v, uint2& hi, uint2& lo) {
    __nv_bfloat16 h0 = __float2bfloat16(v.x), h1 = __float2bfloat16(v.y),
                  h2 = __float2bfloat16(v.z), h3 = __float2bfloat16(v.w);
    __nv_bfloat16 l0 = __float2bfloat16(v.x - __bfloat162float(h0)),
                  l1 = __float2bfloat16(v.y - __bfloat162float(h1)),
                  l2 = __float2bfloat16(v.z - __bfloat162float(h2)),
                  l3 = __float2bfloat16(v.w - __bfloat162float(h3));
    __nv_bfloat162 hp0 = __halves2bfloat162(h0, h1);
    __nv_bfloat162 hp1 = __halves2bfloat162(h2, h3);
    __nv_bfloat162 lp0 = __halves2bfloat162(l0, l1);
    __nv_bfloat162 lp1 = __halves2bfloat162(l2, l3);
    hi = make_uint2(*(uint32_t*)&hp0, *(uint32_t*)&hp1);
    lo = make_uint2(*(uint32_t*)&lp0, *(uint32_t*)&lp1);
}

// ===========================================================================
// Mask dtype sniffer
// ===========================================================================
__global__ void detect_mask_kernel(const unsigned int* __restrict__ m)
{
    if (threadIdx.x == 0 && blockIdx.x == 0) {
        int all01 = 1, allf = 1;
        for (int i = 0; i < 1024; i++) {
            unsigned int w = m[i];
            if (w > 1u) all01 = 0;
            if (w != 0u && w != 0x3F800000u) allf = 0;
        }
        g_mask_kind = all01 ? 1 : (allf ? 2 : 0);
    }
}

// ===========================================================================
// HMMA split-bf16 projection GEMM: C = A @ W^T + bias  (unchanged, proven)
// ===========================================================================
#define PADK 40

__global__ __launch_bounds__(256)
void proj_mma(const float* __restrict__ A0, const float* __restrict__ A1,
              const float* __restrict__ A2,
              const float* __restrict__ W0, const float* __restrict__ W1,
              const float* __restrict__ W2,
              float* __restrict__ C0, float* __restrict__ C1, float* __restrict__ C2,
              const float* __restrict__ bi0, const float* __restrict__ bi1,
              const float* __restrict__ bi2)
{
    const int z = blockIdx.z;
    const float* A    = (z == 0) ? A0 : (z == 1) ? A1 : A2;
    const float* W    = (z == 0) ? W0 : (z == 1) ? W1 : W2;
    float* C          = (z == 0) ? C0 : (z == 1) ? C1 : C2;
    const float* bias = (z == 0) ? bi0 : (z == 1) ? bi1 : bi2;

    __shared__ __nv_bfloat16 sAh[128][PADK], sAl[128][PADK];
    __shared__ __nv_bfloat16 sBh[128][PADK], sBl[128][PADK];

    const int tid  = threadIdx.x;
    const int wid  = tid >> 5, lane = tid & 31;
    const int wm   = wid & 1, wn = wid >> 1;          // 2 x 4 warp grid
    const int m0   = blockIdx.y * 128, n0 = blockIdx.x * 128;

    const uint32_t bAh = smem_u32(sAh), bAl = smem_u32(sAl);
    const uint32_t bBh = smem_u32(sBh), bBl = smem_u32(sBl);

    const uint32_t aoff = (uint32_t)((wm * 64 + (lane & 15)) * PADK + ((lane >> 4) << 3)) * 2;
    const uint32_t boff = (uint32_t)((wn * 32 + (lane & 7) + ((lane >> 4) << 3)) * PADK
                                     + (((lane >> 3) & 1) << 3)) * 2;

    const int lrow = tid >> 3;
    const int lk   = (tid & 7) * 4;

    const float* Ag = A + (size_t)m0 * D_;
    const float* Wg = W + (size_t)n0 * D_;

    float acc[4][4][4] = {};

    for (int kc = 0; kc < D_; kc += 32) {
        __syncthreads();
        #pragma unroll
        for (int it = 0; it < 4; it++) {
            int r = it * 32 + lrow;
            uint2 hi, lo;
            split4(*(const float4*)&Ag[(size_t)r * D_ + kc + lk], hi, lo);
            *(uint2*)&sAh[r][lk] = hi;
            *(uint2*)&sAl[r][lk] = lo;
            split4(*(const float4*)&Wg[(size_t)r * D_ + kc + lk], hi, lo);
            *(uint2*)&sBh[r][lk] = hi;
            *(uint2*)&sBl[r][lk] = lo;
        }
        __syncthreads();

        #pragma unroll
        for (int kb = 0; kb < 32; kb += 16) {
            const uint32_t kbo = (uint32_t)kb * 2;
            uint32_t ah[4][4], al[4][4];
            #pragma unroll
            for (int i = 0; i < 4; i++) {
                uint32_t step = (uint32_t)(i * 16 * PADK) * 2;
                ldsm4(ah[i], bAh + aoff + kbo + step);
                ldsm4(al[i], bAl + aoff + kbo + step);
            }
            uint32_t bh[8], bl[8];
            ldsm4(bh,     bBh + boff + kbo);
            ldsm4(bh + 4, bBh + boff + kbo + (uint32_t)(16 * PADK) * 2);
            ldsm4(bl,     bBl + boff + kbo);
            ldsm4(bl + 4, bBl + boff + kbo + (uint32_t)(16 * PADK) * 2);
            #pragma unroll
            for (int i = 0; i < 4; i++)
                #pragma unroll
                for (int j = 0; j < 4; j++) {
                    mma16816(acc[i][j], ah[i], &bh[j * 2]);
                    mma16816(acc[i][j], ah[i], &bl[j * 2]);
                    mma16816(acc[i][j], al[i], &bh[j * 2]);
                }
        }
    }

    const int g = lane >> 2, tig = lane & 3;
    #pragma unroll
    for (int i = 0; i < 4; i++) {
        int row = m0 + wm * 64 + i * 16 + g;
        #pragma unroll
        for (int j = 0; j < 4; j++) {
            int col = n0 + wn * 32 + j * 8 + tig * 2;
            float2 b2 = *(const float2*)&bias[col];
            float2 o0, o1;
            o0.x = acc[i][j][0] + b2.x;  o0.y = acc[i][j][1] + b2.y;
            o1.x = acc[i][j][2] + b2.x;  o1.y = acc[i][j][3] + b2.y;
            *(float2*)&C[(size_t)row * D_ + col]       = o0;
            *(float2*)&C[(size_t)(row + 8) * D_ + col] = o1;
        }
    }
}

// ---------------------------------------------------------------------------
// RoPE in-place on q and k, one launch.
// ---------------------------------------------------------------------------
__global__ void rope_kernel(float* __restrict__ q, float* __restrict__ k)
{
    int idx = blockIdx.x * blockDim.x + threadIdx.x;
    float* x = (idx >> 21) ? k : q;
    idx &= (1 << 21) - 1;
    int j = idx & 31;
    int h = (idx >> 5) & 15;
    int l = (idx >> 9) & 2047;
    int b = idx >> 20;
    size_t base = (((size_t)(b * L_ + l)) * H_ + h) * DK_;
    float inv = 1.0f / powf(10000.0f, (2.0f * j) / 64.0f);
    float freq = (float)l * inv;
    float c = cosf(freq), s = sinf(freq);
    float a  = x[base + j];
    float bb = x[base + j + 32];
    x[base + j]      = a * c - bb * s;
    x[base + j + 32] = bb * c + a * s;
}

// ===========================================================================
// HMMA logits, 128x64 tile: Q.K^T/8, mask, +awb, exp, rowsum atomics.
// ===========================================================================
__global__ __launch_bounds__(256, 3)
void logits_mma(const float* __restrict__ gq,
                const float* __restrict__ gk,
                const void* __restrict__ mask,
                const float* __restrict__ awb,
                float* __restrict__ Wt)
{
    const int z = blockIdx.z;
    const int h = z >> 1, b = z & 1;
    const int zp = b * H_ + h;
    const float* A  = gq + ((size_t)b * L_ * H_ + h) * DK_;   // lda = D_
    const float* Bm = gk + ((size_t)b * L_ * H_ + h) * DK_;   // ldb = D_
    const float* arow = awb + (size_t)h * L_ * L_;
    float* C = Wt + (size_t)zp * L_ * L_;
    const size_t mbase = (size_t)b * L_ * L_;

    const int mk = g_mask_kind;
    const unsigned char* m8  = (const unsigned char*)mask;
    const int*           m32 = (const int*)mask;
    const float*         mf  = (const float*)mask;

    __shared__ __nv_bfloat16 sAh[128][PADK], sAl[128][PADK];
    __shared__ __nv_bfloat16 sBh[64][PADK],  sBl[64][PADK];

    const int tid  = threadIdx.x;
    const int wid  = tid >> 5, lane = tid & 31;
    const int wm   = wid & 1, wn = wid >> 1;           // 2 x 4; 64 rows x 16 cols
    const int m0   = blockIdx.y * 128, n0 = blockIdx.x * 64;

    const uint32_t bAh = smem_u32(sAh), bAl = smem_u32(sAl);
    const uint32_t bBh = smem_u32(sBh), bBl = smem_u32(sBl);

    const uint32_t aoff = (uint32_t)((wm * 64 + (lane & 15)) * PADK + ((lane >> 4) << 3)) * 2;
    const uint32_t boff = (uint32_t)((wn * 16 + (lane & 7) + ((lane >> 4) << 3)) * PADK
                                     + (((lane >> 3) & 1) << 3)) * 2;

    const int lrow = tid >> 3;
    const int lk   = (tid & 7) * 4;

    float acc[4][2][4] = {};

    for (int kc = 0; kc < DK_; kc += 32) {
        __syncthreads();
        #pragma unroll
        for (int it = 0; it < 4; it++) {
            int r = it * 32 + lrow;
            uint2 hi, lo;
            split4(*(const float4*)&A[(size_t)(m0 + r) * D_ + kc + lk], hi, lo);
            *(uint2*)&sAh[r][lk] = hi;
            *(uint2*)&sAl[r][lk] = lo;
        }
        #pragma unroll
        for (int it = 0; it < 2; it++) {
            int r = it * 32 + lrow;
            uint2 hi, lo;
            split4(*(const float4*)&Bm[(size_t)(n0 + r) * D_ + kc + lk], hi, lo);
            *(uint2*)&sBh[r][lk] = hi;
            *(uint2*)&sBl[r][lk] = lo;
        }
        __syncthreads();

        #pragma unroll
        for (int kb = 0; kb < 32; kb += 16) {
            const uint32_t kbo = (uint32_t)kb * 2;
            uint32_t ah[4][4], al[4][4];
            #pragma unroll
            for (int i = 0; i < 4; i++) {
                uint32_t step = (uint32_t)(i * 16 * PADK) * 2;
                ldsm4(ah[i], bAh + aoff + kbo + step);
                ldsm4(al[i], bAl + aoff + kbo + step);
            }
            uint32_t bh[4], bl[4];
            ldsm4(bh, bBh + boff + kbo);
            ldsm4(bl, bBl + boff + kbo);
            #pragma unroll
            for (int i = 0; i < 4; i++)
                #pragma unroll
                for (int j = 0; j < 2; j++) {
                    mma16816(acc[i][j], ah[i], &bh[j * 2]);
                    mma16816(acc[i][j], ah[i], &bl[j * 2]);
                    mma16816(acc[i][j], al[i], &bh[j * 2]);
                }
        }
    }

    // Epilogue: scale, mask, +awb, exp, store, rowsum partials -> atomics.
    const int g = lane >> 2, tig = lane & 3;
    #pragma unroll
    for (int i = 0; i < 4; i++) {
        float s0 = 0.0f, s1 = 0.0f;
        int row = m0 + wm * 64 + i * 16 + g;
        #pragma unroll
        for (int j = 0; j < 2; j++) {
            int col = n0 + wn * 16 + j * 8 + tig * 2;
            size_t o0 = (size_t)row * L_ + col;
            size_t o1 = (size_t)(row + 8) * L_ + col;
            float2 a0 = *(const float2*)&arow[o0];
            float2 a1 = *(const float2*)&arow[o1];
            float v00 = acc[i][j][0] * 0.125f, v01 = acc[i][j][1] * 0.125f;
            float v10 = acc[i][j][2] * 0.125f, v11 = acc[i][j][3] * 0.125f;
            bool k00, k01, k10, k11;
            if (mk == 1) {
                int2 q0 = *(const int2*)&m32[mbase + o0];
                int2 q1 = *(const int2*)&m32[mbase + o1];
                k00 = q0.x != 0; k01 = q0.y != 0; k10 = q1.x != 0; k11 = q1.y != 0;
            } else if (mk == 2) {
                float2 q0 = *(const float2*)&mf[mbase + o0];
                float2 q1 = *(const float2*)&mf[mbase + o1];
                k00 = q0.x != 0.0f; k01 = q0.y != 0.0f;
                k10 = q1.x != 0.0f; k11 = q1.y != 0.0f;
            } else {
                k00 = m8[mbase + o0] != 0;     k01 = m8[mbase + o0 + 1] != 0;
                k10 = m8[mbase + o1] != 0;     k11 = m8[mbase + o1 + 1] != 0;
            }
            v00 = k00 ? v00 : -1e30f;  v01 = k01 ? v01 : -1e30f;
            v10 = k10 ? v10 : -1e30f;  v11 = k11 ? v11 : -1e30f;
            float2 e0, e1;
            e0.x = expf(fminf(v00 + a0.x, 80.0f));
            e0.y = expf(fminf(v01 + a0.y, 80.0f));
            e1.x = expf(fminf(v10 + a1.x, 80.0f));
            e1.y = expf(fminf(v11 + a1.y, 80.0f));
            *(float2*)&C[o0] = e0;
            *(float2*)&C[o1] = e1;
            s0 += e0.x + e0.y;
            s1 += e1.x + e1.y;
        }
        s0 += __shfl_xor_sync(0xffffffffu, s0, 1);
        s0 += __shfl_xor_sync(0xffffffffu, s0, 2);
        s1 += __shfl_xor_sync(0xffffffffu, s1, 1);
        s1 += __shfl_xor_sync(0xffffffffu, s1, 2);
        if (tig == 0) {
            atomicAdd(&g_rsum[(size_t)zp * L_ + row], s0);
            atomicAdd(&g_rsum[(size_t)zp * L_ + row + 8], s1);
        }
    }
}

// ===========================================================================
// HMMA attnv, split-K: blockIdx.x owns k-range [x*512, (x+1)*512).
// Normalizes + writes back its weights slice, accumulates partial attn
// into g_part[x]. Grid (4, 16, 32) = 2048 blocks.
// ===========================================================================
__global__ __launch_bounds__(256, 3)
void attnv_mma(float* __restrict__ Wt,
               const float* __restrict__ gv,
               float* __restrict__ gpart)
{
    const int z = blockIdx.z;
    const int kch = blockIdx.x;
    const int b = z >> 4, h = z & 15;
    float* A  = Wt + (size_t)z * L_ * L_;                       // lda = L_
    const float* V = gv + ((size_t)b * L_ * H_ + h) * DK_;      // ldb = D_
    float* C = gpart + (size_t)kch * ML_ * D_
                     + (size_t)b * L_ * D_ + h * DK_;           // ldc = D_

    __shared__ __nv_bfloat16 sAh[128][PADK], sAl[128][PADK];
    __shared__ __nv_bfloat16 sVh[64][PADK],  sVl[64][PADK];
    __shared__ float inv_s[128];

    const int tid  = threadIdx.x;
    const int wid  = tid >> 5, lane = tid & 31;
    const int wm   = wid & 3, wn = wid >> 2;          // 4 x 2 warp grid
    const int m0   = blockIdx.y * 128;

    const uint32_t bAh = smem_u32(sAh), bAl = smem_u32(sAl);
    const uint32_t bVh = smem_u32(sVh), bVl = smem_u32(sVl);

    const uint32_t aoff = (uint32_t)((wm * 32 + (lane & 15)) * PADK + ((lane >> 4) << 3)) * 2;
    const uint32_t boff = (uint32_t)((wn * 32 + (lane & 7) + ((lane >> 4) << 3)) * PADK
                                     + (((lane >> 3) & 1) << 3)) * 2;

    const int lrow = tid >> 3;
    const int lk   = (tid & 7) * 4;
    const int vkr  = tid >> 4;
    const int vnc  = (tid & 15) * 4;

    if (tid < 128) inv_s[tid] = 1.0f / g_rsum[(size_t)z * L_ + m0 + tid];
    __syncthreads();

    float acc[2][4][4] = {};

    const int kc0 = kch * KCH;
    for (int kc = kc0; kc < kc0 + KCH; kc += 32) {
        __syncthreads();
        #pragma unroll
        for (int it = 0; it < 4; it++) {
            int r = it * 32 + lrow;
            size_t ao = (size_t)(m0 + r) * L_ + kc + lk;
            float4 v = *(const float4*)&A[ao];
            float iv = inv_s[r];
            v.x *= iv; v.y *= iv; v.z *= iv; v.w *= iv;
            *(float4*)&A[ao] = v;
            uint2 hi, lo;
            split4(v, hi, lo);
            *(uint2*)&sAh[r][lk] = hi;
            *(uint2*)&sAl[r][lk] = lo;
        }
        #pragma unroll
        for (int it = 0; it < 2; it++) {
            int kr = it * 16 + vkr;
            float4 v = *(const float4*)&V[(size_t)(kc + kr) * D_ + vnc];
            uint2 hi, lo;
            split4(v, hi, lo);
            __nv_bfloat162 h0 = *(__nv_bfloat162*)&hi.x;
            __nv_bfloat162 h1 = *(__nv_bfloat162*)&hi.y;
            __nv_bfloat162 l0 = *(__nv_bfloat162*)&lo.x;
            __nv_bfloat162 l1 = *(__nv_bfloat162*)&lo.y;
            int krl = kr - kc + kc - kc0;      // local k-row within chunk tile
            krl = kr;                           // (kr is 0..31 already)
            sVh[vnc + 0][kr] = __low2bfloat16(h0);
            sVh[vnc + 1][kr] = __high2bfloat16(h0);
            sVh[vnc + 2][kr] = __low2bfloat16(h1);
            sVh[vnc + 3][kr] = __high2bfloat16(h1);
            sVl[vnc + 0][kr] = __low2bfloat16(l0);
            sVl[vnc + 1][kr] = __high2bfloat16(l0);
            sVl[vnc + 2][kr] = __low2bfloat16(l1);
            sVl[vnc + 3][kr] = __high2bfloat16(l1);
        }
        __syncthreads();

        #pragma unroll
        for (int kb = 0; kb < 32; kb += 16) {
            const uint32_t kbo = (uint32_t)kb * 2;
            uint32_t ah[2][4], al[2][4];
            #pragma unroll
            for (int i = 0; i < 2; i++) {
                uint32_t step = (uint32_t)(i * 16 * PADK) * 2;
                ldsm4(ah[i], bAh + aoff + kbo + step);
                ldsm4(al[i], bAl + aoff + kbo + step);
            }
            uint32_t bh[8], bl[8];
            ldsm4(bh,     bVh + boff + kbo);
            ldsm4(bh + 4, bVh + boff + kbo + (uint32_t)(16 * PADK) * 2);
            ldsm4(bl,     bVl + boff + kbo);
            ldsm4(bl + 4, bVl + boff + kbo + (uint32_t)(16 * PADK) * 2);
            #pragma unroll
            for (int i = 0; i < 2; i++)
                #pragma unroll
                for (int j = 0; j < 4; j++) {
                    mma16816(acc[i][j], ah[i], &bh[j * 2]);
                    mma16816(acc[i][j], ah[i], &bl[j * 2]);
                    mma16816(acc[i][j], al[i], &bh[j * 2]);
                }
        }
    }

    const int g = lane >> 2, tig = lane & 3;
    #pragma unroll
    for (int i = 0; i < 2; i++) {
        int row = m0 + wm * 32 + i * 16 + g;
        #pragma unroll
        for (int j = 0; j < 4; j++) {
            int col = wn * 32 + j * 8 + tig * 2;
            float2 o0, o1;
            o0.x = acc[i][j][0];  o0.y = acc[i][j][1];
            o1.x = acc[i][j][2];  o1.y = acc[i][j][3];
            *(float2*)&C[(size_t)row * D_ + col]       = o0;
            *(float2*)&C[(size_t)(row + 8) * D_ + col] = o1;
        }
    }
}

// ---------------------------------------------------------------------------
// Reduce the KSPLIT partial attn buffers into g_attn (float4).
// ---------------------------------------------------------------------------
__global__ void reduce_part(const float* __restrict__ gpart,
                            float* __restrict__ gattn)
{
    size_t i = ((size_t)blockIdx.x * blockDim.x + threadIdx.x) * 4;
    const size_t stride = (size_t)ML_ * D_;
    float4 a = *(const float4*)&gpart[i];
    float4 b = *(const float4*)&gpart[stride + i];
    float4 c = *(const float4*)&gpart[2 * stride + i];
    float4 d = *(const float4*)&gpart[3 * stride + i];
    float4 o;
    o.x = (a.x + b.x) + (c.x + d.x);
    o.y = (a.y + b.y) + (c.y + d.y);
    o.z = (a.z + b.z) + (c.z + d.z);
    o.w = (a.w + b.w) + (c.w + d.w);
    *(float4*)&gattn[i] = o;
}

// ---------------------------------------------------------------------------
extern "C" void kernel_launch(void* const* d_in, const int* in_sizes, int n_in,
                              void* d_out, int out_size)
{
    const float* query = (const float*)d_in[0];
    const float* key   = (const float*)d_in[1];
    const float* value = (const float*)d_in[2];
    const void*  mask  = d_in[3];
    const float* awb = (const float*)d_in[4];
    const float* Wq = (const float*)d_in[5];
    const float* bq = (const float*)d_in[6];
    const float* Wk = (const float*)d_in[7];
    const float* bk = (const float*)d_in[8];
    const float* Wv = (const float*)d_in[9];
    const float* bv = (const float*)d_in[10];
    const float* Wo = (const float*)d_in[11];
    const float* bo = (const float*)d_in[12];

    float* out = (float*)d_out;                              // (B, L, D)
    float* weights = out + (size_t)B_ * L_ * D_;             // (B, H, L, L)

    float *gq, *gk, *gv, *gattn, *grsum, *gpart;
    cudaGetSymbolAddress((void**)&gq, g_q);
    cudaGetSymbolAddress((void**)&gk, g_k);
    cudaGetSymbolAddress((void**)&gv, g_v);
    cudaGetSymbolAddress((void**)&gattn, g_attn);
    cudaGetSymbolAddress((void**)&grsum, g_rsum);
    cudaGetSymbolAddress((void**)&gpart, g_part);

    dim3 blk(256);

    // 0) mask dtype sniff + zero row sums
    detect_mask_kernel<<<1, 32>>>((const unsigned int*)mask);
    cudaMemsetAsync(grsum, 0, (size_t)B_ * H_ * L_ * sizeof(float));

    // 1) QKV projections via HMMA split-bf16
    dim3 gproj(D_ / 128, ML_ / 128, 3);
    proj_mma<<<gproj, blk>>>(query, key, value, Wq, Wk, Wv,
                             gq, gk, gv, bq, bk, bv);

    // 2) RoPE on q and k
    rope_kernel<<<2 * (B_ * L_ * H_ * 32) / 256, 256>>>(gq, gk);

    // 3) Logits via HMMA (128x64 tiles) -> exp(logit) + row-sum atomics
    dim3 glog(L_ / 64, L_ / 128, B_ * H_);                   // 32 x 16 x 32
    logits_mma<<<glog, blk>>>(gq, gk, mask, awb, weights);

    // 4) Normalize weights (write back) + partial attn via split-K HMMA
    dim3 gat(KSPLIT, L_ / 128, B_ * H_);                     // 4 x 16 x 32
    attnv_mma<<<gat, blk>>>(weights, gv, gpart);

    // 4b) Reduce partials
    reduce_part<<<(ML_ * D_ / 4) / 256, 256>>>(gpart, gattn);

    // 5) Output projection via HMMA
    dim3 gout(D_ / 128, ML_ / 128, 1);
    proj_mma<<<gout, blk>>>(gattn, gattn, gattn, Wo, Wo, Wo,
                            out, out, out, bo, bo, bo);
}

// round 12
// speedup vs baseline: 2.8977x; 1.0407x over previous
#include <cuda_runtime.h>
#include <cuda_bf16.h>
#include <math.h>
#include <stdint.h>

// Problem constants
#define B_  2
#define L_  2048
#define H_  16
#define DK_ 64
#define D_  (H_ * DK_)        // 1024
#define ML_ (B_ * L_)         // 4096
#define KSPLIT 4
#define KCH (L_ / KSPLIT)     // 512

// Scratch (device globals: no allocation allowed)
__device__ float g_q[(size_t)ML_ * D_];
__device__ float g_k[(size_t)ML_ * D_];
__device__ float g_v[(size_t)ML_ * D_];
__device__ float g_attn[(size_t)ML_ * D_];
__device__ float g_part[KSPLIT][(size_t)ML_ * D_];
__device__ float g_rsum[(size_t)B_ * H_ * L_];
__device__ int   g_mask_kind;   // 0 = uint8, 1 = int32, 2 = float32

// ===========================================================================
// Helpers
// ===========================================================================
__device__ __forceinline__ uint32_t smem_u32(const void* p) {
    uint32_t a;
    asm("{ .reg .u64 t; cvta.to.shared.u64 t, %1; cvt.u32.u64 %0, t; }"
        : "=r"(a) : "l"(p));
    return a;
}

__device__ __forceinline__ void ldsm4(uint32_t* r, uint32_t addr) {
    asm volatile("ldmatrix.sync.aligned.m8n8.x4.shared.b16 {%0,%1,%2,%3}, [%4];"
                 : "=r"(r[0]), "=r"(r[1]), "=r"(r[2]), "=r"(r[3]) : "r"(addr));
}

__device__ __forceinline__ void mma16816(float* c, const uint32_t* a, const uint32_t* b) {
    asm volatile(
        "mma.sync.aligned.m16n8k16.row.col.f32.bf16.bf16.f32 "
        "{%0,%1,%2,%3}, {%4,%5,%6,%7}, {%8,%9}, {%0,%1,%2,%3};"
        : "+f"(c[0]), "+f"(c[1]), "+f"(c[2]), "+f"(c[3])
        : "r"(a[0]), "r"(a[1]), "r"(a[2]), "r"(a[3]), "r"(b[0]), "r"(b[1]));
}

// Split fp32 float4 -> packed hi / lo bf16x2 pairs (uint2 each)
__device__ __forceinline__ void split4(float4 v, uint2& hi, uint2& lo) {
    __nv_bfloat16 h0 = __float2bfloat16(v.x), h1 = __float2bfloat16(v.y),
                  h2 = __float2bfloat16(v.z), h3 = __float2bfloat16(v.w);
    __nv_bfloat16 l0 = __float2bfloat16(v.x - __bfloat162float(h0)),
                  l1 = __float2bfloat16(v.y - __bfloat162float(h1)),
                  l2 = __float2bfloat16(v.z - __bfloat162float(h2)),
                  l3 = __float2bfloat16(v.w - __bfloat162float(h3));
    __nv_bfloat162 hp0 = __halves2bfloat162(h0, h1);
    __nv_bfloat162 hp1 = __halves2bfloat162(h2, h3);
    __nv_bfloat162 lp0 = __halves2bfloat162(l0, l1);
    __nv_bfloat162 lp1 = __halves2bfloat162(l2, l3);
    hi = make_uint2(*(uint32_t*)&hp0, *(uint32_t*)&hp1);
    lo = make_uint2(*(uint32_t*)&lp0, *(uint32_t*)&lp1);
}

// ===========================================================================
// Mask dtype sniffer
// ===========================================================================
__global__ void detect_mask_kernel(const unsigned int* __restrict__ m)
{
    if (threadIdx.x == 0 && blockIdx.x == 0) {
        int all01 = 1, allf = 1;
        for (int i = 0; i < 1024; i++) {
            unsigned int w = m[i];
            if (w > 1u) all01 = 0;
            if (w != 0u && w != 0x3F800000u) allf = 0;
        }
        g_mask_kind = all01 ? 1 : (allf ? 2 : 0);
    }
}

// ===========================================================================
// HMMA split-bf16 projection GEMM: C = A @ W^T + bias  (unchanged, proven)
// ===========================================================================
#define PADK 40

__global__ __launch_bounds__(256)
void proj_mma(const float* __restrict__ A0, const float* __restrict__ A1,
              const float* __restrict__ A2,
              const float* __restrict__ W0, const float* __restrict__ W1,
              const float* __restrict__ W2,
              float* __restrict__ C0, float* __restrict__ C1, float* __restrict__ C2,
              const float* __restrict__ bi0, const float* __restrict__ bi1,
              const float* __restrict__ bi2)
{
    const int z = blockIdx.z;
    const float* A    = (z == 0) ? A0 : (z == 1) ? A1 : A2;
    const float* W    = (z == 0) ? W0 : (z == 1) ? W1 : W2;
    float* C          = (z == 0) ? C0 : (z == 1) ? C1 : C2;
    const float* bias = (z == 0) ? bi0 : (z == 1) ? bi1 : bi2;

    __shared__ __nv_bfloat16 sAh[128][PADK], sAl[128][PADK];
    __shared__ __nv_bfloat16 sBh[128][PADK], sBl[128][PADK];

    const int tid  = threadIdx.x;
    const int wid  = tid >> 5, lane = tid & 31;
    const int wm   = wid & 1, wn = wid >> 1;          // 2 x 4 warp grid
    const int m0   = blockIdx.y * 128, n0 = blockIdx.x * 128;

    const uint32_t bAh = smem_u32(sAh), bAl = smem_u32(sAl);
    const uint32_t bBh = smem_u32(sBh), bBl = smem_u32(sBl);

    const uint32_t aoff = (uint32_t)((wm * 64 + (lane & 15)) * PADK + ((lane >> 4) << 3)) * 2;
    const uint32_t boff = (uint32_t)((wn * 32 + (lane & 7) + ((lane >> 4) << 3)) * PADK
                                     + (((lane >> 3) & 1) << 3)) * 2;

    const int lrow = tid >> 3;
    const int lk   = (tid & 7) * 4;

    const float* Ag = A + (size_t)m0 * D_;
    const float* Wg = W + (size_t)n0 * D_;

    float acc[4][4][4] = {};

    for (int kc = 0; kc < D_; kc += 32) {
        __syncthreads();
        #pragma unroll
        for (int it = 0; it < 4; it++) {
            int r = it * 32 + lrow;
            uint2 hi, lo;
            split4(*(const float4*)&Ag[(size_t)r * D_ + kc + lk], hi, lo);
            *(uint2*)&sAh[r][lk] = hi;
            *(uint2*)&sAl[r][lk] = lo;
            split4(*(const float4*)&Wg[(size_t)r * D_ + kc + lk], hi, lo);
            *(uint2*)&sBh[r][lk] = hi;
            *(uint2*)&sBl[r][lk] = lo;
        }
        __syncthreads();

        #pragma unroll
        for (int kb = 0; kb < 32; kb += 16) {
            const uint32_t kbo = (uint32_t)kb * 2;
            uint32_t ah[4][4], al[4][4];
            #pragma unroll
            for (int i = 0; i < 4; i++) {
                uint32_t step = (uint32_t)(i * 16 * PADK) * 2;
                ldsm4(ah[i], bAh + aoff + kbo + step);
                ldsm4(al[i], bAl + aoff + kbo + step);
            }
            uint32_t bh[8], bl[8];
            ldsm4(bh,     bBh + boff + kbo);
            ldsm4(bh + 4, bBh + boff + kbo + (uint32_t)(16 * PADK) * 2);
            ldsm4(bl,     bBl + boff + kbo);
            ldsm4(bl + 4, bBl + boff + kbo + (uint32_t)(16 * PADK) * 2);
            #pragma unroll
            for (int i = 0; i < 4; i++)
                #pragma unroll
                for (int j = 0; j < 4; j++) {
                    mma16816(acc[i][j], ah[i], &bh[j * 2]);
                    mma16816(acc[i][j], ah[i], &bl[j * 2]);
                    mma16816(acc[i][j], al[i], &bh[j * 2]);
                }
        }
    }

    const int g = lane >> 2, tig = lane & 3;
    #pragma unroll
    for (int i = 0; i < 4; i++) {
        int row = m0 + wm * 64 + i * 16 + g;
        #pragma unroll
        for (int j = 0; j < 4; j++) {
            int col = n0 + wn * 32 + j * 8 + tig * 2;
            float2 b2 = *(const float2*)&bias[col];
            float2 o0, o1;
            o0.x = acc[i][j][0] + b2.x;  o0.y = acc[i][j][1] + b2.y;
            o1.x = acc[i][j][2] + b2.x;  o1.y = acc[i][j][3] + b2.y;
            *(float2*)&C[(size_t)row * D_ + col]       = o0;
            *(float2*)&C[(size_t)(row + 8) * D_ + col] = o1;
        }
    }
}

// ---------------------------------------------------------------------------
// RoPE in-place on q and k, one launch.
// ---------------------------------------------------------------------------
__global__ void rope_kernel(float* __restrict__ q, float* __restrict__ k)
{
    int idx = blockIdx.x * blockDim.x + threadIdx.x;
    float* x = (idx >> 21) ? k : q;
    idx &= (1 << 21) - 1;
    int j = idx & 31;
    int h = (idx >> 5) & 15;
    int l = (idx >> 9) & 2047;
    int b = idx >> 20;
    size_t base = (((size_t)(b * L_ + l)) * H_ + h) * DK_;
    float inv = 1.0f / powf(10000.0f, (2.0f * j) / 64.0f);
    float freq = (float)l * inv;
    float c = cosf(freq), s = sinf(freq);
    float a  = x[base + j];
    float bb = x[base + j + 32];
    x[base + j]      = a * c - bb * s;
    x[base + j + 32] = bb * c + a * s;
}

// ===========================================================================
// HMMA logits, 128x64 tile, smem-staged epilogue (all gmem I/O 16B):
// Q.K^T -> stage raw tile in smem -> stream: scale, mask, +awb, exp,
// float4 store, rowsum via 16-lane shuffle + 1 atomic per row.
// Smem: MMA operand buffers (30720 B) overlaid with fp32 stage (34816 B).
// ===========================================================================
#define STAGE_BYTES (128 * 68 * 4)   // 34816

__global__ __launch_bounds__(256, 3)
void logits_mma(const float* __restrict__ gq,
                const float* __restrict__ gk,
                const void* __restrict__ mask,
                const float* __restrict__ awb,
                float* __restrict__ Wt)
{
    const int z = blockIdx.z;
    const int h = z >> 1, b = z & 1;
    const int zp = b * H_ + h;
    const float* A  = gq + ((size_t)b * L_ * H_ + h) * DK_;   // lda = D_
    const float* Bm = gk + ((size_t)b * L_ * H_ + h) * DK_;   // ldb = D_
    const float* arow = awb + (size_t)h * L_ * L_;
    float* C = Wt + (size_t)zp * L_ * L_;
    const size_t mbase = (size_t)b * L_ * L_;

    const int mk = g_mask_kind;
    const unsigned char* m8  = (const unsigned char*)mask;
    const int*           m32 = (const int*)mask;
    const float*         mf  = (const float*)mask;

    __shared__ __align__(16) char smem_raw[STAGE_BYTES];
    __nv_bfloat16 (*sAh)[PADK] = (__nv_bfloat16(*)[PADK])(smem_raw);          // 10240
    __nv_bfloat16 (*sAl)[PADK] = (__nv_bfloat16(*)[PADK])(smem_raw + 10240);  // 10240
    __nv_bfloat16 (*sBh)[PADK] = (__nv_bfloat16(*)[PADK])(smem_raw + 20480);  // 5120
    __nv_bfloat16 (*sBl)[PADK] = (__nv_bfloat16(*)[PADK])(smem_raw + 25600);  // 5120
    float (*sC)[68] = (float(*)[68])smem_raw;

    const int tid  = threadIdx.x;
    const int wid  = tid >> 5, lane = tid & 31;
    const int wm   = wid & 1, wn = wid >> 1;           // 2 x 4; 64 rows x 16 cols
    const int m0   = blockIdx.y * 128, n0 = blockIdx.x * 64;

    const uint32_t bAh = smem_u32(sAh), bAl = smem_u32(sAl);
    const uint32_t bBh = smem_u32(sBh), bBl = smem_u32(sBl);

    const uint32_t aoff = (uint32_t)((wm * 64 + (lane & 15)) * PADK + ((lane >> 4) << 3)) * 2;
    const uint32_t boff = (uint32_t)((wn * 16 + (lane & 7) + ((lane >> 4) << 3)) * PADK
                                     + (((lane >> 3) & 1) << 3)) * 2;

    const int lrow = tid >> 3;
    const int lk   = (tid & 7) * 4;

    float acc[4][2][4] = {};

    for (int kc = 0; kc < DK_; kc += 32) {
        __syncthreads();
        #pragma unroll
        for (int it = 0; it < 4; it++) {
            int r = it * 32 + lrow;
            uint2 hi, lo;
            split4(*(const float4*)&A[(size_t)(m0 + r) * D_ + kc + lk], hi, lo);
            *(uint2*)&sAh[r][lk] = hi;
            *(uint2*)&sAl[r][lk] = lo;
        }
        #pragma unroll
        for (int it = 0; it < 2; it++) {
            int r = it * 32 + lrow;
            uint2 hi, lo;
            split4(*(const float4*)&Bm[(size_t)(n0 + r) * D_ + kc + lk], hi, lo);
            *(uint2*)&sBh[r][lk] = hi;
            *(uint2*)&sBl[r][lk] = lo;
        }
        __syncthreads();

        #pragma unroll
        for (int kb = 0; kb < 32; kb += 16) {
            const uint32_t kbo = (uint32_t)kb * 2;
            uint32_t ah[4][4], al[4][4];
            #pragma unroll
            for (int i = 0; i < 4; i++) {
                uint32_t step = (uint32_t)(i * 16 * PADK) * 2;
                ldsm4(ah[i], bAh + aoff + kbo + step);
                ldsm4(al[i], bAl + aoff + kbo + step);
            }
            uint32_t bh[4], bl[4];
            ldsm4(bh, bBh + boff + kbo);
            ldsm4(bl, bBl + boff + kbo);
            #pragma unroll
            for (int i = 0; i < 4; i++)
                #pragma unroll
                for (int j = 0; j < 2; j++) {
                    mma16816(acc[i][j], ah[i], &bh[j * 2]);
                    mma16816(acc[i][j], ah[i], &bl[j * 2]);
                    mma16816(acc[i][j], al[i], &bh[j * 2]);
                }
        }
    }

    // Stage raw logits tile into smem (overlaying dead MMA buffers).
    __syncthreads();
    const int g = lane >> 2, tig = lane & 3;
    #pragma unroll
    for (int i = 0; i < 4; i++) {
        int row = wm * 64 + i * 16 + g;
        #pragma unroll
        for (int j = 0; j < 2; j++) {
            int col = wn * 16 + j * 8 + tig * 2;
            *(float2*)&sC[row][col]     = make_float2(acc[i][j][0], acc[i][j][1]);
            *(float2*)&sC[row + 8][col] = make_float2(acc[i][j][2], acc[i][j][3]);
        }
    }
    __syncthreads();

    // Stream out: 16 rows per pass, 8 passes; all gmem ops are 16B.
    const int srow = tid >> 4, scol = (tid & 15) * 4;
    #pragma unroll
    for (int p = 0; p < 8; p++) {
        int row = p * 16 + srow;
        int grow = m0 + row;
        size_t o = (size_t)grow * L_ + n0 + scol;
        float4 v = *(const float4*)&sC[row][scol];
        v.x *= 0.125f; v.y *= 0.125f; v.z *= 0.125f; v.w *= 0.125f;
        bool k0, k1, k2, k3;
        if (mk == 1) {
            int4 mm = *(const int4*)&m32[mbase + o];
            k0 = mm.x != 0; k1 = mm.y != 0; k2 = mm.z != 0; k3 = mm.w != 0;
        } else if (mk == 2) {
            float4 mm = *(const float4*)&mf[mbase + o];
            k0 = mm.x != 0.0f; k1 = mm.y != 0.0f; k2 = mm.z != 0.0f; k3 = mm.w != 0.0f;
        } else {
            uchar4 mm = *(const uchar4*)&m8[mbase + o];
            k0 = mm.x != 0; k1 = mm.y != 0; k2 = mm.z != 0; k3 = mm.w != 0;
        }
        float4 a = *(const float4*)&arow[o];
        float4 e;
        e.x = expf(fminf((k0 ? v.x : -1e30f) + a.x, 80.0f));
        e.y = expf(fminf((k1 ? v.y : -1e30f) + a.y, 80.0f));
        e.z = expf(fminf((k2 ? v.z : -1e30f) + a.z, 80.0f));
        e.w = expf(fminf((k3 ? v.w : -1e30f) + a.w, 80.0f));
        *(float4*)&C[o] = e;
        float s = (e.x + e.y) + (e.z + e.w);
        s += __shfl_xor_sync(0xffffffffu, s, 1);
        s += __shfl_xor_sync(0xffffffffu, s, 2);
        s += __shfl_xor_sync(0xffffffffu, s, 4);
        s += __shfl_xor_sync(0xffffffffu, s, 8);
        if ((tid & 15) == 0)
            atomicAdd(&g_rsum[(size_t)zp * L_ + grow], s);
    }
}

// ===========================================================================
// HMMA attnv, split-K: blockIdx.x owns k-range [x*512, (x+1)*512).
// Normalizes + writes back its weights slice, accumulates partial attn
// into g_part[x]. Grid (4, 16, 32) = 2048 blocks.
// ===========================================================================
__global__ __launch_bounds__(256, 3)
void attnv_mma(float* __restrict__ Wt,
               const float* __restrict__ gv,
               float* __restrict__ gpart)
{
    const int z = blockIdx.z;
    const int kch = blockIdx.x;
    const int b = z >> 4, h = z & 15;
    float* A  = Wt + (size_t)z * L_ * L_;                       // lda = L_
    const float* V = gv + ((size_t)b * L_ * H_ + h) * DK_;      // ldb = D_
    float* C = gpart + (size_t)kch * ML_ * D_
                     + (size_t)b * L_ * D_ + h * DK_;           // ldc = D_

    __shared__ __nv_bfloat16 sAh[128][PADK], sAl[128][PADK];
    __shared__ __nv_bfloat16 sVh[64][PADK],  sVl[64][PADK];
    __shared__ float inv_s[128];

    const int tid  = threadIdx.x;
    const int wid  = tid >> 5, lane = tid & 31;
    const int wm   = wid & 3, wn = wid >> 2;          // 4 x 2 warp grid
    const int m0   = blockIdx.y * 128;

    const uint32_t bAh = smem_u32(sAh), bAl = smem_u32(sAl);
    const uint32_t bVh = smem_u32(sVh), bVl = smem_u32(sVl);

    const uint32_t aoff = (uint32_t)((wm * 32 + (lane & 15)) * PADK + ((lane >> 4) << 3)) * 2;
    const uint32_t boff = (uint32_t)((wn * 32 + (lane & 7) + ((lane >> 4) << 3)) * PADK
                                     + (((lane >> 3) & 1) << 3)) * 2;

    const int lrow = tid >> 3;
    const int lk   = (tid & 7) * 4;
    const int vkr  = tid >> 4;
    const int vnc  = (tid & 15) * 4;

    if (tid < 128) inv_s[tid] = 1.0f / g_rsum[(size_t)z * L_ + m0 + tid];
    __syncthreads();

    float acc[2][4][4] = {};

    const int kc0 = kch * KCH;
    for (int kc = kc0; kc < kc0 + KCH; kc += 32) {
        __syncthreads();
        #pragma unroll
        for (int it = 0; it < 4; it++) {
            int r = it * 32 + lrow;
            size_t ao = (size_t)(m0 + r) * L_ + kc + lk;
            float4 v = *(const float4*)&A[ao];
            float iv = inv_s[r];
            v.x *= iv; v.y *= iv; v.z *= iv; v.w *= iv;
            *(float4*)&A[ao] = v;
            uint2 hi, lo;
            split4(v, hi, lo);
            *(uint2*)&sAh[r][lk] = hi;
            *(uint2*)&sAl[r][lk] = lo;
        }
        #pragma unroll
        for (int it = 0; it < 2; it++) {
            int kr = it * 16 + vkr;
            float4 v = *(const float4*)&V[(size_t)(kc + kr) * D_ + vnc];
            uint2 hi, lo;
            split4(v, hi, lo);
            __nv_bfloat162 h0 = *(__nv_bfloat162*)&hi.x;
            __nv_bfloat162 h1 = *(__nv_bfloat162*)&hi.y;
            __nv_bfloat162 l0 = *(__nv_bfloat162*)&lo.x;
            __nv_bfloat162 l1 = *(__nv_bfloat162*)&lo.y;
            sVh[vnc + 0][kr] = __low2bfloat16(h0);
            sVh[vnc + 1][kr] = __high2bfloat16(h0);
            sVh[vnc + 2][kr] = __low2bfloat16(h1);
            sVh[vnc + 3][kr] = __high2bfloat16(h1);
            sVl[vnc + 0][kr] = __low2bfloat16(l0);
            sVl[vnc + 1][kr] = __high2bfloat16(l0);
            sVl[vnc + 2][kr] = __low2bfloat16(l1);
            sVl[vnc + 3][kr] = __high2bfloat16(l1);
        }
        __syncthreads();

        #pragma unroll
        for (int kb = 0; kb < 32; kb += 16) {
            const uint32_t kbo = (uint32_t)kb * 2;
            uint32_t ah[2][4], al[2][4];
            #pragma unroll
            for (int i = 0; i < 2; i++) {
                uint32_t step = (uint32_t)(i * 16 * PADK) * 2;
                ldsm4(ah[i], bAh + aoff + kbo + step);
                ldsm4(al[i], bAl + aoff + kbo + step);
            }
            uint32_t bh[8], bl[8];
            ldsm4(bh,     bVh + boff + kbo);
            ldsm4(bh + 4, bVh + boff + kbo + (uint32_t)(16 * PADK) * 2);
            ldsm4(bl,     bVl + boff + kbo);
            ldsm4(bl + 4, bVl + boff + kbo + (uint32_t)(16 * PADK) * 2);
            #pragma unroll
            for (int i = 0; i < 2; i++)
                #pragma unroll
                for (int j = 0; j < 4; j++) {
                    mma16816(acc[i][j], ah[i], &bh[j * 2]);
                    mma16816(acc[i][j], ah[i], &bl[j * 2]);
                    mma16816(acc[i][j], al[i], &bh[j * 2]);
                }
        }
    }

    const int g = lane >> 2, tig = lane & 3;
    #pragma unroll
    for (int i = 0; i < 2; i++) {
        int row = m0 + wm * 32 + i * 16 + g;
        #pragma unroll
        for (int j = 0; j < 4; j++) {
            int col = wn * 32 + j * 8 + tig * 2;
            float2 o0, o1;
            o0.x = acc[i][j][0];  o0.y = acc[i][j][1];
            o1.x = acc[i][j][2];  o1.y = acc[i][j][3];
            *(float2*)&C[(size_t)row * D_ + col]       = o0;
            *(float2*)&C[(size_t)(row + 8) * D_ + col] = o1;
        }
    }
}

// ---------------------------------------------------------------------------
// Reduce the KSPLIT partial attn buffers into g_attn (float4).
// ---------------------------------------------------------------------------
__global__ void reduce_part(const float* __restrict__ gpart,
                            float* __restrict__ gattn)
{
    size_t i = ((size_t)blockIdx.x * blockDim.x + threadIdx.x) * 4;
    const size_t stride = (size_t)ML_ * D_;
    float4 a = *(const float4*)&gpart[i];
    float4 b = *(const float4*)&gpart[stride + i];
    float4 c = *(const float4*)&gpart[2 * stride + i];
    float4 d = *(const float4*)&gpart[3 * stride + i];
    float4 o;
    o.x = (a.x + b.x) + (c.x + d.x);
    o.y = (a.y + b.y) + (c.y + d.y);
    o.z = (a.z + b.z) + (c.z + d.z);
    o.w = (a.w + b.w) + (c.w + d.w);
    *(float4*)&gattn[i] = o;
}

// ---------------------------------------------------------------------------
extern "C" void kernel_launch(void* const* d_in, const int* in_sizes, int n_in,
                              void* d_out, int out_size)
{
    const float* query = (const float*)d_in[0];
    const float* key   = (const float*)d_in[1];
    const float* value = (const float*)d_in[2];
    const void*  mask  = d_in[3];
    const float* awb = (const float*)d_in[4];
    const float* Wq = (const float*)d_in[5];
    const float* bq = (const float*)d_in[6];
    const float* Wk = (const float*)d_in[7];
    const float* bk = (const float*)d_in[8];
    const float* Wv = (const float*)d_in[9];
    const float* bv = (const float*)d_in[10];
    const float* Wo = (const float*)d_in[11];
    const float* bo = (const float*)d_in[12];

    float* out = (float*)d_out;                              // (B, L, D)
    float* weights = out + (size_t)B_ * L_ * D_;             // (B, H, L, L)

    float *gq, *gk, *gv, *gattn, *grsum, *gpart;
    cudaGetSymbolAddress((void**)&gq, g_q);
    cudaGetSymbolAddress((void**)&gk, g_k);
    cudaGetSymbolAddress((void**)&gv, g_v);
    cudaGetSymbolAddress((void**)&gattn, g_attn);
    cudaGetSymbolAddress((void**)&grsum, g_rsum);
    cudaGetSymbolAddress((void**)&gpart, g_part);

    dim3 blk(256);

    // 0) mask dtype sniff + zero row sums
    detect_mask_kernel<<<1, 32>>>((const unsigned int*)mask);
    cudaMemsetAsync(grsum, 0, (size_t)B_ * H_ * L_ * sizeof(float));

    // 1) QKV projections via HMMA split-bf16
    dim3 gproj(D_ / 128, ML_ / 128, 3);
    proj_mma<<<gproj, blk>>>(query, key, value, Wq, Wk, Wv,
                             gq, gk, gv, bq, bk, bv);

    // 2) RoPE on q and k
    rope_kernel<<<2 * (B_ * L_ * H_ * 32) / 256, 256>>>(gq, gk);

    // 3) Logits via HMMA (128x64 tiles, staged epilogue)
    dim3 glog(L_ / 64, L_ / 128, B_ * H_);                   // 32 x 16 x 32
    logits_mma<<<glog, blk>>>(gq, gk, mask, awb, weights);

    // 4) Normalize weights (write back) + partial attn via split-K HMMA
    dim3 gat(KSPLIT, L_ / 128, B_ * H_);                     // 4 x 16 x 32
    attnv_mma<<<gat, blk>>>(weights, gv, gpart);

    // 4b) Reduce partials
    reduce_part<<<(ML_ * D_ / 4) / 256, 256>>>(gpart, gattn);

    // 5) Output projection via HMMA
    dim3 gout(D_ / 128, ML_ / 128, 1);
    proj_mma<<<gout, blk>>>(gattn, gattn, gattn, Wo, Wo, Wo,
                            out, out, out, bo, bo, bo);
}

// round 13
// speedup vs baseline: 2.9042x; 1.0022x over previous
#include <cuda_runtime.h>
#include <cuda_bf16.h>
#include <math.h>
#include <stdint.h>

// Problem constants
#define B_  2
#define L_  2048
#define H_  16
#define DK_ 64
#define D_  (H_ * DK_)        // 1024
#define ML_ (B_ * L_)         // 4096
#define KSPLIT 4
#define KCH (L_ / KSPLIT)     // 512

// Scratch (device globals: no allocation allowed)
__device__ float g_q[(size_t)ML_ * D_];
__device__ float g_k[(size_t)ML_ * D_];
__device__ float g_v[(size_t)ML_ * D_];
__device__ float g_attn[(size_t)ML_ * D_];
__device__ float g_rsum[(size_t)B_ * H_ * L_];
__device__ int   g_mask_kind;   // 0 = uint8, 1 = int32, 2 = float32

// ===========================================================================
// Helpers
// ===========================================================================
__device__ __forceinline__ uint32_t smem_u32(const void* p) {
    uint32_t a;
    asm("{ .reg .u64 t; cvta.to.shared.u64 t, %1; cvt.u32.u64 %0, t; }"
        : "=r"(a) : "l"(p));
    return a;
}

__device__ __forceinline__ void ldsm4(uint32_t* r, uint32_t addr) {
    asm volatile("ldmatrix.sync.aligned.m8n8.x4.shared.b16 {%0,%1,%2,%3}, [%4];"
                 : "=r"(r[0]), "=r"(r[1]), "=r"(r[2]), "=r"(r[3]) : "r"(addr));
}

__device__ __forceinline__ void mma16816(float* c, const uint32_t* a, const uint32_t* b) {
    asm volatile(
        "mma.sync.aligned.m16n8k16.row.col.f32.bf16.bf16.f32 "
        "{%0,%1,%2,%3}, {%4,%5,%6,%7}, {%8,%9}, {%0,%1,%2,%3};"
        : "+f"(c[0]), "+f"(c[1]), "+f"(c[2]), "+f"(c[3])
        : "r"(a[0]), "r"(a[1]), "r"(a[2]), "r"(a[3]), "r"(b[0]), "r"(b[1]));
}

// Split fp32 float4 -> packed hi / lo bf16x2 pairs (uint2 each)
__device__ __forceinline__ void split4(float4 v, uint2& hi, uint2& lo) {
    __nv_bfloat16 h0 = __float2bfloat16(v.x), h1 = __float2bfloat16(v.y),
                  h2 = __float2bfloat16(v.z), h3 = __float2bfloat16(v.w);
    __nv_bfloat16 l0 = __float2bfloat16(v.x - __bfloat162float(h0)),
                  l1 = __float2bfloat16(v.y - __bfloat162float(h1)),
                  l2 = __float2bfloat16(v.z - __bfloat162float(h2)),
                  l3 = __float2bfloat16(v.w - __bfloat162float(h3));
    __nv_bfloat162 hp0 = __halves2bfloat162(h0, h1);
    __nv_bfloat162 hp1 = __halves2bfloat162(h2, h3);
    __nv_bfloat162 lp0 = __halves2bfloat162(l0, l1);
    __nv_bfloat162 lp1 = __halves2bfloat162(l2, l3);
    hi = make_uint2(*(uint32_t*)&hp0, *(uint32_t*)&hp1);
    lo = make_uint2(*(uint32_t*)&lp0, *(uint32_t*)&lp1);
}

// ===========================================================================
// Mask dtype sniffer
// ===========================================================================
__global__ void detect_mask_kernel(const unsigned int* __restrict__ m)
{
    if (threadIdx.x == 0 && blockIdx.x == 0) {
        int all01 = 1, allf = 1;
        for (int i = 0; i < 1024; i++) {
            unsigned int w = m[i];
            if (w > 1u) all01 = 0;
            if (w != 0u && w != 0x3F800000u) allf = 0;
        }
        g_mask_kind = all01 ? 1 : (allf ? 2 : 0);
    }
}

// ===========================================================================
// HMMA split-bf16 projection GEMM: C = A @ W^T + bias  (unchanged, proven)
// ===========================================================================
#define PADK 40

__global__ __launch_bounds__(256)
void proj_mma(const float* __restrict__ A0, const float* __restrict__ A1,
              const float* __restrict__ A2,
              const float* __restrict__ W0, const float* __restrict__ W1,
              const float* __restrict__ W2,
              float* __restrict__ C0, float* __restrict__ C1, float* __restrict__ C2,
              const float* __restrict__ bi0, const float* __restrict__ bi1,
              const float* __restrict__ bi2)
{
    const int z = blockIdx.z;
    const float* A    = (z == 0) ? A0 : (z == 1) ? A1 : A2;
    const float* W    = (z == 0) ? W0 : (z == 1) ? W1 : W2;
    float* C          = (z == 0) ? C0 : (z == 1) ? C1 : C2;
    const float* bias = (z == 0) ? bi0 : (z == 1) ? bi1 : bi2;

    __shared__ __nv_bfloat16 sAh[128][PADK], sAl[128][PADK];
    __shared__ __nv_bfloat16 sBh[128][PADK], sBl[128][PADK];

    const int tid  = threadIdx.x;
    const int wid  = tid >> 5, lane = tid & 31;
    const int wm   = wid & 1, wn = wid >> 1;          // 2 x 4 warp grid
    const int m0   = blockIdx.y * 128, n0 = blockIdx.x * 128;

    const uint32_t bAh = smem_u32(sAh), bAl = smem_u32(sAl);
    const uint32_t bBh = smem_u32(sBh), bBl = smem_u32(sBl);

    const uint32_t aoff = (uint32_t)((wm * 64 + (lane & 15)) * PADK + ((lane >> 4) << 3)) * 2;
    const uint32_t boff = (uint32_t)((wn * 32 + (lane & 7) + ((lane >> 4) << 3)) * PADK
                                     + (((lane >> 3) & 1) << 3)) * 2;

    const int lrow = tid >> 3;
    const int lk   = (tid & 7) * 4;

    const float* Ag = A + (size_t)m0 * D_;
    const float* Wg = W + (size_t)n0 * D_;

    float acc[4][4][4] = {};

    for (int kc = 0; kc < D_; kc += 32) {
        __syncthreads();
        #pragma unroll
        for (int it = 0; it < 4; it++) {
            int r = it * 32 + lrow;
            uint2 hi, lo;
            split4(*(const float4*)&Ag[(size_t)r * D_ + kc + lk], hi, lo);
            *(uint2*)&sAh[r][lk] = hi;
            *(uint2*)&sAl[r][lk] = lo;
            split4(*(const float4*)&Wg[(size_t)r * D_ + kc + lk], hi, lo);
            *(uint2*)&sBh[r][lk] = hi;
            *(uint2*)&sBl[r][lk] = lo;
        }
        __syncthreads();

        #pragma unroll
        for (int kb = 0; kb < 32; kb += 16) {
            const uint32_t kbo = (uint32_t)kb * 2;
            uint32_t ah[4][4], al[4][4];
            #pragma unroll
            for (int i = 0; i < 4; i++) {
                uint32_t step = (uint32_t)(i * 16 * PADK) * 2;
                ldsm4(ah[i], bAh + aoff + kbo + step);
                ldsm4(al[i], bAl + aoff + kbo + step);
            }
            uint32_t bh[8], bl[8];
            ldsm4(bh,     bBh + boff + kbo);
            ldsm4(bh + 4, bBh + boff + kbo + (uint32_t)(16 * PADK) * 2);
            ldsm4(bl,     bBl + boff + kbo);
            ldsm4(bl + 4, bBl + boff + kbo + (uint32_t)(16 * PADK) * 2);
            #pragma unroll
            for (int i = 0; i < 4; i++)
                #pragma unroll
                for (int j = 0; j < 4; j++) {
                    mma16816(acc[i][j], ah[i], &bh[j * 2]);
                    mma16816(acc[i][j], ah[i], &bl[j * 2]);
                    mma16816(acc[i][j], al[i], &bh[j * 2]);
                }
        }
    }

    const int g = lane >> 2, tig = lane & 3;
    #pragma unroll
    for (int i = 0; i < 4; i++) {
        int row = m0 + wm * 64 + i * 16 + g;
        #pragma unroll
        for (int j = 0; j < 4; j++) {
            int col = n0 + wn * 32 + j * 8 + tig * 2;
            float2 b2 = *(const float2*)&bias[col];
            float2 o0, o1;
            o0.x = acc[i][j][0] + b2.x;  o0.y = acc[i][j][1] + b2.y;
            o1.x = acc[i][j][2] + b2.x;  o1.y = acc[i][j][3] + b2.y;
            *(float2*)&C[(size_t)row * D_ + col]       = o0;
            *(float2*)&C[(size_t)(row + 8) * D_ + col] = o1;
        }
    }
}

// ---------------------------------------------------------------------------
// RoPE in-place on q and k, one launch.
// ---------------------------------------------------------------------------
__global__ void rope_kernel(float* __restrict__ q, float* __restrict__ k)
{
    int idx = blockIdx.x * blockDim.x + threadIdx.x;
    float* x = (idx >> 21) ? k : q;
    idx &= (1 << 21) - 1;
    int j = idx & 31;
    int h = (idx >> 5) & 15;
    int l = (idx >> 9) & 2047;
    int b = idx >> 20;
    size_t base = (((size_t)(b * L_ + l)) * H_ + h) * DK_;
    float inv = 1.0f / powf(10000.0f, (2.0f * j) / 64.0f);
    float freq = (float)l * inv;
    float c = cosf(freq), s = sinf(freq);
    float a  = x[base + j];
    float bb = x[base + j + 32];
    x[base + j]      = a * c - bb * s;
    x[base + j + 32] = bb * c + a * s;
}

// ===========================================================================
// HMMA logits, 128x64 tile, smem-staged epilogue (all gmem I/O 16B).
// ===========================================================================
#define STAGE_BYTES (128 * 68 * 4)   // 34816

__global__ __launch_bounds__(256, 3)
void logits_mma(const float* __restrict__ gq,
                const float* __restrict__ gk,
                const void* __restrict__ mask,
                const float* __restrict__ awb,
                float* __restrict__ Wt)
{
    const int z = blockIdx.z;
    const int h = z >> 1, b = z & 1;
    const int zp = b * H_ + h;
    const float* A  = gq + ((size_t)b * L_ * H_ + h) * DK_;   // lda = D_
    const float* Bm = gk + ((size_t)b * L_ * H_ + h) * DK_;   // ldb = D_
    const float* arow = awb + (size_t)h * L_ * L_;
    float* C = Wt + (size_t)zp * L_ * L_;
    const size_t mbase = (size_t)b * L_ * L_;

    const int mk = g_mask_kind;
    const unsigned char* m8  = (const unsigned char*)mask;
    const int*           m32 = (const int*)mask;
    const float*         mf  = (const float*)mask;

    __shared__ __align__(16) char smem_raw[STAGE_BYTES];
    __nv_bfloat16 (*sAh)[PADK] = (__nv_bfloat16(*)[PADK])(smem_raw);          // 10240
    __nv_bfloat16 (*sAl)[PADK] = (__nv_bfloat16(*)[PADK])(smem_raw + 10240);  // 10240
    __nv_bfloat16 (*sBh)[PADK] = (__nv_bfloat16(*)[PADK])(smem_raw + 20480);  // 5120
    __nv_bfloat16 (*sBl)[PADK] = (__nv_bfloat16(*)[PADK])(smem_raw + 25600);  // 5120
    float (*sC)[68] = (float(*)[68])smem_raw;

    const int tid  = threadIdx.x;
    const int wid  = tid >> 5, lane = tid & 31;
    const int wm   = wid & 1, wn = wid >> 1;           // 2 x 4; 64 rows x 16 cols
    const int m0   = blockIdx.y * 128, n0 = blockIdx.x * 64;

    const uint32_t bAh = smem_u32(sAh), bAl = smem_u32(sAl);
    const uint32_t bBh = smem_u32(sBh), bBl = smem_u32(sBl);

    const uint32_t aoff = (uint32_t)((wm * 64 + (lane & 15)) * PADK + ((lane >> 4) << 3)) * 2;
    const uint32_t boff = (uint32_t)((wn * 16 + (lane & 7) + ((lane >> 4) << 3)) * PADK
                                     + (((lane >> 3) & 1) << 3)) * 2;

    const int lrow = tid >> 3;
    const int lk   = (tid & 7) * 4;

    float acc[4][2][4] = {};

    for (int kc = 0; kc < DK_; kc += 32) {
        __syncthreads();
        #pragma unroll
        for (int it = 0; it < 4; it++) {
            int r = it * 32 + lrow;
            uint2 hi, lo;
            split4(*(const float4*)&A[(size_t)(m0 + r) * D_ + kc + lk], hi, lo);
            *(uint2*)&sAh[r][lk] = hi;
            *(uint2*)&sAl[r][lk] = lo;
        }
        #pragma unroll
        for (int it = 0; it < 2; it++) {
            int r = it * 32 + lrow;
            uint2 hi, lo;
            split4(*(const float4*)&Bm[(size_t)(n0 + r) * D_ + kc + lk], hi, lo);
            *(uint2*)&sBh[r][lk] = hi;
            *(uint2*)&sBl[r][lk] = lo;
        }
        __syncthreads();

        #pragma unroll
        for (int kb = 0; kb < 32; kb += 16) {
            const uint32_t kbo = (uint32_t)kb * 2;
            uint32_t ah[4][4], al[4][4];
            #pragma unroll
            for (int i = 0; i < 4; i++) {
                uint32_t step = (uint32_t)(i * 16 * PADK) * 2;
                ldsm4(ah[i], bAh + aoff + kbo + step);
                ldsm4(al[i], bAl + aoff + kbo + step);
            }
            uint32_t bh[4], bl[4];
            ldsm4(bh, bBh + boff + kbo);
            ldsm4(bl, bBl + boff + kbo);
            #pragma unroll
            for (int i = 0; i < 4; i++)
                #pragma unroll
                for (int j = 0; j < 2; j++) {
                    mma16816(acc[i][j], ah[i], &bh[j * 2]);
                    mma16816(acc[i][j], ah[i], &bl[j * 2]);
                    mma16816(acc[i][j], al[i], &bh[j * 2]);
                }
        }
    }

    // Stage raw logits tile into smem (overlaying dead MMA buffers).
    __syncthreads();
    const int g = lane >> 2, tig = lane & 3;
    #pragma unroll
    for (int i = 0; i < 4; i++) {
        int row = wm * 64 + i * 16 + g;
        #pragma unroll
        for (int j = 0; j < 2; j++) {
            int col = wn * 16 + j * 8 + tig * 2;
            *(float2*)&sC[row][col]     = make_float2(acc[i][j][0], acc[i][j][1]);
            *(float2*)&sC[row + 8][col] = make_float2(acc[i][j][2], acc[i][j][3]);
        }
    }
    __syncthreads();

    // Stream out: 16 rows per pass, 8 passes; all gmem ops are 16B.
    const int srow = tid >> 4, scol = (tid & 15) * 4;
    #pragma unroll
    for (int p = 0; p < 8; p++) {
        int row = p * 16 + srow;
        int grow = m0 + row;
        size_t o = (size_t)grow * L_ + n0 + scol;
        float4 v = *(const float4*)&sC[row][scol];
        v.x *= 0.125f; v.y *= 0.125f; v.z *= 0.125f; v.w *= 0.125f;
        bool k0, k1, k2, k3;
        if (mk == 1) {
            int4 mm = *(const int4*)&m32[mbase + o];
            k0 = mm.x != 0; k1 = mm.y != 0; k2 = mm.z != 0; k3 = mm.w != 0;
        } else if (mk == 2) {
            float4 mm = *(const float4*)&mf[mbase + o];
            k0 = mm.x != 0.0f; k1 = mm.y != 0.0f; k2 = mm.z != 0.0f; k3 = mm.w != 0.0f;
        } else {
            uchar4 mm = *(const uchar4*)&m8[mbase + o];
            k0 = mm.x != 0; k1 = mm.y != 0; k2 = mm.z != 0; k3 = mm.w != 0;
        }
        float4 a = *(const float4*)&arow[o];
        float4 e;
        e.x = __expf(fminf((k0 ? v.x : -1e30f) + a.x, 80.0f));
        e.y = __expf(fminf((k1 ? v.y : -1e30f) + a.y, 80.0f));
        e.z = __expf(fminf((k2 ? v.z : -1e30f) + a.z, 80.0f));
        e.w = __expf(fminf((k3 ? v.w : -1e30f) + a.w, 80.0f));
        *(float4*)&C[o] = e;
        float s = (e.x + e.y) + (e.z + e.w);
        s += __shfl_xor_sync(0xffffffffu, s, 1);
        s += __shfl_xor_sync(0xffffffffu, s, 2);
        s += __shfl_xor_sync(0xffffffffu, s, 4);
        s += __shfl_xor_sync(0xffffffffu, s, 8);
        if ((tid & 15) == 0)
            atomicAdd(&g_rsum[(size_t)zp * L_ + grow], s);
    }
}

// ===========================================================================
// HMMA attnv, split-K: blockIdx.x owns k-range [x*512, (x+1)*512).
// Normalizes + writes back its weights slice; partial attn accumulated
// directly into g_attn via RED.F32 (g_attn pre-zeroed each launch).
// ===========================================================================
__global__ __launch_bounds__(256, 3)
void attnv_mma(float* __restrict__ Wt,
               const float* __restrict__ gv,
               float* __restrict__ gattn)
{
    const int z = blockIdx.z;
    const int kch = blockIdx.x;
    const int b = z >> 4, h = z & 15;
    float* A  = Wt + (size_t)z * L_ * L_;                       // lda = L_
    const float* V = gv + ((size_t)b * L_ * H_ + h) * DK_;      // ldb = D_
    float* C = gattn + (size_t)b * L_ * D_ + h * DK_;           // ldc = D_

    __shared__ __nv_bfloat16 sAh[128][PADK], sAl[128][PADK];
    __shared__ __nv_bfloat16 sVh[64][PADK],  sVl[64][PADK];
    __shared__ float inv_s[128];

    const int tid  = threadIdx.x;
    const int wid  = tid >> 5, lane = tid & 31;
    const int wm   = wid & 3, wn = wid >> 2;          // 4 x 2 warp grid
    const int m0   = blockIdx.y * 128;

    const uint32_t bAh = smem_u32(sAh), bAl = smem_u32(sAl);
    const uint32_t bVh = smem_u32(sVh), bVl = smem_u32(sVl);

    const uint32_t aoff = (uint32_t)((wm * 32 + (lane & 15)) * PADK + ((lane >> 4) << 3)) * 2;
    const uint32_t boff = (uint32_t)((wn * 32 + (lane & 7) + ((lane >> 4) << 3)) * PADK
                                     + (((lane >> 3) & 1) << 3)) * 2;

    const int lrow = tid >> 3;
    const int lk   = (tid & 7) * 4;
    const int vkr  = tid >> 4;
    const int vnc  = (tid & 15) * 4;

    if (tid < 128) inv_s[tid] = 1.0f / g_rsum[(size_t)z * L_ + m0 + tid];
    __syncthreads();

    float acc[2][4][4] = {};

    const int kc0 = kch * KCH;
    for (int kc = kc0; kc < kc0 + KCH; kc += 32) {
        __syncthreads();
        #pragma unroll
        for (int it = 0; it < 4; it++) {
            int r = it * 32 + lrow;
            size_t ao = (size_t)(m0 + r) * L_ + kc + lk;
            float4 v = *(const float4*)&A[ao];
            float iv = inv_s[r];
            v.x *= iv; v.y *= iv; v.z *= iv; v.w *= iv;
            *(float4*)&A[ao] = v;
            uint2 hi, lo;
            split4(v, hi, lo);
            *(uint2*)&sAh[r][lk] = hi;
            *(uint2*)&sAl[r][lk] = lo;
        }
        #pragma unroll
        for (int it = 0; it < 2; it++) {
            int kr = it * 16 + vkr;
            float4 v = *(const float4*)&V[(size_t)(kc + kr) * D_ + vnc];
            uint2 hi, lo;
            split4(v, hi, lo);
            __nv_bfloat162 h0 = *(__nv_bfloat162*)&hi.x;
            __nv_bfloat162 h1 = *(__nv_bfloat162*)&hi.y;
            __nv_bfloat162 l0 = *(__nv_bfloat162*)&lo.x;
            __nv_bfloat162 l1 = *(__nv_bfloat162*)&lo.y;
            sVh[vnc + 0][kr] = __low2bfloat16(h0);
            sVh[vnc + 1][kr] = __high2bfloat16(h0);
            sVh[vnc + 2][kr] = __low2bfloat16(h1);
            sVh[vnc + 3][kr] = __high2bfloat16(h1);
            sVl[vnc + 0][kr] = __low2bfloat16(l0);
            sVl[vnc + 1][kr] = __high2bfloat16(l0);
            sVl[vnc + 2][kr] = __low2bfloat16(l1);
            sVl[vnc + 3][kr] = __high2bfloat16(l1);
        }
        __syncthreads();

        #pragma unroll
        for (int kb = 0; kb < 32; kb += 16) {
            const uint32_t kbo = (uint32_t)kb * 2;
            uint32_t ah[2][4], al[2][4];
            #pragma unroll
            for (int i = 0; i < 2; i++) {
                uint32_t step = (uint32_t)(i * 16 * PADK) * 2;
                ldsm4(ah[i], bAh + aoff + kbo + step);
                ldsm4(al[i], bAl + aoff + kbo + step);
            }
            uint32_t bh[8], bl[8];
            ldsm4(bh,     bVh + boff + kbo);
            ldsm4(bh + 4, bVh + boff + kbo + (uint32_t)(16 * PADK) * 2);
            ldsm4(bl,     bVl + boff + kbo);
            ldsm4(bl + 4, bVl + boff + kbo + (uint32_t)(16 * PADK) * 2);
            #pragma unroll
            for (int i = 0; i < 2; i++)
                #pragma unroll
                for (int j = 0; j < 4; j++) {
                    mma16816(acc[i][j], ah[i], &bh[j * 2]);
                    mma16816(acc[i][j], ah[i], &bl[j * 2]);
                    mma16816(acc[i][j], al[i], &bh[j * 2]);
                }
        }
    }

    const int g = lane >> 2, tig = lane & 3;
    #pragma unroll
    for (int i = 0; i < 2; i++) {
        int row = m0 + wm * 32 + i * 16 + g;
        #pragma unroll
        for (int j = 0; j < 4; j++) {
            int col = wn * 32 + j * 8 + tig * 2;
            float* p0 = &C[(size_t)row * D_ + col];
            float* p1 = &C[(size_t)(row + 8) * D_ + col];
            atomicAdd(p0,     acc[i][j][0]);
            atomicAdd(p0 + 1, acc[i][j][1]);
            atomicAdd(p1,     acc[i][j][2]);
            atomicAdd(p1 + 1, acc[i][j][3]);
        }
    }
}

// ---------------------------------------------------------------------------
extern "C" void kernel_launch(void* const* d_in, const int* in_sizes, int n_in,
                              void* d_out, int out_size)
{
    const float* query = (const float*)d_in[0];
    const float* key   = (const float*)d_in[1];
    const float* value = (const float*)d_in[2];
    const void*  mask  = d_in[3];
    const float* awb = (const float*)d_in[4];
    const float* Wq = (const float*)d_in[5];
    const float* bq = (const float*)d_in[6];
    const float* Wk = (const float*)d_in[7];
    const float* bk = (const float*)d_in[8];
    const float* Wv = (const float*)d_in[9];
    const float* bv = (const float*)d_in[10];
    const float* Wo = (const float*)d_in[11];
    const float* bo = (const float*)d_in[12];

    float* out = (float*)d_out;                              // (B, L, D)
    float* weights = out + (size_t)B_ * L_ * D_;             // (B, H, L, L)

    float *gq, *gk, *gv, *gattn, *grsum;
    cudaGetSymbolAddress((void**)&gq, g_q);
    cudaGetSymbolAddress((void**)&gk, g_k);
    cudaGetSymbolAddress((void**)&gv, g_v);
    cudaGetSymbolAddress((void**)&gattn, g_attn);
    cudaGetSymbolAddress((void**)&grsum, g_rsum);

    dim3 blk(256);

    // 0) mask dtype sniff + zero row sums + zero attn accumulator
    detect_mask_kernel<<<1, 32>>>((const unsigned int*)mask);
    cudaMemsetAsync(grsum, 0, (size_t)B_ * H_ * L_ * sizeof(float));
    cudaMemsetAsync(gattn, 0, (size_t)ML_ * D_ * sizeof(float));

    // 1) QKV projections via HMMA split-bf16
    dim3 gproj(D_ / 128, ML_ / 128, 3);
    proj_mma<<<gproj, blk>>>(query, key, value, Wq, Wk, Wv,
                             gq, gk, gv, bq, bk, bv);

    // 2) RoPE on q and k
    rope_kernel<<<2 * (B_ * L_ * H_ * 32) / 256, 256>>>(gq, gk);

    // 3) Logits via HMMA (128x64 tiles, staged epilogue)
    dim3 glog(L_ / 64, L_ / 128, B_ * H_);                   // 32 x 16 x 32
    logits_mma<<<glog, blk>>>(gq, gk, mask, awb, weights);

    // 4) Normalize weights (write back) + attn accumulated via RED.F32
    dim3 gat(KSPLIT, L_ / 128, B_ * H_);                     // 4 x 16 x 32
    attnv_mma<<<gat, blk>>>(weights, gv, gattn);

    // 5) Output projection via HMMA
    dim3 gout(D_ / 128, ML_ / 128, 1);
    proj_mma<<<gout, blk>>>(gattn, gattn, gattn, Wo, Wo, Wo,
                            out, out, out, bo, bo, bo);
}

// round 14
// speedup vs baseline: 2.9140x; 1.0034x over previous
#include <cuda_runtime.h>
#include <cuda_bf16.h>
#include <math.h>
#include <stdint.h>

// Problem constants
#define B_  2
#define L_  2048
#define H_  16
#define DK_ 64
#define D_  (H_ * DK_)        // 1024
#define ML_ (B_ * L_)         // 4096
#define KSPLIT 8
#define KCH (L_ / KSPLIT)     // 256

// Scratch (device globals: no allocation allowed)
__device__ float g_q[(size_t)ML_ * D_];
__device__ float g_k[(size_t)ML_ * D_];
__device__ float g_v[(size_t)ML_ * D_];
__device__ float g_attn[(size_t)ML_ * D_];
__device__ float g_rsum[(size_t)B_ * H_ * L_];
__device__ float2 g_rope[L_][32];
__device__ int   g_mask_kind;   // 0 = uint8, 1 = int32, 2 = float32

// ===========================================================================
// Helpers
// ===========================================================================
__device__ __forceinline__ uint32_t smem_u32(const void* p) {
    uint32_t a;
    asm("{ .reg .u64 t; cvta.to.shared.u64 t, %1; cvt.u32.u64 %0, t; }"
        : "=r"(a) : "l"(p));
    return a;
}

__device__ __forceinline__ void ldsm4(uint32_t* r, uint32_t addr) {
    asm volatile("ldmatrix.sync.aligned.m8n8.x4.shared.b16 {%0,%1,%2,%3}, [%4];"
                 : "=r"(r[0]), "=r"(r[1]), "=r"(r[2]), "=r"(r[3]) : "r"(addr));
}

__device__ __forceinline__ void mma16816(float* c, const uint32_t* a, const uint32_t* b) {
    asm volatile(
        "mma.sync.aligned.m16n8k16.row.col.f32.bf16.bf16.f32 "
        "{%0,%1,%2,%3}, {%4,%5,%6,%7}, {%8,%9}, {%0,%1,%2,%3};"
        : "+f"(c[0]), "+f"(c[1]), "+f"(c[2]), "+f"(c[3])
        : "r"(a[0]), "r"(a[1]), "r"(a[2]), "r"(a[3]), "r"(b[0]), "r"(b[1]));
}

__device__ __forceinline__ void red_add_v2(float* p, float a, float b) {
    asm volatile("red.global.add.v2.f32 [%0], {%1, %2};"
                 :: "l"(p), "f"(a), "f"(b) : "memory");
}

// Split fp32 float4 -> packed hi / lo bf16x2 pairs (uint2 each)
__device__ __forceinline__ void split4(float4 v, uint2& hi, uint2& lo) {
    __nv_bfloat16 h0 = __float2bfloat16(v.x), h1 = __float2bfloat16(v.y),
                  h2 = __float2bfloat16(v.z), h3 = __float2bfloat16(v.w);
    __nv_bfloat16 l0 = __float2bfloat16(v.x - __bfloat162float(h0)),
                  l1 = __float2bfloat16(v.y - __bfloat162float(h1)),
                  l2 = __float2bfloat16(v.z - __bfloat162float(h2)),
                  l3 = __float2bfloat16(v.w - __bfloat162float(h3));
    __nv_bfloat162 hp0 = __halves2bfloat162(h0, h1);
    __nv_bfloat162 hp1 = __halves2bfloat162(h2, h3);
    __nv_bfloat162 lp0 = __halves2bfloat162(l0, l1);
    __nv_bfloat162 lp1 = __halves2bfloat162(l2, l3);
    hi = make_uint2(*(uint32_t*)&hp0, *(uint32_t*)&hp1);
    lo = make_uint2(*(uint32_t*)&lp0, *(uint32_t*)&lp1);
}

// ===========================================================================
// Mask dtype sniffer
// ===========================================================================
__global__ void detect_mask_kernel(const unsigned int* __restrict__ m)
{
    if (threadIdx.x == 0 && blockIdx.x == 0) {
        int all01 = 1, allf = 1;
        for (int i = 0; i < 1024; i++) {
            unsigned int w = m[i];
            if (w > 1u) all01 = 0;
            if (w != 0u && w != 0x3F800000u) allf = 0;
        }
        g_mask_kind = all01 ? 1 : (allf ? 2 : 0);
    }
}

// ===========================================================================
// RoPE cos/sin table build: 2048 x 32 accurate sincos (one-time per launch).
// ===========================================================================
__global__ void rope_table_kernel()
{
    int idx = blockIdx.x * blockDim.x + threadIdx.x;   // 65536
    int l = idx >> 5, j = idx & 31;
    // inv_freq = 10000^(-2j/64) = 2^(-j * log2(10000)/32)
    float inv = exp2f(-0.41524101186092f * (float)j);
    float freq = (float)l * inv;
    g_rope[l][j] = make_float2(cosf(freq), sinf(freq));
}

// ===========================================================================
// HMMA split-bf16 projection GEMM: C = A @ W^T + bias  (unchanged, proven)
// ===========================================================================
#define PADK 40

__global__ __launch_bounds__(256)
void proj_mma(const float* __restrict__ A0, const float* __restrict__ A1,
              const float* __restrict__ A2,
              const float* __restrict__ W0, const float* __restrict__ W1,
              const float* __restrict__ W2,
              float* __restrict__ C0, float* __restrict__ C1, float* __restrict__ C2,
              const float* __restrict__ bi0, const float* __restrict__ bi1,
              const float* __restrict__ bi2)
{
    const int z = blockIdx.z;
    const float* A    = (z == 0) ? A0 : (z == 1) ? A1 : A2;
    const float* W    = (z == 0) ? W0 : (z == 1) ? W1 : W2;
    float* C          = (z == 0) ? C0 : (z == 1) ? C1 : C2;
    const float* bias = (z == 0) ? bi0 : (z == 1) ? bi1 : bi2;

    __shared__ __nv_bfloat16 sAh[128][PADK], sAl[128][PADK];
    __shared__ __nv_bfloat16 sBh[128][PADK], sBl[128][PADK];

    const int tid  = threadIdx.x;
    const int wid  = tid >> 5, lane = tid & 31;
    const int wm   = wid & 1, wn = wid >> 1;          // 2 x 4 warp grid
    const int m0   = blockIdx.y * 128, n0 = blockIdx.x * 128;

    const uint32_t bAh = smem_u32(sAh), bAl = smem_u32(sAl);
    const uint32_t bBh = smem_u32(sBh), bBl = smem_u32(sBl);

    const uint32_t aoff = (uint32_t)((wm * 64 + (lane & 15)) * PADK + ((lane >> 4) << 3)) * 2;
    const uint32_t boff = (uint32_t)((wn * 32 + (lane & 7) + ((lane >> 4) << 3)) * PADK
                                     + (((lane >> 3) & 1) << 3)) * 2;

    const int lrow = tid >> 3;
    const int lk   = (tid & 7) * 4;

    const float* Ag = A + (size_t)m0 * D_;
    const float* Wg = W + (size_t)n0 * D_;

    float acc[4][4][4] = {};

    for (int kc = 0; kc < D_; kc += 32) {
        __syncthreads();
        #pragma unroll
        for (int it = 0; it < 4; it++) {
            int r = it * 32 + lrow;
            uint2 hi, lo;
            split4(*(const float4*)&Ag[(size_t)r * D_ + kc + lk], hi, lo);
            *(uint2*)&sAh[r][lk] = hi;
            *(uint2*)&sAl[r][lk] = lo;
            split4(*(const float4*)&Wg[(size_t)r * D_ + kc + lk], hi, lo);
            *(uint2*)&sBh[r][lk] = hi;
            *(uint2*)&sBl[r][lk] = lo;
        }
        __syncthreads();

        #pragma unroll
        for (int kb = 0; kb < 32; kb += 16) {
            const uint32_t kbo = (uint32_t)kb * 2;
            uint32_t ah[4][4], al[4][4];
            #pragma unroll
            for (int i = 0; i < 4; i++) {
                uint32_t step = (uint32_t)(i * 16 * PADK) * 2;
                ldsm4(ah[i], bAh + aoff + kbo + step);
                ldsm4(al[i], bAl + aoff + kbo + step);
            }
            uint32_t bh[8], bl[8];
            ldsm4(bh,     bBh + boff + kbo);
            ldsm4(bh + 4, bBh + boff + kbo + (uint32_t)(16 * PADK) * 2);
            ldsm4(bl,     bBl + boff + kbo);
            ldsm4(bl + 4, bBl + boff + kbo + (uint32_t)(16 * PADK) * 2);
            #pragma unroll
            for (int i = 0; i < 4; i++)
                #pragma unroll
                for (int j = 0; j < 4; j++) {
                    mma16816(acc[i][j], ah[i], &bh[j * 2]);
                    mma16816(acc[i][j], ah[i], &bl[j * 2]);
                    mma16816(acc[i][j], al[i], &bh[j * 2]);
                }
        }
    }

    const int g = lane >> 2, tig = lane & 3;
    #pragma unroll
    for (int i = 0; i < 4; i++) {
        int row = m0 + wm * 64 + i * 16 + g;
        #pragma unroll
        for (int j = 0; j < 4; j++) {
            int col = n0 + wn * 32 + j * 8 + tig * 2;
            float2 b2 = *(const float2*)&bias[col];
            float2 o0, o1;
            o0.x = acc[i][j][0] + b2.x;  o0.y = acc[i][j][1] + b2.y;
            o1.x = acc[i][j][2] + b2.x;  o1.y = acc[i][j][3] + b2.y;
            *(float2*)&C[(size_t)row * D_ + col]       = o0;
            *(float2*)&C[(size_t)(row + 8) * D_ + col] = o1;
        }
    }
}

// ---------------------------------------------------------------------------
// RoPE apply in-place on q and k (table-driven, pure streaming).
// ---------------------------------------------------------------------------
__global__ void rope_kernel(float* __restrict__ q, float* __restrict__ k)
{
    int idx = blockIdx.x * blockDim.x + threadIdx.x;
    float* x = (idx >> 21) ? k : q;
    idx &= (1 << 21) - 1;
    int j = idx & 31;
    int h = (idx >> 5) & 15;
    int l = (idx >> 9) & 2047;
    int b = idx >> 20;
    size_t base = (((size_t)(b * L_ + l)) * H_ + h) * DK_;
    float2 cs = g_rope[l][j];
    float a  = x[base + j];
    float bb = x[base + j + 32];
    x[base + j]      = a * cs.x - bb * cs.y;
    x[base + j + 32] = bb * cs.x + a * cs.y;
}

// ===========================================================================
// HMMA logits, 128x64 tile, smem-staged epilogue (all gmem I/O 16B).
// ===========================================================================
#define STAGE_BYTES (128 * 68 * 4)   // 34816

__global__ __launch_bounds__(256, 3)
void logits_mma(const float* __restrict__ gq,
                const float* __restrict__ gk,
                const void* __restrict__ mask,
                const float* __restrict__ awb,
                float* __restrict__ Wt)
{
    const int z = blockIdx.z;
    const int h = z >> 1, b = z & 1;
    const int zp = b * H_ + h;
    const float* A  = gq + ((size_t)b * L_ * H_ + h) * DK_;   // lda = D_
    const float* Bm = gk + ((size_t)b * L_ * H_ + h) * DK_;   // ldb = D_
    const float* arow = awb + (size_t)h * L_ * L_;
    float* C = Wt + (size_t)zp * L_ * L_;
    const size_t mbase = (size_t)b * L_ * L_;

    const int mk = g_mask_kind;
    const unsigned char* m8  = (const unsigned char*)mask;
    const int*           m32 = (const int*)mask;
    const float*         mf  = (const float*)mask;

    __shared__ __align__(16) char smem_raw[STAGE_BYTES];
    __nv_bfloat16 (*sAh)[PADK] = (__nv_bfloat16(*)[PADK])(smem_raw);          // 10240
    __nv_bfloat16 (*sAl)[PADK] = (__nv_bfloat16(*)[PADK])(smem_raw + 10240);  // 10240
    __nv_bfloat16 (*sBh)[PADK] = (__nv_bfloat16(*)[PADK])(smem_raw + 20480);  // 5120
    __nv_bfloat16 (*sBl)[PADK] = (__nv_bfloat16(*)[PADK])(smem_raw + 25600);  // 5120
    float (*sC)[68] = (float(*)[68])smem_raw;

    const int tid  = threadIdx.x;
    const int wid  = tid >> 5, lane = tid & 31;
    const int wm   = wid & 1, wn = wid >> 1;           // 2 x 4; 64 rows x 16 cols
    const int m0   = blockIdx.y * 128, n0 = blockIdx.x * 64;

    const uint32_t bAh = smem_u32(sAh), bAl = smem_u32(sAl);
    const uint32_t bBh = smem_u32(sBh), bBl = smem_u32(sBl);

    const uint32_t aoff = (uint32_t)((wm * 64 + (lane & 15)) * PADK + ((lane >> 4) << 3)) * 2;
    const uint32_t boff = (uint32_t)((wn * 16 + (lane & 7) + ((lane >> 4) << 3)) * PADK
                                     + (((lane >> 3) & 1) << 3)) * 2;

    const int lrow = tid >> 3;
    const int lk   = (tid & 7) * 4;

    float acc[4][2][4] = {};

    for (int kc = 0; kc < DK_; kc += 32) {
        __syncthreads();
        #pragma unroll
        for (int it = 0; it < 4; it++) {
            int r = it * 32 + lrow;
            uint2 hi, lo;
            split4(*(const float4*)&A[(size_t)(m0 + r) * D_ + kc + lk], hi, lo);
            *(uint2*)&sAh[r][lk] = hi;
            *(uint2*)&sAl[r][lk] = lo;
        }
        #pragma unroll
        for (int it = 0; it < 2; it++) {
            int r = it * 32 + lrow;
            uint2 hi, lo;
            split4(*(const float4*)&Bm[(size_t)(n0 + r) * D_ + kc + lk], hi, lo);
            *(uint2*)&sBh[r][lk] = hi;
            *(uint2*)&sBl[r][lk] = lo;
        }
        __syncthreads();

        #pragma unroll
        for (int kb = 0; kb < 32; kb += 16) {
            const uint32_t kbo = (uint32_t)kb * 2;
            uint32_t ah[4][4], al[4][4];
            #pragma unroll
            for (int i = 0; i < 4; i++) {
                uint32_t step = (uint32_t)(i * 16 * PADK) * 2;
                ldsm4(ah[i], bAh + aoff + kbo + step);
                ldsm4(al[i], bAl + aoff + kbo + step);
            }
            uint32_t bh[4], bl[4];
            ldsm4(bh, bBh + boff + kbo);
            ldsm4(bl, bBl + boff + kbo);
            #pragma unroll
            for (int i = 0; i < 4; i++)
                #pragma unroll
                for (int j = 0; j < 2; j++) {
                    mma16816(acc[i][j], ah[i], &bh[j * 2]);
                    mma16816(acc[i][j], ah[i], &bl[j * 2]);
                    mma16816(acc[i][j], al[i], &bh[j * 2]);
                }
        }
    }

    // Stage raw logits tile into smem (overlaying dead MMA buffers).
    __syncthreads();
    const int g = lane >> 2, tig = lane & 3;
    #pragma unroll
    for (int i = 0; i < 4; i++) {
        int row = wm * 64 + i * 16 + g;
        #pragma unroll
        for (int j = 0; j < 2; j++) {
            int col = wn * 16 + j * 8 + tig * 2;
            *(float2*)&sC[row][col]     = make_float2(acc[i][j][0], acc[i][j][1]);
            *(float2*)&sC[row + 8][col] = make_float2(acc[i][j][2], acc[i][j][3]);
        }
    }
    __syncthreads();

    // Stream out: 16 rows per pass, 8 passes; all gmem ops are 16B.
    const int srow = tid >> 4, scol = (tid & 15) * 4;
    #pragma unroll
    for (int p = 0; p < 8; p++) {
        int row = p * 16 + srow;
        int grow = m0 + row;
        size_t o = (size_t)grow * L_ + n0 + scol;
        float4 v = *(const float4*)&sC[row][scol];
        v.x *= 0.125f; v.y *= 0.125f; v.z *= 0.125f; v.w *= 0.125f;
        bool k0, k1, k2, k3;
        if (mk == 1) {
            int4 mm = *(const int4*)&m32[mbase + o];
            k0 = mm.x != 0; k1 = mm.y != 0; k2 = mm.z != 0; k3 = mm.w != 0;
        } else if (mk == 2) {
            float4 mm = *(const float4*)&mf[mbase + o];
            k0 = mm.x != 0.0f; k1 = mm.y != 0.0f; k2 = mm.z != 0.0f; k3 = mm.w != 0.0f;
        } else {
            uchar4 mm = *(const uchar4*)&m8[mbase + o];
            k0 = mm.x != 0; k1 = mm.y != 0; k2 = mm.z != 0; k3 = mm.w != 0;
        }
        float4 a = *(const float4*)&arow[o];
        float4 e;
        e.x = __expf(fminf((k0 ? v.x : -1e30f) + a.x, 80.0f));
        e.y = __expf(fminf((k1 ? v.y : -1e30f) + a.y, 80.0f));
        e.z = __expf(fminf((k2 ? v.z : -1e30f) + a.z, 80.0f));
        e.w = __expf(fminf((k3 ? v.w : -1e30f) + a.w, 80.0f));
        *(float4*)&C[o] = e;
        float s = (e.x + e.y) + (e.z + e.w);
        s += __shfl_xor_sync(0xffffffffu, s, 1);
        s += __shfl_xor_sync(0xffffffffu, s, 2);
        s += __shfl_xor_sync(0xffffffffu, s, 4);
        s += __shfl_xor_sync(0xffffffffu, s, 8);
        if ((tid & 15) == 0)
            atomicAdd(&g_rsum[(size_t)zp * L_ + grow], s);
    }
}

// ===========================================================================
// HMMA attnv, split-K x8: blockIdx.x owns k-range [x*256, (x+1)*256).
// Normalizes + writes back its weights slice; partial attn accumulated
// into g_attn via red.v2.f32 (g_attn pre-zeroed each launch).
// Grid (8, 16, 32) = 4096 blocks.
// ===========================================================================
__global__ __launch_bounds__(256, 3)
void attnv_mma(float* __restrict__ Wt,
               const float* __restrict__ gv,
               float* __restrict__ gattn)
{
    const int z = blockIdx.z;
    const int kch = blockIdx.x;
    const int b = z >> 4, h = z & 15;
    float* A  = Wt + (size_t)z * L_ * L_;                       // lda = L_
    const float* V = gv + ((size_t)b * L_ * H_ + h) * DK_;      // ldb = D_
    float* C = gattn + (size_t)b * L_ * D_ + h * DK_;           // ldc = D_

    __shared__ __nv_bfloat16 sAh[128][PADK], sAl[128][PADK];
    __shared__ __nv_bfloat16 sVh[64][PADK],  sVl[64][PADK];
    __shared__ float inv_s[128];

    const int tid  = threadIdx.x;
    const int wid  = tid >> 5, lane = tid & 31;
    const int wm   = wid & 3, wn = wid >> 2;          // 4 x 2 warp grid
    const int m0   = blockIdx.y * 128;

    const uint32_t bAh = smem_u32(sAh), bAl = smem_u32(sAl);
    const uint32_t bVh = smem_u32(sVh), bVl = smem_u32(sVl);

    const uint32_t aoff = (uint32_t)((wm * 32 + (lane & 15)) * PADK + ((lane >> 4) << 3)) * 2;
    const uint32_t boff = (uint32_t)((wn * 32 + (lane & 7) + ((lane >> 4) << 3)) * PADK
                                     + (((lane >> 3) & 1) << 3)) * 2;

    const int lrow = tid >> 3;
    const int lk   = (tid & 7) * 4;
    const int vkr  = tid >> 4;
    const int vnc  = (tid & 15) * 4;

    if (tid < 128) inv_s[tid] = 1.0f / g_rsum[(size_t)z * L_ + m0 + tid];
    __syncthreads();

    float acc[2][4][4] = {};

    const int kc0 = kch * KCH;
    for (int kc = kc0; kc < kc0 + KCH; kc += 32) {
        __syncthreads();
        #pragma unroll
        for (int it = 0; it < 4; it++) {
            int r = it * 32 + lrow;
            size_t ao = (size_t)(m0 + r) * L_ + kc + lk;
            float4 v = *(const float4*)&A[ao];
            float iv = inv_s[r];
            v.x *= iv; v.y *= iv; v.z *= iv; v.w *= iv;
            *(float4*)&A[ao] = v;
            uint2 hi, lo;
            split4(v, hi, lo);
            *(uint2*)&sAh[r][lk] = hi;
            *(uint2*)&sAl[r][lk] = lo;
        }
        #pragma unroll
        for (int it = 0; it < 2; it++) {
            int kr = it * 16 + vkr;
            float4 v = *(const float4*)&V[(size_t)(kc + kr) * D_ + vnc];
            uint2 hi, lo;
            split4(v, hi, lo);
            __nv_bfloat162 h0 = *(__nv_bfloat162*)&hi.x;
            __nv_bfloat162 h1 = *(__nv_bfloat162*)&hi.y;
            __nv_bfloat162 l0 = *(__nv_bfloat162*)&lo.x;
            __nv_bfloat162 l1 = *(__nv_bfloat162*)&lo.y;
            sVh[vnc + 0][kr] = __low2bfloat16(h0);
            sVh[vnc + 1][kr] = __high2bfloat16(h0);
            sVh[vnc + 2][kr] = __low2bfloat16(h1);
            sVh[vnc + 3][kr] = __high2bfloat16(h1);
            sVl[vnc + 0][kr] = __low2bfloat16(l0);
            sVl[vnc + 1][kr] = __high2bfloat16(l0);
            sVl[vnc + 2][kr] = __low2bfloat16(l1);
            sVl[vnc + 3][kr] = __high2bfloat16(l1);
        }
        __syncthreads();

        #pragma unroll
        for (int kb = 0; kb < 32; kb += 16) {
            const uint32_t kbo = (uint32_t)kb * 2;
            uint32_t ah[2][4], al[2][4];
            #pragma unroll
            for (int i = 0; i < 2; i++) {
                uint32_t step = (uint32_t)(i * 16 * PADK) * 2;
                ldsm4(ah[i], bAh + aoff + kbo + step);
                ldsm4(al[i], bAl + aoff + kbo + step);
            }
            uint32_t bh[8], bl[8];
            ldsm4(bh,     bVh + boff + kbo);
            ldsm4(bh + 4, bVh + boff + kbo + (uint32_t)(16 * PADK) * 2);
            ldsm4(bl,     bVl + boff + kbo);
            ldsm4(bl + 4, bVl + boff + kbo + (uint32_t)(16 * PADK) * 2);
            #pragma unroll
            for (int i = 0; i < 2; i++)
                #pragma unroll
                for (int j = 0; j < 4; j++) {
                    mma16816(acc[i][j], ah[i], &bh[j * 2]);
                    mma16816(acc[i][j], ah[i], &bl[j * 2]);
                    mma16816(acc[i][j], al[i], &bh[j * 2]);
                }
        }
    }

    const int g = lane >> 2, tig = lane & 3;
    #pragma unroll
    for (int i = 0; i < 2; i++) {
        int row = m0 + wm * 32 + i * 16 + g;
        #pragma unroll
        for (int j = 0; j < 4; j++) {
            int col = wn * 32 + j * 8 + tig * 2;
            red_add_v2(&C[(size_t)row * D_ + col],       acc[i][j][0], acc[i][j][1]);
            red_add_v2(&C[(size_t)(row + 8) * D_ + col], acc[i][j][2], acc[i][j][3]);
        }
    }
}

// ---------------------------------------------------------------------------
extern "C" void kernel_launch(void* const* d_in, const int* in_sizes, int n_in,
                              void* d_out, int out_size)
{
    const float* query = (const float*)d_in[0];
    const float* key   = (const float*)d_in[1];
    const float* value = (const float*)d_in[2];
    const void*  mask  = d_in[3];
    const float* awb = (const float*)d_in[4];
    const float* Wq = (const float*)d_in[5];
    const float* bq = (const float*)d_in[6];
    const float* Wk = (const float*)d_in[7];
    const float* bk = (const float*)d_in[8];
    const float* Wv = (const float*)d_in[9];
    const float* bv = (const float*)d_in[10];
    const float* Wo = (const float*)d_in[11];
    const float* bo = (const float*)d_in[12];

    float* out = (float*)d_out;                              // (B, L, D)
    float* weights = out + (size_t)B_ * L_ * D_;             // (B, H, L, L)

    float *gq, *gk, *gv, *gattn, *grsum;
    cudaGetSymbolAddress((void**)&gq, g_q);
    cudaGetSymbolAddress((void**)&gk, g_k);
    cudaGetSymbolAddress((void**)&gv, g_v);
    cudaGetSymbolAddress((void**)&gattn, g_attn);
    cudaGetSymbolAddress((void**)&grsum, g_rsum);

    dim3 blk(256);

    // 0) mask dtype sniff + rope table + zero accumulators
    detect_mask_kernel<<<1, 32>>>((const unsigned int*)mask);
    rope_table_kernel<<<(L_ * 32) / 256, 256>>>();
    cudaMemsetAsync(grsum, 0, (size_t)B_ * H_ * L_ * sizeof(float));
    cudaMemsetAsync(gattn, 0, (size_t)ML_ * D_ * sizeof(float));

    // 1) QKV projections via HMMA split-bf16
    dim3 gproj(D_ / 128, ML_ / 128, 3);
    proj_mma<<<gproj, blk>>>(query, key, value, Wq, Wk, Wv,
                             gq, gk, gv, bq, bk, bv);

    // 2) RoPE on q and k (table-driven)
    rope_kernel<<<2 * (B_ * L_ * H_ * 32) / 256, 256>>>(gq, gk);

    // 3) Logits via HMMA (128x64 tiles, staged epilogue)
    dim3 glog(L_ / 64, L_ / 128, B_ * H_);                   // 32 x 16 x 32
    logits_mma<<<glog, blk>>>(gq, gk, mask, awb, weights);

    // 4) Normalize weights (write back) + attn accumulated via red.v2
    dim3 gat(KSPLIT, L_ / 128, B_ * H_);                     // 8 x 16 x 32
    attnv_mma<<<gat, blk>>>(weights, gv, gattn);

    // 5) Output projection via HMMA
    dim3 gout(D_ / 128, ML_ / 128, 1);
    proj_mma<<<gout, blk>>>(gattn, gattn, gattn, Wo, Wo, Wo,
                            out, out, out, bo, bo, bo);
}

// round 15
// speedup vs baseline: 3.3222x; 1.1401x over previous
#include <cuda_runtime.h>
#include <cuda_bf16.h>
#include <math.h>
#include <stdint.h>

// Problem constants
#define B_  2
#define L_  2048
#define H_  16
#define DK_ 64
#define D_  (H_ * DK_)        // 1024
#define ML_ (B_ * L_)         // 4096
#define KSPLIT 8
#define KCH (L_ / KSPLIT)     // 256

// Scratch (device globals: no allocation allowed)
__device__ float g_q[(size_t)ML_ * D_];
__device__ float g_k[(size_t)ML_ * D_];
__device__ float g_v[(size_t)ML_ * D_];
__device__ float g_attn[(size_t)ML_ * D_];
__device__ float g_rsum[(size_t)B_ * H_ * L_];
__device__ float2 g_rope[L_][32];
__device__ __nv_bfloat16 g_vh[B_ * H_][DK_][L_];   // V split hi, n-major
__device__ __nv_bfloat16 g_vl[B_ * H_][DK_][L_];   // V split lo, n-major
__device__ int   g_mask_kind;   // 0 = uint8, 1 = int32, 2 = float32

// ===========================================================================
// Helpers
// ===========================================================================
__device__ __forceinline__ uint32_t smem_u32(const void* p) {
    uint32_t a;
    asm("{ .reg .u64 t; cvta.to.shared.u64 t, %1; cvt.u32.u64 %0, t; }"
        : "=r"(a) : "l"(p));
    return a;
}

__device__ __forceinline__ void ldsm4(uint32_t* r, uint32_t addr) {
    asm volatile("ldmatrix.sync.aligned.m8n8.x4.shared.b16 {%0,%1,%2,%3}, [%4];"
                 : "=r"(r[0]), "=r"(r[1]), "=r"(r[2]), "=r"(r[3]) : "r"(addr));
}

__device__ __forceinline__ void mma16816(float* c, const uint32_t* a, const uint32_t* b) {
    asm volatile(
        "mma.sync.aligned.m16n8k16.row.col.f32.bf16.bf16.f32 "
        "{%0,%1,%2,%3}, {%4,%5,%6,%7}, {%8,%9}, {%0,%1,%2,%3};"
        : "+f"(c[0]), "+f"(c[1]), "+f"(c[2]), "+f"(c[3])
        : "r"(a[0]), "r"(a[1]), "r"(a[2]), "r"(a[3]), "r"(b[0]), "r"(b[1]));
}

__device__ __forceinline__ void red_add_v2(float* p, float a, float b) {
    asm volatile("red.global.add.v2.f32 [%0], {%1, %2};"
                 :: "l"(p), "f"(a), "f"(b) : "memory");
}

// Split fp32 float4 -> packed hi / lo bf16x2 pairs (uint2 each)
__device__ __forceinline__ void split4(float4 v, uint2& hi, uint2& lo) {
    __nv_bfloat16 h0 = __float2bfloat16(v.x), h1 = __float2bfloat16(v.y),
                  h2 = __float2bfloat16(v.z), h3 = __float2bfloat16(v.w);
    __nv_bfloat16 l0 = __float2bfloat16(v.x - __bfloat162float(h0)),
                  l1 = __float2bfloat16(v.y - __bfloat162float(h1)),
                  l2 = __float2bfloat16(v.z - __bfloat162float(h2)),
                  l3 = __float2bfloat16(v.w - __bfloat162float(h3));
    __nv_bfloat162 hp0 = __halves2bfloat162(h0, h1);
    __nv_bfloat162 hp1 = __halves2bfloat162(h2, h3);
    __nv_bfloat162 lp0 = __halves2bfloat162(l0, l1);
    __nv_bfloat162 lp1 = __halves2bfloat162(l2, l3);
    hi = make_uint2(*(uint32_t*)&hp0, *(uint32_t*)&hp1);
    lo = make_uint2(*(uint32_t*)&lp0, *(uint32_t*)&lp1);
}

// ===========================================================================
// Mask dtype sniffer
// ===========================================================================
__global__ void detect_mask_kernel(const unsigned int* __restrict__ m)
{
    if (threadIdx.x == 0 && blockIdx.x == 0) {
        int all01 = 1, allf = 1;
        for (int i = 0; i < 1024; i++) {
            unsigned int w = m[i];
            if (w > 1u) all01 = 0;
            if (w != 0u && w != 0x3F800000u) allf = 0;
        }
        g_mask_kind = all01 ? 1 : (allf ? 2 : 0);
    }
}

// ===========================================================================
// RoPE cos/sin table build: 2048 x 32 accurate sincos.
// ===========================================================================
__global__ void rope_table_kernel()
{
    int idx = blockIdx.x * blockDim.x + threadIdx.x;   // 65536
    int l = idx >> 5, j = idx & 31;
    float inv = exp2f(-0.41524101186092f * (float)j);
    float freq = (float)l * inv;
    g_rope[l][j] = make_float2(cosf(freq), sinf(freq));
}

// ===========================================================================
// V pre-split: (b,l,h,d) fp32 -> g_vh/g_vl[z][d][k] bf16 (transposed via smem)
// Grid: (L_/64, B_*H_), 256 threads.
// ===========================================================================
__global__ void vsplit_kernel(const float* __restrict__ gv)
{
    __shared__ float t[64][65];
    const int z = blockIdx.y;
    const int b = z >> 4, h = z & 15;
    const int k0 = blockIdx.x * 64;
    for (int i = threadIdx.x; i < 64 * 64; i += 256) {
        int kk = i >> 6, d = i & 63;
        t[kk][d] = gv[(((size_t)(b * L_ + k0 + kk)) * H_ + h) * DK_ + d];
    }
    __syncthreads();
    for (int i = threadIdx.x; i < 64 * 64; i += 256) {
        int d = i >> 6, kk = i & 63;
        float v = t[kk][d];
        __nv_bfloat16 hi = __float2bfloat16(v);
        __nv_bfloat16 lo = __float2bfloat16(v - __bfloat162float(hi));
        g_vh[z][d][k0 + kk] = hi;
        g_vl[z][d][k0 + kk] = lo;
    }
}

// ===========================================================================
// HMMA split-bf16 projection GEMM: C = A @ W^T + bias  (unchanged, proven)
// ===========================================================================
#define PADK 40

__global__ __launch_bounds__(256)
void proj_mma(const float* __restrict__ A0, const float* __restrict__ A1,
              const float* __restrict__ A2,
              const float* __restrict__ W0, const float* __restrict__ W1,
              const float* __restrict__ W2,
              float* __restrict__ C0, float* __restrict__ C1, float* __restrict__ C2,
              const float* __restrict__ bi0, const float* __restrict__ bi1,
              const float* __restrict__ bi2)
{
    const int z = blockIdx.z;
    const float* A    = (z == 0) ? A0 : (z == 1) ? A1 : A2;
    const float* W    = (z == 0) ? W0 : (z == 1) ? W1 : W2;
    float* C          = (z == 0) ? C0 : (z == 1) ? C1 : C2;
    const float* bias = (z == 0) ? bi0 : (z == 1) ? bi1 : bi2;

    __shared__ __nv_bfloat16 sAh[128][PADK], sAl[128][PADK];
    __shared__ __nv_bfloat16 sBh[128][PADK], sBl[128][PADK];

    const int tid  = threadIdx.x;
    const int wid  = tid >> 5, lane = tid & 31;
    const int wm   = wid & 1, wn = wid >> 1;          // 2 x 4 warp grid
    const int m0   = blockIdx.y * 128, n0 = blockIdx.x * 128;

    const uint32_t bAh = smem_u32(sAh), bAl = smem_u32(sAl);
    const uint32_t bBh = smem_u32(sBh), bBl = smem_u32(sBl);

    const uint32_t aoff = (uint32_t)((wm * 64 + (lane & 15)) * PADK + ((lane >> 4) << 3)) * 2;
    const uint32_t boff = (uint32_t)((wn * 32 + (lane & 7) + ((lane >> 4) << 3)) * PADK
                                     + (((lane >> 3) & 1) << 3)) * 2;

    const int lrow = tid >> 3;
    const int lk   = (tid & 7) * 4;

    const float* Ag = A + (size_t)m0 * D_;
    const float* Wg = W + (size_t)n0 * D_;

    float acc[4][4][4] = {};

    for (int kc = 0; kc < D_; kc += 32) {
        __syncthreads();
        #pragma unroll
        for (int it = 0; it < 4; it++) {
            int r = it * 32 + lrow;
            uint2 hi, lo;
            split4(*(const float4*)&Ag[(size_t)r * D_ + kc + lk], hi, lo);
            *(uint2*)&sAh[r][lk] = hi;
            *(uint2*)&sAl[r][lk] = lo;
            split4(*(const float4*)&Wg[(size_t)r * D_ + kc + lk], hi, lo);
            *(uint2*)&sBh[r][lk] = hi;
            *(uint2*)&sBl[r][lk] = lo;
        }
        __syncthreads();

        #pragma unroll
        for (int kb = 0; kb < 32; kb += 16) {
            const uint32_t kbo = (uint32_t)kb * 2;
            uint32_t ah[4][4], al[4][4];
            #pragma unroll
            for (int i = 0; i < 4; i++) {
                uint32_t step = (uint32_t)(i * 16 * PADK) * 2;
                ldsm4(ah[i], bAh + aoff + kbo + step);
                ldsm4(al[i], bAl + aoff + kbo + step);
            }
            uint32_t bh[8], bl[8];
            ldsm4(bh,     bBh + boff + kbo);
            ldsm4(bh + 4, bBh + boff + kbo + (uint32_t)(16 * PADK) * 2);
            ldsm4(bl,     bBl + boff + kbo);
            ldsm4(bl + 4, bBl + boff + kbo + (uint32_t)(16 * PADK) * 2);
            #pragma unroll
            for (int i = 0; i < 4; i++)
                #pragma unroll
                for (int j = 0; j < 4; j++) {
                    mma16816(acc[i][j], ah[i], &bh[j * 2]);
                    mma16816(acc[i][j], ah[i], &bl[j * 2]);
                    mma16816(acc[i][j], al[i], &bh[j * 2]);
                }
        }
    }

    const int g = lane >> 2, tig = lane & 3;
    #pragma unroll
    for (int i = 0; i < 4; i++) {
        int row = m0 + wm * 64 + i * 16 + g;
        #pragma unroll
        for (int j = 0; j < 4; j++) {
            int col = n0 + wn * 32 + j * 8 + tig * 2;
            float2 b2 = *(const float2*)&bias[col];
            float2 o0, o1;
            o0.x = acc[i][j][0] + b2.x;  o0.y = acc[i][j][1] + b2.y;
            o1.x = acc[i][j][2] + b2.x;  o1.y = acc[i][j][3] + b2.y;
            *(float2*)&C[(size_t)row * D_ + col]       = o0;
            *(float2*)&C[(size_t)(row + 8) * D_ + col] = o1;
        }
    }
}

// ---------------------------------------------------------------------------
// RoPE apply in-place on q and k (table-driven).
// ---------------------------------------------------------------------------
__global__ void rope_kernel(float* __restrict__ q, float* __restrict__ k)
{
    int idx = blockIdx.x * blockDim.x + threadIdx.x;
    float* x = (idx >> 21) ? k : q;
    idx &= (1 << 21) - 1;
    int j = idx & 31;
    int h = (idx >> 5) & 15;
    int l = (idx >> 9) & 2047;
    int b = idx >> 20;
    size_t base = (((size_t)(b * L_ + l)) * H_ + h) * DK_;
    float2 cs = g_rope[l][j];
    float a  = x[base + j];
    float bb = x[base + j + 32];
    x[base + j]      = a * cs.x - bb * cs.y;
    x[base + j + 32] = bb * cs.x + a * cs.y;
}

// ===========================================================================
// HMMA logits, 128x64 tile, smem-staged epilogue (all gmem I/O 16B).
// ===========================================================================
#define STAGE_BYTES (128 * 68 * 4)   // 34816

__global__ __launch_bounds__(256, 3)
void logits_mma(const float* __restrict__ gq,
                const float* __restrict__ gk,
                const void* __restrict__ mask,
                const float* __restrict__ awb,
                float* __restrict__ Wt)
{
    const int z = blockIdx.z;
    const int h = z >> 1, b = z & 1;
    const int zp = b * H_ + h;
    const float* A  = gq + ((size_t)b * L_ * H_ + h) * DK_;   // lda = D_
    const float* Bm = gk + ((size_t)b * L_ * H_ + h) * DK_;   // ldb = D_
    const float* arow = awb + (size_t)h * L_ * L_;
    float* C = Wt + (size_t)zp * L_ * L_;
    const size_t mbase = (size_t)b * L_ * L_;

    const int mk = g_mask_kind;
    const unsigned char* m8  = (const unsigned char*)mask;
    const int*           m32 = (const int*)mask;
    const float*         mf  = (const float*)mask;

    __shared__ __align__(16) char smem_raw[STAGE_BYTES];
    __nv_bfloat16 (*sAh)[PADK] = (__nv_bfloat16(*)[PADK])(smem_raw);
    __nv_bfloat16 (*sAl)[PADK] = (__nv_bfloat16(*)[PADK])(smem_raw + 10240);
    __nv_bfloat16 (*sBh)[PADK] = (__nv_bfloat16(*)[PADK])(smem_raw + 20480);
    __nv_bfloat16 (*sBl)[PADK] = (__nv_bfloat16(*)[PADK])(smem_raw + 25600);
    float (*sC)[68] = (float(*)[68])smem_raw;

    const int tid  = threadIdx.x;
    const int wid  = tid >> 5, lane = tid & 31;
    const int wm   = wid & 1, wn = wid >> 1;           // 2 x 4; 64 rows x 16 cols
    const int m0   = blockIdx.y * 128, n0 = blockIdx.x * 64;

    const uint32_t bAh = smem_u32(sAh), bAl = smem_u32(sAl);
    const uint32_t bBh = smem_u32(sBh), bBl = smem_u32(sBl);

    const uint32_t aoff = (uint32_t)((wm * 64 + (lane & 15)) * PADK + ((lane >> 4) << 3)) * 2;
    const uint32_t boff = (uint32_t)((wn * 16 + (lane & 7) + ((lane >> 4) << 3)) * PADK
                                     + (((lane >> 3) & 1) << 3)) * 2;

    const int lrow = tid >> 3;
    const int lk   = (tid & 7) * 4;

    float acc[4][2][4] = {};

    for (int kc = 0; kc < DK_; kc += 32) {
        __syncthreads();
        #pragma unroll
        for (int it = 0; it < 4; it++) {
            int r = it * 32 + lrow;
            uint2 hi, lo;
            split4(*(const float4*)&A[(size_t)(m0 + r) * D_ + kc + lk], hi, lo);
            *(uint2*)&sAh[r][lk] = hi;
            *(uint2*)&sAl[r][lk] = lo;
        }
        #pragma unroll
        for (int it = 0; it < 2; it++) {
            int r = it * 32 + lrow;
            uint2 hi, lo;
            split4(*(const float4*)&Bm[(size_t)(n0 + r) * D_ + kc + lk], hi, lo);
            *(uint2*)&sBh[r][lk] = hi;
            *(uint2*)&sBl[r][lk] = lo;
        }
        __syncthreads();

        #pragma unroll
        for (int kb = 0; kb < 32; kb += 16) {
            const uint32_t kbo = (uint32_t)kb * 2;
            uint32_t ah[4][4], al[4][4];
            #pragma unroll
            for (int i = 0; i < 4; i++) {
                uint32_t step = (uint32_t)(i * 16 * PADK) * 2;
                ldsm4(ah[i], bAh + aoff + kbo + step);
                ldsm4(al[i], bAl + aoff + kbo + step);
            }
            uint32_t bh[4], bl[4];
            ldsm4(bh, bBh + boff + kbo);
            ldsm4(bl, bBl + boff + kbo);
            #pragma unroll
            for (int i = 0; i < 4; i++)
                #pragma unroll
                for (int j = 0; j < 2; j++) {
                    mma16816(acc[i][j], ah[i], &bh[j * 2]);
                    mma16816(acc[i][j], ah[i], &bl[j * 2]);
                    mma16816(acc[i][j], al[i], &bh[j * 2]);
                }
        }
    }

    // Stage raw logits tile into smem (overlaying dead MMA buffers).
    __syncthreads();
    const int g = lane >> 2, tig = lane & 3;
    #pragma unroll
    for (int i = 0; i < 4; i++) {
        int row = wm * 64 + i * 16 + g;
        #pragma unroll
        for (int j = 0; j < 2; j++) {
            int col = wn * 16 + j * 8 + tig * 2;
            *(float2*)&sC[row][col]     = make_float2(acc[i][j][0], acc[i][j][1]);
            *(float2*)&sC[row + 8][col] = make_float2(acc[i][j][2], acc[i][j][3]);
        }
    }
    __syncthreads();

    // Stream out: 16 rows per pass, 8 passes; all gmem ops are 16B.
    const int srow = tid >> 4, scol = (tid & 15) * 4;
    #pragma unroll
    for (int p = 0; p < 8; p++) {
        int row = p * 16 + srow;
        int grow = m0 + row;
        size_t o = (size_t)grow * L_ + n0 + scol;
        float4 v = *(const float4*)&sC[row][scol];
        v.x *= 0.125f; v.y *= 0.125f; v.z *= 0.125f; v.w *= 0.125f;
        bool k0, k1, k2, k3;
        if (mk == 1) {
            int4 mm = *(const int4*)&m32[mbase + o];
            k0 = mm.x != 0; k1 = mm.y != 0; k2 = mm.z != 0; k3 = mm.w != 0;
        } else if (mk == 2) {
            float4 mm = *(const float4*)&mf[mbase + o];
            k0 = mm.x != 0.0f; k1 = mm.y != 0.0f; k2 = mm.z != 0.0f; k3 = mm.w != 0.0f;
        } else {
            uchar4 mm = *(const uchar4*)&m8[mbase + o];
            k0 = mm.x != 0; k1 = mm.y != 0; k2 = mm.z != 0; k3 = mm.w != 0;
        }
        float4 a = *(const float4*)&arow[o];
        float4 e;
        e.x = __expf(fminf((k0 ? v.x : -1e30f) + a.x, 80.0f));
        e.y = __expf(fminf((k1 ? v.y : -1e30f) + a.y, 80.0f));
        e.z = __expf(fminf((k2 ? v.z : -1e30f) + a.z, 80.0f));
        e.w = __expf(fminf((k3 ? v.w : -1e30f) + a.w, 80.0f));
        *(float4*)&C[o] = e;
        float s = (e.x + e.y) + (e.z + e.w);
        s += __shfl_xor_sync(0xffffffffu, s, 1);
        s += __shfl_xor_sync(0xffffffffu, s, 2);
        s += __shfl_xor_sync(0xffffffffu, s, 4);
        s += __shfl_xor_sync(0xffffffffu, s, 8);
        if ((tid & 15) == 0)
            atomicAdd(&g_rsum[(size_t)zp * L_ + grow], s);
    }
}

// ===========================================================================
// HMMA attnv, split-K x8, register-prefetch double buffered.
// V comes pre-split/transposed from g_vh/g_vl (uint4 copy into smem).
// Normalizes + writes back weights slice; attn accumulated via red.v2.f32.
// ===========================================================================
__global__ __launch_bounds__(256, 2)
void attnv_mma(float* __restrict__ Wt, float* __restrict__ gattn)
{
    const int z = blockIdx.z;
    const int kch = blockIdx.x;
    const int b = z >> 4, h = z & 15;
    float* A = Wt + (size_t)z * L_ * L_;                        // lda = L_
    float* C = gattn + (size_t)b * L_ * D_ + h * DK_;           // ldc = D_

    __shared__ __nv_bfloat16 sAh[128][PADK], sAl[128][PADK];
    __shared__ __nv_bfloat16 sVh[64][PADK],  sVl[64][PADK];
    __shared__ float inv_s[128];

    const int tid  = threadIdx.x;
    const int wid  = tid >> 5, lane = tid & 31;
    const int wm   = wid & 3, wn = wid >> 2;          // 4 x 2 warp grid
    const int m0   = blockIdx.y * 128;

    const uint32_t bAh = smem_u32(sAh), bAl = smem_u32(sAl);
    const uint32_t bVh = smem_u32(sVh), bVl = smem_u32(sVl);

    const uint32_t aoff = (uint32_t)((wm * 32 + (lane & 15)) * PADK + ((lane >> 4) << 3)) * 2;
    const uint32_t boff = (uint32_t)((wn * 32 + (lane & 7) + ((lane >> 4) << 3)) * PADK
                                     + (((lane >> 3) & 1) << 3)) * 2;

    const int lrow = tid >> 3;           // A: 32 rows per iter
    const int lk   = (tid & 7) * 4;
    const int vn   = tid >> 2;           // V: row 0..63
    const int vkp  = (tid & 3) * 8;      // 8 bf16 per thread

    if (tid < 128) inv_s[tid] = 1.0f / g_rsum[(size_t)z * L_ + m0 + tid];
    __syncthreads();

    const int kc0 = kch * KCH, kcend = kc0 + KCH;

    // Prefetch first chunk
    float4 pa[4];
    uint4 pvh, pvl;
    #pragma unroll
    for (int it = 0; it < 4; it++)
        pa[it] = *(const float4*)&A[(size_t)(m0 + it * 32 + lrow) * L_ + kc0 + lk];
    pvh = *(const uint4*)&g_vh[z][vn][kc0 + vkp];
    pvl = *(const uint4*)&g_vl[z][vn][kc0 + vkp];

    float acc[2][4][4] = {};

    for (int kc = kc0; kc < kcend; kc += 32) {
        // Store phase: normalize + writeback + split A; copy V.
        #pragma unroll
        for (int it = 0; it < 4; it++) {
            int r = it * 32 + lrow;
            float4 v = pa[it];
            float iv = inv_s[r];
            v.x *= iv; v.y *= iv; v.z *= iv; v.w *= iv;
            *(float4*)&A[(size_t)(m0 + r) * L_ + kc + lk] = v;
            uint2 hi, lo;
            split4(v, hi, lo);
            *(uint2*)&sAh[r][lk] = hi;
            *(uint2*)&sAl[r][lk] = lo;
        }
        *(uint4*)&sVh[vn][vkp] = pvh;
        *(uint4*)&sVl[vn][vkp] = pvl;
        __syncthreads();

        // Prefetch next chunk (overlaps the MMA section below)
        int kn = kc + 32;
        if (kn < kcend) {
            #pragma unroll
            for (int it = 0; it < 4; it++)
                pa[it] = *(const float4*)&A[(size_t)(m0 + it * 32 + lrow) * L_ + kn + lk];
            pvh = *(const uint4*)&g_vh[z][vn][kn + vkp];
            pvl = *(const uint4*)&g_vl[z][vn][kn + vkp];
        }

        #pragma unroll
        for (int kb = 0; kb < 32; kb += 16) {
            const uint32_t kbo = (uint32_t)kb * 2;
            uint32_t ah[2][4], al[2][4];
            #pragma unroll
            for (int i = 0; i < 2; i++) {
                uint32_t step = (uint32_t)(i * 16 * PADK) * 2;
                ldsm4(ah[i], bAh + aoff + kbo + step);
                ldsm4(al[i], bAl + aoff + kbo + step);
            }
            uint32_t bh[8], bl[8];
            ldsm4(bh,     bVh + boff + kbo);
            ldsm4(bh + 4, bVh + boff + kbo + (uint32_t)(16 * PADK) * 2);
            ldsm4(bl,     bVl + boff + kbo);
            ldsm4(bl + 4, bVl + boff + kbo + (uint32_t)(16 * PADK) * 2);
            #pragma unroll
            for (int i = 0; i < 2; i++)
                #pragma unroll
                for (int j = 0; j < 4; j++) {
                    mma16816(acc[i][j], ah[i], &bh[j * 2]);
                    mma16816(acc[i][j], ah[i], &bl[j * 2]);
                    mma16816(acc[i][j], al[i], &bh[j * 2]);
                }
        }
        __syncthreads();
    }

    const int g = lane >> 2, tig = lane & 3;
    #pragma unroll
    for (int i = 0; i < 2; i++) {
        int row = m0 + wm * 32 + i * 16 + g;
        #pragma unroll
        for (int j = 0; j < 4; j++) {
            int col = wn * 32 + j * 8 + tig * 2;
            red_add_v2(&C[(size_t)row * D_ + col],       acc[i][j][0], acc[i][j][1]);
            red_add_v2(&C[(size_t)(row + 8) * D_ + col], acc[i][j][2], acc[i][j][3]);
        }
    }
}

// ---------------------------------------------------------------------------
extern "C" void kernel_launch(void* const* d_in, const int* in_sizes, int n_in,
                              void* d_out, int out_size)
{
    const float* query = (const float*)d_in[0];
    const float* key   = (const float*)d_in[1];
    const float* value = (const float*)d_in[2];
    const void*  mask  = d_in[3];
    const float* awb = (const float*)d_in[4];
    const float* Wq = (const float*)d_in[5];
    const float* bq = (const float*)d_in[6];
    const float* Wk = (const float*)d_in[7];
    const float* bk = (const float*)d_in[8];
    const float* Wv = (const float*)d_in[9];
    const float* bv = (const float*)d_in[10];
    const float* Wo = (const float*)d_in[11];
    const float* bo = (const float*)d_in[12];

    float* out = (float*)d_out;                              // (B, L, D)
    float* weights = out + (size_t)B_ * L_ * D_;             // (B, H, L, L)

    float *gq, *gk, *gv, *gattn, *grsum;
    cudaGetSymbolAddress((void**)&gq, g_q);
    cudaGetSymbolAddress((void**)&gk, g_k);
    cudaGetSymbolAddress((void**)&gv, g_v);
    cudaGetSymbolAddress((void**)&gattn, g_attn);
    cudaGetSymbolAddress((void**)&grsum, g_rsum);

    dim3 blk(256);

    // 0) mask dtype sniff + rope table + zero accumulators
    detect_mask_kernel<<<1, 32>>>((const unsigned int*)mask);
    rope_table_kernel<<<(L_ * 32) / 256, 256>>>();
    cudaMemsetAsync(grsum, 0, (size_t)B_ * H_ * L_ * sizeof(float));
    cudaMemsetAsync(gattn, 0, (size_t)ML_ * D_ * sizeof(float));

    // 1) QKV projections via HMMA split-bf16
    dim3 gproj(D_ / 128, ML_ / 128, 3);
    proj_mma<<<gproj, blk>>>(query, key, value, Wq, Wk, Wv,
                             gq, gk, gv, bq, bk, bv);

    // 2) RoPE on q and k (table-driven); V pre-split/transpose
    rope_kernel<<<2 * (B_ * L_ * H_ * 32) / 256, 256>>>(gq, gk);
    dim3 gvs(L_ / 64, B_ * H_);
    vsplit_kernel<<<gvs, blk>>>(gv);

    // 3) Logits via HMMA (128x64 tiles, staged epilogue)
    dim3 glog(L_ / 64, L_ / 128, B_ * H_);                   // 32 x 16 x 32
    logits_mma<<<glog, blk>>>(gq, gk, mask, awb, weights);

    // 4) Normalize weights (write back) + attn accumulated via red.v2
    dim3 gat(KSPLIT, L_ / 128, B_ * H_);                     // 8 x 16 x 32
    attnv_mma<<<gat, blk>>>(weights, gattn);

    // 5) Output projection via HMMA
    dim3 gout(D_ / 128, ML_ / 128, 1);
    proj_mma<<<gout, blk>>>(gattn, gattn, gattn, Wo, Wo, Wo,
                            out, out, out, bo, bo, bo);
}